// round 2
// baseline (speedup 1.0000x reference)
#include <cuda_runtime.h>

#define BB 4
#define NN 4096
#define DD 512
#define HH 8
#define DHD 64
#define MM 256
#define LLm 16
#define NITER 6
#define KC 33
#define BH (BB*HH)

// ---------------- scratch (static device allocations; no cudaMalloc) ----------
__device__ float g_xn [BB*NN*DD];            // also reused as proj output
__device__ float g_qkv[BB*NN*3*DD];          // also reused as att (reshaped out)
__device__ float g_q  [BH*NN*DHD];
__device__ float g_k  [BH*NN*DHD];
__device__ float g_v  [BH*NN*DHD];
__device__ float g_o  [BH*NN*DHD];
__device__ float g_ql [BH*MM*DHD];
__device__ float g_kl [BH*MM*DHD];
__device__ float g_a1 [(long)BH*NN*MM];
__device__ float g_a3 [(long)BH*MM*NN];
__device__ float g_a2 [BH*MM*MM];
__device__ float g_zA [BH*MM*MM];
__device__ float g_zB [BH*MM*MM];
__device__ float g_xz [BH*MM*MM];
__device__ float g_t1 [BH*MM*MM];
__device__ float g_t2 [BH*MM*MM];
__device__ float g_a3v[BH*MM*DHD];
__device__ float g_W  [BH*MM*DHD];
__device__ float g_colmax;

// ---------------- generic batched SGEMM: C = alpha * A @ B(^T) ---------------
// BM=128, BN=64, BK=16. 256 threads, each computes 8x4.
// All M multiples of 128, N multiples of 64, K multiples of 16 (guaranteed here).
template<bool TB>
__global__ __launch_bounds__(256) void sgemm(
    const float* __restrict__ Ag, const float* __restrict__ Bg,
    float* __restrict__ Cg, int Md, int Nd, int Kd,
    long sA, long sB, long sC, float alpha)
{
    const int BK = 16;
    __shared__ float As[BK][128];
    __shared__ float Bs[BK][64];
    const float* A = Ag + (long)blockIdx.z * sA;
    const float* B = Bg + (long)blockIdx.z * sB;
    float*       C = Cg + (long)blockIdx.z * sC;
    int m0 = blockIdx.y * 128;
    int n0 = blockIdx.x * 64;
    int t  = threadIdx.x;
    int tx = t & 15, ty = t >> 4;

    float acc[8][4];
#pragma unroll
    for (int i = 0; i < 8; i++)
#pragma unroll
        for (int j = 0; j < 4; j++) acc[i][j] = 0.f;

    for (int k0 = 0; k0 < Kd; k0 += BK) {
        // A tile 128x16: 2 float4 per thread, stored transposed
#pragma unroll
        for (int i = 0; i < 2; i++) {
            int e   = t + i * 256;       // float4 index 0..511
            int row = e >> 2;
            int c4  = e & 3;
            float4 va = *(const float4*)(A + (long)(m0 + row) * Kd + k0 + c4 * 4);
            As[c4*4+0][row] = va.x; As[c4*4+1][row] = va.y;
            As[c4*4+2][row] = va.z; As[c4*4+3][row] = va.w;
        }
        if (!TB) {
            // B [K x N]: tile 16x64, one float4 per thread
            int row = t >> 4;
            int c4  = t & 15;
            float4 vb = *(const float4*)(B + (long)(k0 + row) * Nd + n0 + c4 * 4);
            *(float4*)(&Bs[row][c4 * 4]) = vb;
        } else {
            // B [N x K]: need Bs[kk][n] = B[n0+n][k0+kk]
            int n  = t >> 2;
            int c4 = t & 3;
            float4 vb = *(const float4*)(B + (long)(n0 + n) * Kd + k0 + c4 * 4);
            Bs[c4*4+0][n] = vb.x; Bs[c4*4+1][n] = vb.y;
            Bs[c4*4+2][n] = vb.z; Bs[c4*4+3][n] = vb.w;
        }
        __syncthreads();
#pragma unroll
        for (int kk = 0; kk < BK; kk++) {
            float4 a0 = *(const float4*)(&As[kk][ty * 8]);
            float4 a1 = *(const float4*)(&As[kk][ty * 8 + 4]);
            float4 b0 = *(const float4*)(&Bs[kk][tx * 4]);
            float ar[8] = {a0.x, a0.y, a0.z, a0.w, a1.x, a1.y, a1.z, a1.w};
            float br[4] = {b0.x, b0.y, b0.z, b0.w};
#pragma unroll
            for (int i = 0; i < 8; i++)
#pragma unroll
                for (int j = 0; j < 4; j++) acc[i][j] += ar[i] * br[j];
        }
        __syncthreads();
    }
#pragma unroll
    for (int i = 0; i < 8; i++) {
        int row = m0 + ty * 8 + i;
        float4 v4 = make_float4(acc[i][0]*alpha, acc[i][1]*alpha,
                                acc[i][2]*alpha, acc[i][3]*alpha);
        *(float4*)(C + (long)row * Nd + n0 + tx * 4) = v4;
    }
}

// ---------------- LayerNorm: one block per row of 512 -------------------------
__global__ __launch_bounds__(256) void ln_kernel(
    const float* __restrict__ x, const float* __restrict__ w, const float* __restrict__ b)
{
    long row = blockIdx.x;
    const float* xr = x + row * DD;
    int t = threadIdx.x;
    float v0 = xr[t], v1 = xr[t + 256];
    __shared__ float red[32];

    float s = v0 + v1;
    for (int o = 16; o > 0; o >>= 1) s += __shfl_xor_sync(~0u, s, o);
    if ((t & 31) == 0) red[t >> 5] = s;
    __syncthreads();
    if (t < 32) {
        float ss = (t < 8) ? red[t] : 0.f;
        for (int o = 4; o > 0; o >>= 1) ss += __shfl_xor_sync(~0u, ss, o);
        if (t == 0) red[0] = ss;
    }
    __syncthreads();
    float mu = red[0] * (1.f / DD);
    __syncthreads();

    float d0 = v0 - mu, d1 = v1 - mu;
    float q = d0 * d0 + d1 * d1;
    for (int o = 16; o > 0; o >>= 1) q += __shfl_xor_sync(~0u, q, o);
    if ((t & 31) == 0) red[t >> 5] = q;
    __syncthreads();
    if (t < 32) {
        float ss = (t < 8) ? red[t] : 0.f;
        for (int o = 4; o > 0; o >>= 1) ss += __shfl_xor_sync(~0u, ss, o);
        if (t == 0) red[0] = ss;
    }
    __syncthreads();
    float inv = rsqrtf(red[0] * (1.f / DD) + 1e-5f);
    g_xn[row * DD + t]       = d0 * inv * w[t]       + b[t];
    g_xn[row * DD + t + 256] = d1 * inv * w[t + 256] + b[t + 256];
}

// ---------------- split qkv into [B,H,N,D] (q scaled by DH^-0.5) --------------
__global__ void split_qkv()
{
    long i = (long)blockIdx.x * 256 + threadIdx.x;     // over B*N*512 (b,n,h,d)
    int d = i % DHD; long r = i / DHD;
    int h = r % HH;  long bn = r / HH;
    long src = bn * (3 * DD) + h * DHD + d;
    long b = bn / NN, n = bn % NN;
    long dst = ((b * HH + h) * NN + n) * DHD + d;
    g_q[dst] = g_qkv[src] * 0.125f;
    g_k[dst] = g_qkv[src + DD];
    g_v[dst] = g_qkv[src + 2 * DD];
}

// ---------------- landmarks: mean over blocks of 16 tokens --------------------
__global__ void landmarks()
{
    long i = (long)blockIdx.x * 256 + threadIdx.x;     // BH*MM*DHD
    int d = i % DHD; long r = i / DHD;
    int m = r % MM;  int bh = r / MM;
    long base = ((long)bh * NN + m * LLm) * DHD + d;
    float sq = 0.f, sk = 0.f;
#pragma unroll
    for (int u = 0; u < LLm; u++) { sq += g_q[base + u * DHD]; sk += g_k[base + u * DHD]; }
    g_ql[i] = sq * (1.f / LLm);
    g_kl[i] = sk * (1.f / LLm);
}

// ---------------- row softmax (W = 256 or 4096), in place ---------------------
template<int W>
__global__ __launch_bounds__(256) void softmax_rows(float* __restrict__ A)
{
    constexpr int VPT = W / 256;
    float* a = A + (long)blockIdx.x * W;
    int t = threadIdx.x;
    float v[VPT];
    float mx = -1e30f;
    __shared__ float red[32];
#pragma unroll
    for (int i = 0; i < VPT; i++) { v[i] = a[t + i * 256]; mx = fmaxf(mx, v[i]); }
    for (int o = 16; o > 0; o >>= 1) mx = fmaxf(mx, __shfl_xor_sync(~0u, mx, o));
    if ((t & 31) == 0) red[t >> 5] = mx;
    __syncthreads();
    if (t < 32) {
        float m2 = (t < 8) ? red[t] : -1e30f;
        for (int o = 4; o > 0; o >>= 1) m2 = fmaxf(m2, __shfl_xor_sync(~0u, m2, o));
        if (t == 0) red[0] = m2;
    }
    __syncthreads();
    mx = red[0];
    __syncthreads();
    float s = 0.f;
#pragma unroll
    for (int i = 0; i < VPT; i++) { v[i] = __expf(v[i] - mx); s += v[i]; }
    for (int o = 16; o > 0; o >>= 1) s += __shfl_xor_sync(~0u, s, o);
    if ((t & 31) == 0) red[t >> 5] = s;
    __syncthreads();
    if (t < 32) {
        float s2 = (t < 8) ? red[t] : 0.f;
        for (int o = 4; o > 0; o >>= 1) s2 += __shfl_xor_sync(~0u, s2, o);
        if (t == 0) red[0] = s2;
    }
    __syncthreads();
    float inv = 1.f / red[0];
#pragma unroll
    for (int i = 0; i < VPT; i++) a[t + i * 256] = v[i] * inv;
}

// ---------------- pinv init helpers ------------------------------------------
__global__ void init_colmax() { g_colmax = 0.f; }

__global__ __launch_bounds__(256) void colmax_kernel()
{
    int bh = blockIdx.x, j = threadIdx.x;
    const float* a = g_a2 + (long)bh * MM * MM;
    float s = 0.f;
    for (int i = 0; i < MM; i++) s += a[i * MM + j];
    __shared__ float red[32];
    float m = s;
    for (int o = 16; o > 0; o >>= 1) m = fmaxf(m, __shfl_xor_sync(~0u, m, o));
    if ((j & 31) == 0) red[j >> 5] = m;
    __syncthreads();
    if (j < 32) {
        float m2 = (j < 8) ? red[j] : -1e30f;
        for (int o = 4; o > 0; o >>= 1) m2 = fmaxf(m2, __shfl_xor_sync(~0u, m2, o));
        if (j == 0) atomicMax((int*)&g_colmax, __float_as_int(m2));
    }
}

__global__ void zinit()
{
    long i = (long)blockIdx.x * 256 + threadIdx.x;     // BH*MM*MM
    int col = i % MM; long r = i / MM;
    int row = r % MM; int bh = r / MM;
    float inv = 1.f / g_colmax;                        // max row-sum == 1 (softmax)
    g_zA[i] = g_a2[((long)bh * MM + col) * MM + row] * inv;
}

__global__ void aIminus(const float* __restrict__ X, float* __restrict__ Y, float aval)
{
    long i = (long)blockIdx.x * 256 + threadIdx.x;
    int col = i % MM; long r = i / MM; int row = r % MM;
    float dg = (col == row) ? aval : 0.f;
    Y[i] = dg - X[i];
}

// ---------------- depthwise conv residual over sequence dim -------------------
__global__ void conv_res(const float* __restrict__ rw)
{
    long i = (long)blockIdx.x * 256 + threadIdx.x;     // BH*NN*DHD
    int d = i % DHD; long r = i / DHD;
    int n = r % NN;  int bh = r / NN;
    int h = bh % HH;
    const float* vb = g_v + (long)bh * NN * DHD;
    float acc = 0.f;
#pragma unroll
    for (int j = 0; j < KC; j++) {
        int tt = n + j - KC / 2;
        if (tt >= 0 && tt < NN) acc += rw[h * KC + j] * vb[(long)tt * DHD + d];
    }
    g_o[i] += acc;
}

// ---------------- reshape [B,H,N,D] -> [B,N,H*D] (into g_qkv) -----------------
__global__ void reshape_out()
{
    long i = (long)blockIdx.x * 256 + threadIdx.x;     // B*N*512 (b,n,h,d)
    int d = i % DHD; long r = i / DHD;
    int h = r % HH;  long bn = r / HH;
    long b = bn / NN, n = bn % NN;
    g_qkv[bn * DD + h * DHD + d] = g_o[((b * HH + h) * NN + n) * DHD + d];
}

// ---------------- y = x + proj + b_out ----------------------------------------
__global__ void final_add(const float* __restrict__ x, const float* __restrict__ bout,
                          float* __restrict__ y)
{
    long i = (long)blockIdx.x * 256 + threadIdx.x;     // B*N*512
    y[i] = x[i] + g_xn[i] + bout[i % DD];
}

// ---------------- host orchestration ------------------------------------------
extern "C" void kernel_launch(void* const* d_in, const int* in_sizes, int n_in,
                              void* d_out, int out_size)
{
    const float* x      = (const float*)d_in[0];
    const float* norm_w = (const float*)d_in[1];
    const float* norm_b = (const float*)d_in[2];
    const float* w_qkv  = (const float*)d_in[3];
    const float* w_out  = (const float*)d_in[4];
    const float* b_out  = (const float*)d_in[5];
    const float* res_w  = (const float*)d_in[6];
    float* y = (float*)d_out;

    float *p_xn, *p_qkv, *p_q, *p_k, *p_v, *p_o, *p_ql, *p_kl;
    float *p_a1, *p_a3, *p_a2, *p_zA, *p_zB, *p_xz, *p_t1, *p_t2, *p_a3v, *p_W;
    cudaGetSymbolAddress((void**)&p_xn,  g_xn);
    cudaGetSymbolAddress((void**)&p_qkv, g_qkv);
    cudaGetSymbolAddress((void**)&p_q,   g_q);
    cudaGetSymbolAddress((void**)&p_k,   g_k);
    cudaGetSymbolAddress((void**)&p_v,   g_v);
    cudaGetSymbolAddress((void**)&p_o,   g_o);
    cudaGetSymbolAddress((void**)&p_ql,  g_ql);
    cudaGetSymbolAddress((void**)&p_kl,  g_kl);
    cudaGetSymbolAddress((void**)&p_a1,  g_a1);
    cudaGetSymbolAddress((void**)&p_a3,  g_a3);
    cudaGetSymbolAddress((void**)&p_a2,  g_a2);
    cudaGetSymbolAddress((void**)&p_zA,  g_zA);
    cudaGetSymbolAddress((void**)&p_zB,  g_zB);
    cudaGetSymbolAddress((void**)&p_xz,  g_xz);
    cudaGetSymbolAddress((void**)&p_t1,  g_t1);
    cudaGetSymbolAddress((void**)&p_t2,  g_t2);
    cudaGetSymbolAddress((void**)&p_a3v, g_a3v);
    cudaGetSymbolAddress((void**)&p_W,   g_W);

    const long MM2 = (long)MM * MM;

    // 1. LayerNorm
    ln_kernel<<<BB * NN, 256>>>(x, norm_w, norm_b);
    // 2. qkv = xn @ w_qkv   [16384,512]@[512,1536]
    sgemm<false><<<dim3((3 * DD) / 64, (BB * NN) / 128, 1), 256>>>(
        p_xn, w_qkv, p_qkv, BB * NN, 3 * DD, DD, 0, 0, 0, 1.f);
    // 3. split into heads (+ q scale)
    split_qkv<<<(BB * NN * DD) / 256, 256>>>();
    // 4. landmarks
    landmarks<<<(BH * MM * DHD) / 256, 256>>>();
    // 5. sim2 = ql @ kl^T  -> softmax -> a2
    sgemm<true><<<dim3(MM / 64, MM / 128, BH), 256>>>(
        p_ql, p_kl, p_a2, MM, MM, DHD, (long)MM * DHD, (long)MM * DHD, MM2, 1.f);
    softmax_rows<MM><<<BH * MM, 256>>>(p_a2);
    // 6. pinv init: z = a2^T / max(colsum)
    init_colmax<<<1, 1>>>();
    colmax_kernel<<<BH, 256>>>();
    zinit<<<(BH * MM * MM) / 256, 256>>>();
    // 7. Newton-Schulz, 6 iterations
    float* zin = p_zA; float* zout = p_zB;
    for (int it = 0; it < NITER; it++) {
        sgemm<false><<<dim3(MM / 64, MM / 128, BH), 256>>>(
            p_a2, zin, p_xz, MM, MM, MM, MM2, MM2, MM2, 1.f);
        aIminus<<<(BH * MM * MM) / 256, 256>>>(p_xz, p_t1, 7.f);
        sgemm<false><<<dim3(MM / 64, MM / 128, BH), 256>>>(
            p_xz, p_t1, p_t2, MM, MM, MM, MM2, MM2, MM2, 1.f);
        aIminus<<<(BH * MM * MM) / 256, 256>>>(p_t2, p_t1, 15.f);
        sgemm<false><<<dim3(MM / 64, MM / 128, BH), 256>>>(
            p_xz, p_t1, p_t2, MM, MM, MM, MM2, MM2, MM2, 1.f);
        aIminus<<<(BH * MM * MM) / 256, 256>>>(p_t2, p_t1, 13.f);
        sgemm<false><<<dim3(MM / 64, MM / 128, BH), 256>>>(
            zin, p_t1, zout, MM, MM, MM, MM2, MM2, MM2, 0.25f);
        float* tmp = zin; zin = zout; zout = tmp;
    }
    // 8. sim1 = q @ kl^T -> softmax -> a1
    sgemm<true><<<dim3(MM / 64, NN / 128, BH), 256>>>(
        p_q, p_kl, p_a1, NN, MM, DHD, (long)NN * DHD, (long)MM * DHD, (long)NN * MM, 1.f);
    softmax_rows<MM><<<BH * NN, 256>>>(p_a1);
    // 9. sim3 = ql @ k^T -> softmax -> a3
    sgemm<true><<<dim3(NN / 64, MM / 128, BH), 256>>>(
        p_ql, p_k, p_a3, MM, NN, DHD, (long)MM * DHD, (long)NN * DHD, (long)MM * NN, 1.f);
    softmax_rows<NN><<<BH * MM, 256>>>(p_a3);
    // 10. a3v = a3 @ v   [256,4096]@[4096,64]
    sgemm<false><<<dim3(1, MM / 128, BH), 256>>>(
        p_a3, p_v, p_a3v, MM, DHD, NN, (long)MM * NN, (long)NN * DHD, (long)MM * DHD, 1.f);
    // 11. W = z @ a3v    [256,256]@[256,64]
    sgemm<false><<<dim3(1, MM / 128, BH), 256>>>(
        zin, p_a3v, p_W, MM, DHD, MM, MM2, (long)MM * DHD, (long)MM * DHD, 1.f);
    // 12. out = a1 @ W   [4096,256]@[256,64]
    sgemm<false><<<dim3(1, NN / 128, BH), 256>>>(
        p_a1, p_W, p_o, NN, DHD, MM, (long)NN * MM, (long)MM * DHD, (long)NN * DHD, 1.f);
    // 13. += depthwise conv of v
    conv_res<<<(BH * NN * DHD) / 256, 256>>>(res_w);
    // 14. reshape to [B,N,512] (into g_qkv)
    reshape_out<<<(BB * NN * DD) / 256, 256>>>();
    // 15. proj = att @ w_out (into g_xn)
    sgemm<false><<<dim3(DD / 64, (BB * NN) / 128, 1), 256>>>(
        p_qkv, w_out, p_xn, BB * NN, DD, DD, 0, 0, 0, 1.f);
    // 16. y = x + proj + b_out
    final_add<<<(BB * NN * DD) / 256, 256>>>(x, b_out, y);
}

// round 4
// speedup vs baseline: 1.9643x; 1.9643x over previous
#include <cuda_runtime.h>
#include <cstdint>

#define BB 4
#define NN 4096
#define DD 512
#define HH 8
#define DHD 64
#define MM 256
#define LLm 16
#define NITER 6
#define KC 33
#define BH (BB*HH)

// ---------------- scratch (static device allocations; no cudaMalloc) ----------
__device__ float g_xn [BB*NN*DD];            // also reused as proj output
__device__ float g_qkv[BB*NN*3*DD];          // also reused as att (reshaped out)
__device__ float g_q  [BH*NN*DHD];
__device__ float g_k  [BH*NN*DHD];
__device__ float g_v  [BH*NN*DHD];
__device__ float g_o  [BH*NN*DHD];
__device__ float g_ql [BH*MM*DHD];
__device__ float g_kl [BH*MM*DHD];
__device__ float g_a1 [(long)BH*NN*MM];
__device__ float g_a3 [(long)BH*MM*NN];
__device__ float g_a2 [BH*MM*MM];
__device__ float g_zA [BH*MM*MM];
__device__ float g_zB [BH*MM*MM];
__device__ float g_xz [BH*MM*MM];
__device__ float g_t1 [BH*MM*MM];
__device__ float g_t2 [BH*MM*MM];
__device__ float g_a3v[BH*MM*DHD];
__device__ float g_W  [BH*MM*DHD];
__device__ float g_colmax;

// ---------------- TF32 helpers ------------------------------------------------
// cvt.rna.tf32.f32 requires a .b32 destination register.
__device__ __forceinline__ uint32_t tf32r(float x) {
    uint32_t y;
    asm("cvt.rna.tf32.f32 %0, %1;" : "=r"(y) : "f"(x));
    return y;
}
__device__ __forceinline__ void mma_tf32(float* c, const uint32_t* a, const uint32_t* b) {
    asm volatile(
        "mma.sync.aligned.m16n8k8.row.col.f32.tf32.tf32.f32 "
        "{%0,%1,%2,%3}, {%4,%5,%6,%7}, {%8,%9}, {%0,%1,%2,%3};"
        : "+f"(c[0]), "+f"(c[1]), "+f"(c[2]), "+f"(c[3])
        : "r"(a[0]), "r"(a[1]), "r"(a[2]), "r"(a[3]), "r"(b[0]), "r"(b[1]));
}

// ---------------- TF32 tensor-core batched GEMM -------------------------------
// C = alpha * A @ B(^T).  Optional epilogue outputs:
//   Craw = alpha*acc            (if non-null)
//   Ct   = dg*I - alpha*acc     (if non-null; local row/col of this batch matrix)
// BM=128, BN=64, BK=32, 256 threads (8 warps, 4m x 2n), warp tile 32x32.
// Requires: M%128==0, N%64==0, K%32==0.
template<bool TB>
__global__ __launch_bounds__(256) void mmagemm(
    const float* __restrict__ Ag, const float* __restrict__ Bg,
    float* __restrict__ Craw, float* __restrict__ Ct,
    int Md, int Nd, int Kd, long sA, long sB, long sC,
    float alpha, float dg)
{
    __shared__ uint32_t As[2][128 * 32];   // swizzle: idx = m*32 + (k ^ ((m&7)<<2))
    __shared__ uint32_t Bs[2][32 * 64];    // swizzle: idx = k*64 + (n ^ ((k&7)<<3))

    const float* A = Ag + (long)blockIdx.z * sA;
    const float* B = Bg + (long)blockIdx.z * sB;
    const int m0 = blockIdx.y * 128;
    const int n0 = blockIdx.x * 64;
    const int tid = threadIdx.x;
    const int wid = tid >> 5, lane = tid & 31;
    const int warpm = wid & 3, warpn = wid >> 2;
    const int lg = lane >> 2, lt = lane & 3;

    float acc[2][4][4];
#pragma unroll
    for (int mt = 0; mt < 2; mt++)
#pragma unroll
        for (int nt = 0; nt < 4; nt++)
#pragma unroll
            for (int i = 0; i < 4; i++) acc[mt][nt][i] = 0.f;

    const int nk = Kd >> 5;

    // ---- initial tile load (stage 0) ----
    {
        const int k0 = 0;
#pragma unroll
        for (int j = 0; j < 4; j++) {
            int e = tid + j * 256;
            int row = e >> 3, c4 = (e & 7) << 2;
            float4 v = *(const float4*)(A + (long)(m0 + row) * Kd + k0 + c4);
            uint4 w = make_uint4(tf32r(v.x), tf32r(v.y), tf32r(v.z), tf32r(v.w));
            *(uint4*)(&As[0][row * 32 + (c4 ^ ((row & 7) << 2))]) = w;
        }
        if (!TB) {
#pragma unroll
            for (int j = 0; j < 2; j++) {
                int e = tid + j * 256;
                int row = e >> 4, c4 = (e & 15) << 2;
                float4 v = *(const float4*)(B + (long)(k0 + row) * Nd + n0 + c4);
                uint4 w = make_uint4(tf32r(v.x), tf32r(v.y), tf32r(v.z), tf32r(v.w));
                *(uint4*)(&Bs[0][row * 64 + (c4 ^ ((row & 7) << 3))]) = w;
            }
        } else {
#pragma unroll
            for (int j = 0; j < 2; j++) {
                int e = tid + j * 256;
                int n = e >> 3, c4 = (e & 7) << 2;
                float4 v = *(const float4*)(B + (long)(n0 + n) * Kd + k0 + c4);
                Bs[0][(c4 + 0) * 64 + (n ^ (((c4 + 0) & 7) << 3))] = tf32r(v.x);
                Bs[0][(c4 + 1) * 64 + (n ^ (((c4 + 1) & 7) << 3))] = tf32r(v.y);
                Bs[0][(c4 + 2) * 64 + (n ^ (((c4 + 2) & 7) << 3))] = tf32r(v.z);
                Bs[0][(c4 + 3) * 64 + (n ^ (((c4 + 3) & 7) << 3))] = tf32r(v.w);
            }
        }
    }
    __syncthreads();

    for (int kt = 0; kt < nk; kt++) {
        const int st = kt & 1;
        // ---- prefetch next tile into registers ----
        float4 pa[4], pb[2];
        const bool more = (kt + 1 < nk);
        if (more) {
            const int k0 = (kt + 1) << 5;
#pragma unroll
            for (int j = 0; j < 4; j++) {
                int e = tid + j * 256;
                int row = e >> 3, c4 = (e & 7) << 2;
                pa[j] = *(const float4*)(A + (long)(m0 + row) * Kd + k0 + c4);
            }
            if (!TB) {
#pragma unroll
                for (int j = 0; j < 2; j++) {
                    int e = tid + j * 256;
                    int row = e >> 4, c4 = (e & 15) << 2;
                    pb[j] = *(const float4*)(B + (long)(k0 + row) * Nd + n0 + c4);
                }
            } else {
#pragma unroll
                for (int j = 0; j < 2; j++) {
                    int e = tid + j * 256;
                    int n = e >> 3, c4 = (e & 7) << 2;
                    pb[j] = *(const float4*)(B + (long)(n0 + n) * Kd + k0 + c4);
                }
            }
        }

        // ---- compute on stage st ----
#pragma unroll
        for (int kk = 0; kk < 32; kk += 8) {
            uint32_t af[2][4], bf[4][2];
#pragma unroll
            for (int mt = 0; mt < 2; mt++) {
                int r = warpm * 32 + mt * 16 + lg;
                int k = kk + lt;
                af[mt][0] = As[st][r * 32 + (k ^ ((r & 7) << 2))];
                af[mt][1] = As[st][(r + 8) * 32 + (k ^ (((r + 8) & 7) << 2))];
                af[mt][2] = As[st][r * 32 + ((k + 4) ^ ((r & 7) << 2))];
                af[mt][3] = As[st][(r + 8) * 32 + ((k + 4) ^ (((r + 8) & 7) << 2))];
            }
#pragma unroll
            for (int nt = 0; nt < 4; nt++) {
                int c = warpn * 32 + nt * 8 + lg;
                int k = kk + lt;
                bf[nt][0] = Bs[st][k * 64 + (c ^ ((k & 7) << 3))];
                bf[nt][1] = Bs[st][(k + 4) * 64 + (c ^ (((k + 4) & 7) << 3))];
            }
#pragma unroll
            for (int mt = 0; mt < 2; mt++)
#pragma unroll
                for (int nt = 0; nt < 4; nt++)
                    mma_tf32(acc[mt][nt], af[mt], bf[nt]);
        }

        // ---- store prefetched tile into stage st^1 ----
        if (more) {
            const int ns = st ^ 1;
#pragma unroll
            for (int j = 0; j < 4; j++) {
                int e = tid + j * 256;
                int row = e >> 3, c4 = (e & 7) << 2;
                uint4 w = make_uint4(tf32r(pa[j].x), tf32r(pa[j].y), tf32r(pa[j].z), tf32r(pa[j].w));
                *(uint4*)(&As[ns][row * 32 + (c4 ^ ((row & 7) << 2))]) = w;
            }
            if (!TB) {
#pragma unroll
                for (int j = 0; j < 2; j++) {
                    int e = tid + j * 256;
                    int row = e >> 4, c4 = (e & 15) << 2;
                    uint4 w = make_uint4(tf32r(pb[j].x), tf32r(pb[j].y), tf32r(pb[j].z), tf32r(pb[j].w));
                    *(uint4*)(&Bs[ns][row * 64 + (c4 ^ ((row & 7) << 3))]) = w;
                }
            } else {
#pragma unroll
                for (int j = 0; j < 2; j++) {
                    int e = tid + j * 256;
                    int n = e >> 3, c4 = (e & 7) << 2;
                    Bs[ns][(c4 + 0) * 64 + (n ^ (((c4 + 0) & 7) << 3))] = tf32r(pb[j].x);
                    Bs[ns][(c4 + 1) * 64 + (n ^ (((c4 + 1) & 7) << 3))] = tf32r(pb[j].y);
                    Bs[ns][(c4 + 2) * 64 + (n ^ (((c4 + 2) & 7) << 3))] = tf32r(pb[j].z);
                    Bs[ns][(c4 + 3) * 64 + (n ^ (((c4 + 3) & 7) << 3))] = tf32r(pb[j].w);
                }
            }
        }
        __syncthreads();
    }

    // ---- epilogue ----
    float* CrawB = Craw ? Craw + (long)blockIdx.z * sC : nullptr;
    float* CtB   = Ct   ? Ct   + (long)blockIdx.z * sC : nullptr;
#pragma unroll
    for (int mt = 0; mt < 2; mt++) {
#pragma unroll
        for (int nt = 0; nt < 4; nt++) {
            int r = m0 + warpm * 32 + mt * 16 + lg;
            int c = n0 + warpn * 32 + nt * 8 + 2 * lt;
            float v00 = acc[mt][nt][0] * alpha;
            float v01 = acc[mt][nt][1] * alpha;
            float v10 = acc[mt][nt][2] * alpha;
            float v11 = acc[mt][nt][3] * alpha;
            if (CrawB) {
                *(float2*)(CrawB + (long)r * Nd + c)       = make_float2(v00, v01);
                *(float2*)(CrawB + (long)(r + 8) * Nd + c) = make_float2(v10, v11);
            }
            if (CtB) {
                float t00 = ((r == c)         ? dg : 0.f) - v00;
                float t01 = ((r == c + 1)     ? dg : 0.f) - v01;
                float t10 = ((r + 8 == c)     ? dg : 0.f) - v10;
                float t11 = ((r + 8 == c + 1) ? dg : 0.f) - v11;
                *(float2*)(CtB + (long)r * Nd + c)       = make_float2(t00, t01);
                *(float2*)(CtB + (long)(r + 8) * Nd + c) = make_float2(t10, t11);
            }
        }
    }
}

// ---------------- LayerNorm: one block per row of 512 -------------------------
__global__ __launch_bounds__(256) void ln_kernel(
    const float* __restrict__ x, const float* __restrict__ w, const float* __restrict__ b)
{
    long row = blockIdx.x;
    const float* xr = x + row * DD;
    int t = threadIdx.x;
    float v0 = xr[t], v1 = xr[t + 256];
    __shared__ float red[32];

    float s = v0 + v1;
    for (int o = 16; o > 0; o >>= 1) s += __shfl_xor_sync(~0u, s, o);
    if ((t & 31) == 0) red[t >> 5] = s;
    __syncthreads();
    if (t < 32) {
        float ss = (t < 8) ? red[t] : 0.f;
        for (int o = 4; o > 0; o >>= 1) ss += __shfl_xor_sync(~0u, ss, o);
        if (t == 0) red[0] = ss;
    }
    __syncthreads();
    float mu = red[0] * (1.f / DD);
    __syncthreads();

    float d0 = v0 - mu, d1 = v1 - mu;
    float q = d0 * d0 + d1 * d1;
    for (int o = 16; o > 0; o >>= 1) q += __shfl_xor_sync(~0u, q, o);
    if ((t & 31) == 0) red[t >> 5] = q;
    __syncthreads();
    if (t < 32) {
        float ss = (t < 8) ? red[t] : 0.f;
        for (int o = 4; o > 0; o >>= 1) ss += __shfl_xor_sync(~0u, ss, o);
        if (t == 0) red[0] = ss;
    }
    __syncthreads();
    float inv = rsqrtf(red[0] * (1.f / DD) + 1e-5f);
    g_xn[row * DD + t]       = d0 * inv * w[t]       + b[t];
    g_xn[row * DD + t + 256] = d1 * inv * w[t + 256] + b[t + 256];
}

// ---------------- split qkv into [B,H,N,D] (q scaled by DH^-0.5) --------------
__global__ void split_qkv()
{
    long i = (long)blockIdx.x * 256 + threadIdx.x;
    int d = i % DHD; long r = i / DHD;
    int h = r % HH;  long bn = r / HH;
    long src = bn * (3 * DD) + h * DHD + d;
    long b = bn / NN, n = bn % NN;
    long dst = ((b * HH + h) * NN + n) * DHD + d;
    g_q[dst] = g_qkv[src] * 0.125f;
    g_k[dst] = g_qkv[src + DD];
    g_v[dst] = g_qkv[src + 2 * DD];
}

// ---------------- landmarks: mean over blocks of 16 tokens --------------------
__global__ void landmarks()
{
    long i = (long)blockIdx.x * 256 + threadIdx.x;
    int d = i % DHD; long r = i / DHD;
    int m = r % MM;  int bh = r / MM;
    long base = ((long)bh * NN + m * LLm) * DHD + d;
    float sq = 0.f, sk = 0.f;
#pragma unroll
    for (int u = 0; u < LLm; u++) { sq += g_q[base + u * DHD]; sk += g_k[base + u * DHD]; }
    g_ql[i] = sq * (1.f / LLm);
    g_kl[i] = sk * (1.f / LLm);
}

// ---------------- row softmax (W = 256 or 4096), in place ---------------------
template<int W>
__global__ __launch_bounds__(256) void softmax_rows(float* __restrict__ A)
{
    constexpr int VPT = W / 256;
    float* a = A + (long)blockIdx.x * W;
    int t = threadIdx.x;
    float v[VPT];
    float mx = -1e30f;
    __shared__ float red[32];
#pragma unroll
    for (int i = 0; i < VPT; i++) { v[i] = a[t + i * 256]; mx = fmaxf(mx, v[i]); }
    for (int o = 16; o > 0; o >>= 1) mx = fmaxf(mx, __shfl_xor_sync(~0u, mx, o));
    if ((t & 31) == 0) red[t >> 5] = mx;
    __syncthreads();
    if (t < 32) {
        float m2 = (t < 8) ? red[t] : -1e30f;
        for (int o = 4; o > 0; o >>= 1) m2 = fmaxf(m2, __shfl_xor_sync(~0u, m2, o));
        if (t == 0) red[0] = m2;
    }
    __syncthreads();
    mx = red[0];
    __syncthreads();
    float s = 0.f;
#pragma unroll
    for (int i = 0; i < VPT; i++) { v[i] = __expf(v[i] - mx); s += v[i]; }
    for (int o = 16; o > 0; o >>= 1) s += __shfl_xor_sync(~0u, s, o);
    if ((t & 31) == 0) red[t >> 5] = s;
    __syncthreads();
    if (t < 32) {
        float s2 = (t < 8) ? red[t] : 0.f;
        for (int o = 4; o > 0; o >>= 1) s2 += __shfl_xor_sync(~0u, s2, o);
        if (t == 0) red[0] = s2;
    }
    __syncthreads();
    float inv = 1.f / red[0];
#pragma unroll
    for (int i = 0; i < VPT; i++) a[t + i * 256] = v[i] * inv;
}

// ---------------- pinv init helpers ------------------------------------------
__global__ void init_colmax() { g_colmax = 0.f; }

__global__ __launch_bounds__(256) void colmax_kernel()
{
    int bh = blockIdx.x, j = threadIdx.x;
    const float* a = g_a2 + (long)bh * MM * MM;
    float s = 0.f;
    for (int i = 0; i < MM; i++) s += a[i * MM + j];
    __shared__ float red[32];
    float m = s;
    for (int o = 16; o > 0; o >>= 1) m = fmaxf(m, __shfl_xor_sync(~0u, m, o));
    if ((j & 31) == 0) red[j >> 5] = m;
    __syncthreads();
    if (j < 32) {
        float m2 = (j < 8) ? red[j] : -1e30f;
        for (int o = 4; o > 0; o >>= 1) m2 = fmaxf(m2, __shfl_xor_sync(~0u, m2, o));
        if (j == 0) atomicMax((int*)&g_colmax, __float_as_int(m2));
    }
}

__global__ void zinit()
{
    long i = (long)blockIdx.x * 256 + threadIdx.x;
    int col = i % MM; long r = i / MM;
    int row = r % MM; int bh = r / MM;
    float inv = 1.f / g_colmax;
    g_zA[i] = g_a2[((long)bh * MM + col) * MM + row] * inv;
}

// ---------------- depthwise conv residual over sequence dim -------------------
__global__ void conv_res(const float* __restrict__ rw)
{
    long i = (long)blockIdx.x * 256 + threadIdx.x;
    int d = i % DHD; long r = i / DHD;
    int n = r % NN;  int bh = r / NN;
    int h = bh % HH;
    const float* vb = g_v + (long)bh * NN * DHD;
    float acc = 0.f;
#pragma unroll
    for (int j = 0; j < KC; j++) {
        int tt = n + j - KC / 2;
        if (tt >= 0 && tt < NN) acc += rw[h * KC + j] * vb[(long)tt * DHD + d];
    }
    g_o[i] += acc;
}

// ---------------- reshape [B,H,N,D] -> [B,N,H*D] (into g_qkv) -----------------
__global__ void reshape_out()
{
    long i = (long)blockIdx.x * 256 + threadIdx.x;
    int d = i % DHD; long r = i / DHD;
    int h = r % HH;  long bn = r / HH;
    long b = bn / NN, n = bn % NN;
    g_qkv[bn * DD + h * DHD + d] = g_o[((b * HH + h) * NN + n) * DHD + d];
}

// ---------------- y = x + proj + b_out ----------------------------------------
__global__ void final_add(const float* __restrict__ x, const float* __restrict__ bout,
                          float* __restrict__ y)
{
    long i = (long)blockIdx.x * 256 + threadIdx.x;
    y[i] = x[i] + g_xn[i] + bout[i % DD];
}

// ---------------- host orchestration ------------------------------------------
extern "C" void kernel_launch(void* const* d_in, const int* in_sizes, int n_in,
                              void* d_out, int out_size)
{
    const float* x      = (const float*)d_in[0];
    const float* norm_w = (const float*)d_in[1];
    const float* norm_b = (const float*)d_in[2];
    const float* w_qkv  = (const float*)d_in[3];
    const float* w_out  = (const float*)d_in[4];
    const float* b_out  = (const float*)d_in[5];
    const float* res_w  = (const float*)d_in[6];
    float* y = (float*)d_out;

    float *p_xn, *p_qkv, *p_q, *p_k, *p_v, *p_o, *p_ql, *p_kl;
    float *p_a1, *p_a3, *p_a2, *p_zA, *p_zB, *p_xz, *p_t1, *p_t2, *p_a3v, *p_W;
    cudaGetSymbolAddress((void**)&p_xn,  g_xn);
    cudaGetSymbolAddress((void**)&p_qkv, g_qkv);
    cudaGetSymbolAddress((void**)&p_q,   g_q);
    cudaGetSymbolAddress((void**)&p_k,   g_k);
    cudaGetSymbolAddress((void**)&p_v,   g_v);
    cudaGetSymbolAddress((void**)&p_o,   g_o);
    cudaGetSymbolAddress((void**)&p_ql,  g_ql);
    cudaGetSymbolAddress((void**)&p_kl,  g_kl);
    cudaGetSymbolAddress((void**)&p_a1,  g_a1);
    cudaGetSymbolAddress((void**)&p_a3,  g_a3);
    cudaGetSymbolAddress((void**)&p_a2,  g_a2);
    cudaGetSymbolAddress((void**)&p_zA,  g_zA);
    cudaGetSymbolAddress((void**)&p_zB,  g_zB);
    cudaGetSymbolAddress((void**)&p_xz,  g_xz);
    cudaGetSymbolAddress((void**)&p_t1,  g_t1);
    cudaGetSymbolAddress((void**)&p_t2,  g_t2);
    cudaGetSymbolAddress((void**)&p_a3v, g_a3v);
    cudaGetSymbolAddress((void**)&p_W,   g_W);

    const long MM2 = (long)MM * MM;
    float* nul = nullptr;

    // 1. LayerNorm
    ln_kernel<<<BB * NN, 256>>>(x, norm_w, norm_b);
    // 2. qkv = xn @ w_qkv   [16384,512]@[512,1536]
    mmagemm<false><<<dim3((3 * DD) / 64, (BB * NN) / 128, 1), 256>>>(
        p_xn, w_qkv, p_qkv, nul, BB * NN, 3 * DD, DD, 0, 0, 0, 1.f, 0.f);
    // 3. split into heads (+ q scale)
    split_qkv<<<(BB * NN * DD) / 256, 256>>>();
    // 4. landmarks
    landmarks<<<(BH * MM * DHD) / 256, 256>>>();
    // 5. sim2 = ql @ kl^T  -> softmax -> a2
    mmagemm<true><<<dim3(MM / 64, MM / 128, BH), 256>>>(
        p_ql, p_kl, p_a2, nul, MM, MM, DHD, (long)MM * DHD, (long)MM * DHD, MM2, 1.f, 0.f);
    softmax_rows<MM><<<BH * MM, 256>>>(p_a2);
    // 6. pinv init: z = a2^T / max(colsum)
    init_colmax<<<1, 1>>>();
    colmax_kernel<<<BH, 256>>>();
    zinit<<<(BH * MM * MM) / 256, 256>>>();
    // 7. Newton-Schulz, 6 iterations (aIminus fused into GEMM epilogues)
    float* zin = p_zA; float* zout = p_zB;
    for (int it = 0; it < NITER; it++) {
        // xz = a2@zin ; t1 = 7I - xz
        mmagemm<false><<<dim3(MM / 64, MM / 128, BH), 256>>>(
            p_a2, zin, p_xz, p_t1, MM, MM, MM, MM2, MM2, MM2, 1.f, 7.f);
        // t2 = 15I - xz@t1
        mmagemm<false><<<dim3(MM / 64, MM / 128, BH), 256>>>(
            p_xz, p_t1, nul, p_t2, MM, MM, MM, MM2, MM2, MM2, 1.f, 15.f);
        // t1 = 13I - xz@t2
        mmagemm<false><<<dim3(MM / 64, MM / 128, BH), 256>>>(
            p_xz, p_t2, nul, p_t1, MM, MM, MM, MM2, MM2, MM2, 1.f, 13.f);
        // zout = 0.25 * zin@t1
        mmagemm<false><<<dim3(MM / 64, MM / 128, BH), 256>>>(
            zin, p_t1, zout, nul, MM, MM, MM, MM2, MM2, MM2, 0.25f, 0.f);
        float* tmp = zin; zin = zout; zout = tmp;
    }
    // 8. sim1 = q @ kl^T -> softmax -> a1
    mmagemm<true><<<dim3(MM / 64, NN / 128, BH), 256>>>(
        p_q, p_kl, p_a1, nul, NN, MM, DHD, (long)NN * DHD, (long)MM * DHD, (long)NN * MM, 1.f, 0.f);
    softmax_rows<MM><<<BH * NN, 256>>>(p_a1);
    // 9. sim3 = ql @ k^T -> softmax -> a3
    mmagemm<true><<<dim3(NN / 64, MM / 128, BH), 256>>>(
        p_ql, p_k, p_a3, nul, MM, NN, DHD, (long)MM * DHD, (long)NN * DHD, (long)MM * NN, 1.f, 0.f);
    softmax_rows<NN><<<BH * MM, 256>>>(p_a3);
    // 10. a3v = a3 @ v   [256,4096]@[4096,64]
    mmagemm<false><<<dim3(1, MM / 128, BH), 256>>>(
        p_a3, p_v, p_a3v, nul, MM, DHD, NN, (long)MM * NN, (long)NN * DHD, (long)MM * DHD, 1.f, 0.f);
    // 11. W = z @ a3v    [256,256]@[256,64]
    mmagemm<false><<<dim3(1, MM / 128, BH), 256>>>(
        zin, p_a3v, p_W, nul, MM, DHD, MM, MM2, (long)MM * DHD, (long)MM * DHD, 1.f, 0.f);
    // 12. out = a1 @ W   [4096,256]@[256,64]
    mmagemm<false><<<dim3(1, NN / 128, BH), 256>>>(
        p_a1, p_W, p_o, nul, NN, DHD, MM, (long)NN * MM, (long)MM * DHD, (long)NN * DHD, 1.f, 0.f);
    // 13. += depthwise conv of v
    conv_res<<<(BH * NN * DHD) / 256, 256>>>(res_w);
    // 14. reshape to [B,N,512] (into g_qkv)
    reshape_out<<<(BB * NN * DD) / 256, 256>>>();
    // 15. proj = att @ w_out (into g_xn)
    mmagemm<false><<<dim3(DD / 64, (BB * NN) / 128, 1), 256>>>(
        p_qkv, w_out, p_xn, nul, BB * NN, DD, DD, 0, 0, 0, 1.f, 0.f);
    // 16. y = x + proj + b_out
    final_add<<<(BB * NN * DD) / 256, 256>>>(x, b_out, y);
}

// round 5
// speedup vs baseline: 2.3440x; 1.1933x over previous
#include <cuda_runtime.h>
#include <cstdint>

#define BB 4
#define NN 4096
#define DD 512
#define HH 8
#define DHD 64
#define MM 256
#define LLm 16
#define NITER 6
#define KC 33
#define BH (BB*HH)

// ---------------- scratch (static device allocations; no cudaMalloc) ----------
__device__ float g_xn [BB*NN*DD];            // also reused as proj output
__device__ float g_qkv[BB*NN*3*DD];          // reused as att (fused reshape out)
__device__ float g_q  [BH*NN*DHD];
__device__ float g_k  [BH*NN*DHD];
__device__ float g_v  [BH*NN*DHD];
__device__ float g_o  [BH*NN*DHD];
__device__ float g_ql [BH*MM*DHD];
__device__ float g_kl [BH*MM*DHD];
__device__ float g_a1 [(long)BH*NN*MM];
__device__ float g_a3 [(long)BH*MM*NN];
__device__ float g_a2 [BH*MM*MM];
__device__ float g_zA [BH*MM*MM];
__device__ float g_zB [BH*MM*MM];
__device__ float g_xz [BH*MM*MM];
__device__ float g_t1 [BH*MM*MM];
__device__ float g_t2 [BH*MM*MM];
__device__ float g_a3v[BH*MM*DHD];
__device__ float g_W  [BH*MM*DHD];
__device__ float g_colmax;

// ---------------- TF32 helpers ------------------------------------------------
__device__ __forceinline__ uint32_t tf32r(float x) {
    uint32_t y;
    asm("cvt.rna.tf32.f32 %0, %1;" : "=r"(y) : "f"(x));
    return y;
}
__device__ __forceinline__ void mma_tf32(float* c, const uint32_t* a, const uint32_t* b) {
    asm volatile(
        "mma.sync.aligned.m16n8k8.row.col.f32.tf32.tf32.f32 "
        "{%0,%1,%2,%3}, {%4,%5,%6,%7}, {%8,%9}, {%0,%1,%2,%3};"
        : "+f"(c[0]), "+f"(c[1]), "+f"(c[2]), "+f"(c[3])
        : "r"(a[0]), "r"(a[1]), "r"(a[2]), "r"(a[3]), "r"(b[0]), "r"(b[1]));
}

// =============================================================================
// mmagemm2: 128x128x32 TF32 GEMM. 256 threads, 8 warps (4m x 2n), warp 32x64.
// MODE 0: Craw = alpha*acc (if non-null); Ct = dg*I - alpha*acc (if non-null)
// MODE 1: qkv split epilogue -> qp/kp/vp in [B,H,N,D] layout, q scaled 0.125
// Requires M%128==0, N%128==0, K%32==0.
// =============================================================================
template<bool TB, int MODE>
__global__ __launch_bounds__(256) void mmagemm2(
    const float* __restrict__ Ag, const float* __restrict__ Bg,
    float* __restrict__ Craw, float* __restrict__ Ct,
    float* __restrict__ qp, float* __restrict__ kp, float* __restrict__ vp,
    int Md, int Nd, int Kd, long sA, long sB, long sC,
    float alpha, float dg)
{
    __shared__ uint32_t As[128 * 32];   // idx = m*32 + (k ^ ((m&7)<<2))
    __shared__ uint32_t Bs[32 * 128];   // idx = k*128 + (n ^ ((k&7)<<3))

    const float* A = Ag + (long)blockIdx.z * sA;
    const float* B = Bg + (long)blockIdx.z * sB;
    const int m0 = blockIdx.y * 128;
    const int n0 = blockIdx.x * 128;
    const int tid = threadIdx.x;
    const int wid = tid >> 5, lane = tid & 31;
    const int warpm = wid & 3, warpn = wid >> 2;   // 4m x 2n
    const int lg = lane >> 2, lt = lane & 3;

    float acc[2][8][4];
#pragma unroll
    for (int mt = 0; mt < 2; mt++)
#pragma unroll
        for (int nt = 0; nt < 8; nt++)
#pragma unroll
            for (int i = 0; i < 4; i++) acc[mt][nt][i] = 0.f;

    const int nk = Kd >> 5;

    // ---- initial tile load ----
    {
#pragma unroll
        for (int j = 0; j < 4; j++) {
            int e = tid + j * 256;
            int row = e >> 3, c4 = (e & 7) << 2;
            float4 v = *(const float4*)(A + (long)(m0 + row) * Kd + c4);
            uint4 w = make_uint4(tf32r(v.x), tf32r(v.y), tf32r(v.z), tf32r(v.w));
            *(uint4*)(&As[row * 32 + (c4 ^ ((row & 7) << 2))]) = w;
        }
        if (!TB) {
#pragma unroll
            for (int j = 0; j < 4; j++) {
                int e = tid + j * 256;
                int row = e >> 5, c4 = (e & 31) << 2;
                float4 v = *(const float4*)(B + (long)row * Nd + n0 + c4);
                uint4 w = make_uint4(tf32r(v.x), tf32r(v.y), tf32r(v.z), tf32r(v.w));
                *(uint4*)(&Bs[row * 128 + (c4 ^ ((row & 7) << 3))]) = w;
            }
        } else {
#pragma unroll
            for (int j = 0; j < 4; j++) {
                int e = tid + j * 256;
                int n = e >> 3, c4 = (e & 7) << 2;
                float4 v = *(const float4*)(B + (long)(n0 + n) * Kd + c4);
                Bs[(c4 + 0) * 128 + (n ^ (((c4 + 0) & 7) << 3))] = tf32r(v.x);
                Bs[(c4 + 1) * 128 + (n ^ (((c4 + 1) & 7) << 3))] = tf32r(v.y);
                Bs[(c4 + 2) * 128 + (n ^ (((c4 + 2) & 7) << 3))] = tf32r(v.z);
                Bs[(c4 + 3) * 128 + (n ^ (((c4 + 3) & 7) << 3))] = tf32r(v.w);
            }
        }
    }
    __syncthreads();

    for (int kt = 0; kt < nk; kt++) {
        float4 pa[4], pb[4];
        const bool more = (kt + 1 < nk);
        if (more) {
            const int k0 = (kt + 1) << 5;
#pragma unroll
            for (int j = 0; j < 4; j++) {
                int e = tid + j * 256;
                int row = e >> 3, c4 = (e & 7) << 2;
                pa[j] = *(const float4*)(A + (long)(m0 + row) * Kd + k0 + c4);
            }
            if (!TB) {
#pragma unroll
                for (int j = 0; j < 4; j++) {
                    int e = tid + j * 256;
                    int row = e >> 5, c4 = (e & 31) << 2;
                    pb[j] = *(const float4*)(B + (long)(k0 + row) * Nd + n0 + c4);
                }
            } else {
#pragma unroll
                for (int j = 0; j < 4; j++) {
                    int e = tid + j * 256;
                    int n = e >> 3, c4 = (e & 7) << 2;
                    pb[j] = *(const float4*)(B + (long)(n0 + n) * Kd + k0 + c4);
                }
            }
        }

#pragma unroll
        for (int kk = 0; kk < 32; kk += 8) {
            uint32_t af[2][4], bf[8][2];
#pragma unroll
            for (int mt = 0; mt < 2; mt++) {
                int r = warpm * 32 + mt * 16 + lg;
                int k = kk + lt;
                af[mt][0] = As[r * 32 + (k ^ ((r & 7) << 2))];
                af[mt][1] = As[(r + 8) * 32 + (k ^ (((r + 8) & 7) << 2))];
                af[mt][2] = As[r * 32 + ((k + 4) ^ ((r & 7) << 2))];
                af[mt][3] = As[(r + 8) * 32 + ((k + 4) ^ (((r + 8) & 7) << 2))];
            }
#pragma unroll
            for (int nt = 0; nt < 8; nt++) {
                int c = warpn * 64 + nt * 8 + lg;
                int k = kk + lt;
                bf[nt][0] = Bs[k * 128 + (c ^ ((k & 7) << 3))];
                bf[nt][1] = Bs[(k + 4) * 128 + (c ^ (((k + 4) & 7) << 3))];
            }
#pragma unroll
            for (int mt = 0; mt < 2; mt++)
#pragma unroll
                for (int nt = 0; nt < 8; nt++)
                    mma_tf32(acc[mt][nt], af[mt], bf[nt]);
        }
        __syncthreads();

        if (more) {
#pragma unroll
            for (int j = 0; j < 4; j++) {
                int e = tid + j * 256;
                int row = e >> 3, c4 = (e & 7) << 2;
                uint4 w = make_uint4(tf32r(pa[j].x), tf32r(pa[j].y), tf32r(pa[j].z), tf32r(pa[j].w));
                *(uint4*)(&As[row * 32 + (c4 ^ ((row & 7) << 2))]) = w;
            }
            if (!TB) {
#pragma unroll
                for (int j = 0; j < 4; j++) {
                    int e = tid + j * 256;
                    int row = e >> 5, c4 = (e & 31) << 2;
                    uint4 w = make_uint4(tf32r(pb[j].x), tf32r(pb[j].y), tf32r(pb[j].z), tf32r(pb[j].w));
                    *(uint4*)(&Bs[row * 128 + (c4 ^ ((row & 7) << 3))]) = w;
                }
            } else {
#pragma unroll
                for (int j = 0; j < 4; j++) {
                    int e = tid + j * 256;
                    int n = e >> 3, c4 = (e & 7) << 2;
                    Bs[(c4 + 0) * 128 + (n ^ (((c4 + 0) & 7) << 3))] = tf32r(pb[j].x);
                    Bs[(c4 + 1) * 128 + (n ^ (((c4 + 1) & 7) << 3))] = tf32r(pb[j].y);
                    Bs[(c4 + 2) * 128 + (n ^ (((c4 + 2) & 7) << 3))] = tf32r(pb[j].z);
                    Bs[(c4 + 3) * 128 + (n ^ (((c4 + 3) & 7) << 3))] = tf32r(pb[j].w);
                }
            }
            __syncthreads();
        }
    }

    // ---- epilogue ----
    if (MODE == 0) {
        float* CrawB = Craw ? Craw + (long)blockIdx.z * sC : nullptr;
        float* CtB   = Ct   ? Ct   + (long)blockIdx.z * sC : nullptr;
#pragma unroll
        for (int mt = 0; mt < 2; mt++) {
#pragma unroll
            for (int nt = 0; nt < 8; nt++) {
                int r = m0 + warpm * 32 + mt * 16 + lg;
                int c = n0 + warpn * 64 + nt * 8 + 2 * lt;
                float v00 = acc[mt][nt][0] * alpha;
                float v01 = acc[mt][nt][1] * alpha;
                float v10 = acc[mt][nt][2] * alpha;
                float v11 = acc[mt][nt][3] * alpha;
                if (CrawB) {
                    *(float2*)(CrawB + (long)r * Nd + c)       = make_float2(v00, v01);
                    *(float2*)(CrawB + (long)(r + 8) * Nd + c) = make_float2(v10, v11);
                }
                if (CtB) {
                    float t00 = ((r == c)         ? dg : 0.f) - v00;
                    float t01 = ((r == c + 1)     ? dg : 0.f) - v01;
                    float t10 = ((r + 8 == c)     ? dg : 0.f) - v10;
                    float t11 = ((r + 8 == c + 1) ? dg : 0.f) - v11;
                    *(float2*)(CtB + (long)r * Nd + c)       = make_float2(t00, t01);
                    *(float2*)(CtB + (long)(r + 8) * Nd + c) = make_float2(t10, t11);
                }
            }
        }
    } else {
        // qkv split: row m -> (b,n); col c -> (which, h, d)
#pragma unroll
        for (int mt = 0; mt < 2; mt++) {
#pragma unroll
            for (int nt = 0; nt < 8; nt++) {
                int c = n0 + warpn * 64 + nt * 8 + 2 * lt;
                int which = c >> 9, cc = c & 511;
                int h = cc >> 6, d = cc & 63;
                float* dstb = (which == 0) ? qp : (which == 1) ? kp : vp;
                float sc = (which == 0) ? 0.125f : 1.f;
#pragma unroll
                for (int half = 0; half < 2; half++) {
                    int m = m0 + warpm * 32 + mt * 16 + half * 8 + lg;
                    int b = m >> 12, n = m & 4095;
                    long dst = (((long)(b * HH + h) * NN + n)) * DHD + d;
                    *(float2*)(dstb + dst) = make_float2(acc[mt][nt][half*2] * sc,
                                                         acc[mt][nt][half*2+1] * sc);
                }
            }
        }
    }
}

// =============================================================================
// old BN=64 GEMM kept for N==64 cases (a3v, W, out). Double-buffered, 48KB smem.
// =============================================================================
template<bool TB>
__global__ __launch_bounds__(256) void mmagemm(
    const float* __restrict__ Ag, const float* __restrict__ Bg,
    float* __restrict__ Craw,
    int Md, int Nd, int Kd, long sA, long sB, long sC, float alpha)
{
    __shared__ uint32_t As[2][128 * 32];
    __shared__ uint32_t Bs[2][32 * 64];

    const float* A = Ag + (long)blockIdx.z * sA;
    const float* B = Bg + (long)blockIdx.z * sB;
    const int m0 = blockIdx.y * 128;
    const int n0 = blockIdx.x * 64;
    const int tid = threadIdx.x;
    const int wid = tid >> 5, lane = tid & 31;
    const int warpm = wid & 3, warpn = wid >> 2;
    const int lg = lane >> 2, lt = lane & 3;

    float acc[2][4][4];
#pragma unroll
    for (int mt = 0; mt < 2; mt++)
#pragma unroll
        for (int nt = 0; nt < 4; nt++)
#pragma unroll
            for (int i = 0; i < 4; i++) acc[mt][nt][i] = 0.f;

    const int nk = Kd >> 5;

    {
#pragma unroll
        for (int j = 0; j < 4; j++) {
            int e = tid + j * 256;
            int row = e >> 3, c4 = (e & 7) << 2;
            float4 v = *(const float4*)(A + (long)(m0 + row) * Kd + c4);
            uint4 w = make_uint4(tf32r(v.x), tf32r(v.y), tf32r(v.z), tf32r(v.w));
            *(uint4*)(&As[0][row * 32 + (c4 ^ ((row & 7) << 2))]) = w;
        }
        if (!TB) {
#pragma unroll
            for (int j = 0; j < 2; j++) {
                int e = tid + j * 256;
                int row = e >> 4, c4 = (e & 15) << 2;
                float4 v = *(const float4*)(B + (long)row * Nd + n0 + c4);
                uint4 w = make_uint4(tf32r(v.x), tf32r(v.y), tf32r(v.z), tf32r(v.w));
                *(uint4*)(&Bs[0][row * 64 + (c4 ^ ((row & 7) << 3))]) = w;
            }
        } else {
#pragma unroll
            for (int j = 0; j < 2; j++) {
                int e = tid + j * 256;
                int n = e >> 3, c4 = (e & 7) << 2;
                float4 v = *(const float4*)(B + (long)(n0 + n) * Kd + c4);
                Bs[0][(c4 + 0) * 64 + (n ^ (((c4 + 0) & 7) << 3))] = tf32r(v.x);
                Bs[0][(c4 + 1) * 64 + (n ^ (((c4 + 1) & 7) << 3))] = tf32r(v.y);
                Bs[0][(c4 + 2) * 64 + (n ^ (((c4 + 2) & 7) << 3))] = tf32r(v.z);
                Bs[0][(c4 + 3) * 64 + (n ^ (((c4 + 3) & 7) << 3))] = tf32r(v.w);
            }
        }
    }
    __syncthreads();

    for (int kt = 0; kt < nk; kt++) {
        const int st = kt & 1;
        float4 pa[4], pb[2];
        const bool more = (kt + 1 < nk);
        if (more) {
            const int k0 = (kt + 1) << 5;
#pragma unroll
            for (int j = 0; j < 4; j++) {
                int e = tid + j * 256;
                int row = e >> 3, c4 = (e & 7) << 2;
                pa[j] = *(const float4*)(A + (long)(m0 + row) * Kd + k0 + c4);
            }
            if (!TB) {
#pragma unroll
                for (int j = 0; j < 2; j++) {
                    int e = tid + j * 256;
                    int row = e >> 4, c4 = (e & 15) << 2;
                    pb[j] = *(const float4*)(B + (long)(k0 + row) * Nd + n0 + c4);
                }
            } else {
#pragma unroll
                for (int j = 0; j < 2; j++) {
                    int e = tid + j * 256;
                    int n = e >> 3, c4 = (e & 7) << 2;
                    pb[j] = *(const float4*)(B + (long)(n0 + n) * Kd + k0 + c4);
                }
            }
        }

#pragma unroll
        for (int kk = 0; kk < 32; kk += 8) {
            uint32_t af[2][4], bf[4][2];
#pragma unroll
            for (int mt = 0; mt < 2; mt++) {
                int r = warpm * 32 + mt * 16 + lg;
                int k = kk + lt;
                af[mt][0] = As[st][r * 32 + (k ^ ((r & 7) << 2))];
                af[mt][1] = As[st][(r + 8) * 32 + (k ^ (((r + 8) & 7) << 2))];
                af[mt][2] = As[st][r * 32 + ((k + 4) ^ ((r & 7) << 2))];
                af[mt][3] = As[st][(r + 8) * 32 + ((k + 4) ^ (((r + 8) & 7) << 2))];
            }
#pragma unroll
            for (int nt = 0; nt < 4; nt++) {
                int c = warpn * 32 + nt * 8 + lg;
                int k = kk + lt;
                bf[nt][0] = Bs[st][k * 64 + (c ^ ((k & 7) << 3))];
                bf[nt][1] = Bs[st][(k + 4) * 64 + (c ^ (((k + 4) & 7) << 3))];
            }
#pragma unroll
            for (int mt = 0; mt < 2; mt++)
#pragma unroll
                for (int nt = 0; nt < 4; nt++)
                    mma_tf32(acc[mt][nt], af[mt], bf[nt]);
        }

        if (more) {
            const int ns = st ^ 1;
#pragma unroll
            for (int j = 0; j < 4; j++) {
                int e = tid + j * 256;
                int row = e >> 3, c4 = (e & 7) << 2;
                uint4 w = make_uint4(tf32r(pa[j].x), tf32r(pa[j].y), tf32r(pa[j].z), tf32r(pa[j].w));
                *(uint4*)(&As[ns][row * 32 + (c4 ^ ((row & 7) << 2))]) = w;
            }
            if (!TB) {
#pragma unroll
                for (int j = 0; j < 2; j++) {
                    int e = tid + j * 256;
                    int row = e >> 4, c4 = (e & 15) << 2;
                    uint4 w = make_uint4(tf32r(pb[j].x), tf32r(pb[j].y), tf32r(pb[j].z), tf32r(pb[j].w));
                    *(uint4*)(&Bs[ns][row * 64 + (c4 ^ ((row & 7) << 3))]) = w;
                }
            } else {
#pragma unroll
                for (int j = 0; j < 2; j++) {
                    int e = tid + j * 256;
                    int n = e >> 3, c4 = (e & 7) << 2;
                    Bs[ns][(c4 + 0) * 64 + (n ^ (((c4 + 0) & 7) << 3))] = tf32r(pb[j].x);
                    Bs[ns][(c4 + 1) * 64 + (n ^ (((c4 + 1) & 7) << 3))] = tf32r(pb[j].y);
                    Bs[ns][(c4 + 2) * 64 + (n ^ (((c4 + 2) & 7) << 3))] = tf32r(pb[j].z);
                    Bs[ns][(c4 + 3) * 64 + (n ^ (((c4 + 3) & 7) << 3))] = tf32r(pb[j].w);
                }
            }
        }
        __syncthreads();
    }

    float* CrawB = Craw + (long)blockIdx.z * sC;
#pragma unroll
    for (int mt = 0; mt < 2; mt++) {
#pragma unroll
        for (int nt = 0; nt < 4; nt++) {
            int r = m0 + warpm * 32 + mt * 16 + lg;
            int c = n0 + warpn * 32 + nt * 8 + 2 * lt;
            *(float2*)(CrawB + (long)r * Nd + c) =
                make_float2(acc[mt][nt][0] * alpha, acc[mt][nt][1] * alpha);
            *(float2*)(CrawB + (long)(r + 8) * Nd + c) =
                make_float2(acc[mt][nt][2] * alpha, acc[mt][nt][3] * alpha);
        }
    }
}

// =============================================================================
// sim_softmax: Out = softmax_row(A @ B^T), A [Md x 64], B [256 x 64], Out [Md x 256]
// BM=64 rows per block. 8 warps (2m x 4n), warp tile 32x64. Fused row softmax.
// =============================================================================
__global__ __launch_bounds__(256) void sim_softmax(
    const float* __restrict__ Ag, const float* __restrict__ Bg,
    float* __restrict__ Og, long sA, long sB, long sO)
{
    __shared__ uint32_t As[64 * 32];    // idx = m*32 + (k ^ ((m&7)<<2))
    __shared__ uint32_t Bs[32 * 256];   // idx = k*256 + (n ^ ((k&7)<<3))
    __shared__ float redm[64 * 4];
    __shared__ float reds[64 * 4];

    const float* A = Ag + (long)blockIdx.z * sA;
    const float* B = Bg + (long)blockIdx.z * sB;
    float*       O = Og + (long)blockIdx.z * sO;
    const int m0 = blockIdx.x * 64;
    const int tid = threadIdx.x;
    const int wid = tid >> 5, lane = tid & 31;
    const int warpm = wid & 1, warpn = wid >> 1;   // 2m x 4n
    const int lg = lane >> 2, lt = lane & 3;

    float acc[2][8][4];
#pragma unroll
    for (int mt = 0; mt < 2; mt++)
#pragma unroll
        for (int nt = 0; nt < 8; nt++)
#pragma unroll
            for (int i = 0; i < 4; i++) acc[mt][nt][i] = 0.f;

#pragma unroll
    for (int kt = 0; kt < 2; kt++) {
        const int k0 = kt * 32;
        // A tile 64x32
#pragma unroll
        for (int j = 0; j < 2; j++) {
            int e = tid + j * 256;
            int row = e >> 3, c4 = (e & 7) << 2;
            float4 v = *(const float4*)(A + (long)(m0 + row) * DHD + k0 + c4);
            uint4 w = make_uint4(tf32r(v.x), tf32r(v.y), tf32r(v.z), tf32r(v.w));
            *(uint4*)(&As[row * 32 + (c4 ^ ((row & 7) << 2))]) = w;
        }
        // B tile 256 rows x 32 k (transposed store)
#pragma unroll
        for (int j = 0; j < 8; j++) {
            int e = tid + j * 256;
            int n = e >> 3, c4 = (e & 7) << 2;
            float4 v = *(const float4*)(B + (long)n * DHD + k0 + c4);
            Bs[(c4 + 0) * 256 + (n ^ (((c4 + 0) & 7) << 3))] = tf32r(v.x);
            Bs[(c4 + 1) * 256 + (n ^ (((c4 + 1) & 7) << 3))] = tf32r(v.y);
            Bs[(c4 + 2) * 256 + (n ^ (((c4 + 2) & 7) << 3))] = tf32r(v.z);
            Bs[(c4 + 3) * 256 + (n ^ (((c4 + 3) & 7) << 3))] = tf32r(v.w);
        }
        __syncthreads();

#pragma unroll
        for (int kk = 0; kk < 32; kk += 8) {
            uint32_t af[2][4], bf[8][2];
#pragma unroll
            for (int mt = 0; mt < 2; mt++) {
                int r = warpm * 32 + mt * 16 + lg;
                int k = kk + lt;
                af[mt][0] = As[r * 32 + (k ^ ((r & 7) << 2))];
                af[mt][1] = As[(r + 8) * 32 + (k ^ (((r + 8) & 7) << 2))];
                af[mt][2] = As[r * 32 + ((k + 4) ^ ((r & 7) << 2))];
                af[mt][3] = As[(r + 8) * 32 + ((k + 4) ^ (((r + 8) & 7) << 2))];
            }
#pragma unroll
            for (int nt = 0; nt < 8; nt++) {
                int c = warpn * 64 + nt * 8 + lg;
                int k = kk + lt;
                bf[nt][0] = Bs[k * 256 + (c ^ ((k & 7) << 3))];
                bf[nt][1] = Bs[(k + 4) * 256 + (c ^ (((k + 4) & 7) << 3))];
            }
#pragma unroll
            for (int mt = 0; mt < 2; mt++)
#pragma unroll
                for (int nt = 0; nt < 8; nt++)
                    mma_tf32(acc[mt][nt], af[mt], bf[nt]);
        }
        __syncthreads();
    }

    // ---- fused row softmax over 256 cols (4 warpn strips) ----
    // phase 1: per-row local max over this warp's 64 cols
#pragma unroll
    for (int mt = 0; mt < 2; mt++)
#pragma unroll
        for (int half = 0; half < 2; half++) {
            float mx = -1e30f;
#pragma unroll
            for (int nt = 0; nt < 8; nt++) {
                mx = fmaxf(mx, acc[mt][nt][half * 2]);
                mx = fmaxf(mx, acc[mt][nt][half * 2 + 1]);
            }
            mx = fmaxf(mx, __shfl_xor_sync(~0u, mx, 1));
            mx = fmaxf(mx, __shfl_xor_sync(~0u, mx, 2));
            int rloc = warpm * 32 + mt * 16 + half * 8 + lg;
            if (lt == 0) redm[rloc * 4 + warpn] = mx;
        }
    __syncthreads();
    // phase 2: exp + local sum
#pragma unroll
    for (int mt = 0; mt < 2; mt++)
#pragma unroll
        for (int half = 0; half < 2; half++) {
            int rloc = warpm * 32 + mt * 16 + half * 8 + lg;
            float m4 = fmaxf(fmaxf(redm[rloc * 4 + 0], redm[rloc * 4 + 1]),
                             fmaxf(redm[rloc * 4 + 2], redm[rloc * 4 + 3]));
            float s = 0.f;
#pragma unroll
            for (int nt = 0; nt < 8; nt++) {
                float e0 = __expf(acc[mt][nt][half * 2]     - m4);
                float e1 = __expf(acc[mt][nt][half * 2 + 1] - m4);
                acc[mt][nt][half * 2]     = e0;
                acc[mt][nt][half * 2 + 1] = e1;
                s += e0 + e1;
            }
            s += __shfl_xor_sync(~0u, s, 1);
            s += __shfl_xor_sync(~0u, s, 2);
            if (lt == 0) reds[rloc * 4 + warpn] = s;
        }
    __syncthreads();
    // phase 3: normalize + write
#pragma unroll
    for (int mt = 0; mt < 2; mt++)
#pragma unroll
        for (int half = 0; half < 2; half++) {
            int rloc = warpm * 32 + mt * 16 + half * 8 + lg;
            float tot = reds[rloc * 4 + 0] + reds[rloc * 4 + 1]
                      + reds[rloc * 4 + 2] + reds[rloc * 4 + 3];
            float inv = 1.f / tot;
            int r = m0 + rloc;
#pragma unroll
            for (int nt = 0; nt < 8; nt++) {
                int c = warpn * 64 + nt * 8 + 2 * lt;
                *(float2*)(O + (long)r * MM + c) =
                    make_float2(acc[mt][nt][half * 2] * inv, acc[mt][nt][half * 2 + 1] * inv);
            }
        }
}

// ---------------- LayerNorm: one block per row of 512 -------------------------
__global__ __launch_bounds__(256) void ln_kernel(
    const float* __restrict__ x, const float* __restrict__ w, const float* __restrict__ b)
{
    long row = blockIdx.x;
    const float* xr = x + row * DD;
    int t = threadIdx.x;
    float v0 = xr[t], v1 = xr[t + 256];
    __shared__ float red[32];

    float s = v0 + v1;
    for (int o = 16; o > 0; o >>= 1) s += __shfl_xor_sync(~0u, s, o);
    if ((t & 31) == 0) red[t >> 5] = s;
    __syncthreads();
    if (t < 32) {
        float ss = (t < 8) ? red[t] : 0.f;
        for (int o = 4; o > 0; o >>= 1) ss += __shfl_xor_sync(~0u, ss, o);
        if (t == 0) red[0] = ss;
    }
    __syncthreads();
    float mu = red[0] * (1.f / DD);
    __syncthreads();

    float d0 = v0 - mu, d1 = v1 - mu;
    float q = d0 * d0 + d1 * d1;
    for (int o = 16; o > 0; o >>= 1) q += __shfl_xor_sync(~0u, q, o);
    if ((t & 31) == 0) red[t >> 5] = q;
    __syncthreads();
    if (t < 32) {
        float ss = (t < 8) ? red[t] : 0.f;
        for (int o = 4; o > 0; o >>= 1) ss += __shfl_xor_sync(~0u, ss, o);
        if (t == 0) red[0] = ss;
    }
    __syncthreads();
    float inv = rsqrtf(red[0] * (1.f / DD) + 1e-5f);
    g_xn[row * DD + t]       = d0 * inv * w[t]       + b[t];
    g_xn[row * DD + t + 256] = d1 * inv * w[t + 256] + b[t + 256];
}

// ---------------- landmarks: mean over blocks of 16 tokens --------------------
__global__ void landmarks()
{
    long i = (long)blockIdx.x * 256 + threadIdx.x;
    int d = i % DHD; long r = i / DHD;
    int m = r % MM;  int bh = r / MM;
    long base = ((long)bh * NN + m * LLm) * DHD + d;
    float sq = 0.f, sk = 0.f;
#pragma unroll
    for (int u = 0; u < LLm; u++) { sq += g_q[base + u * DHD]; sk += g_k[base + u * DHD]; }
    g_ql[i] = sq * (1.f / LLm);
    g_kl[i] = sk * (1.f / LLm);
}

// ---------------- row softmax W=4096, in place (for a3) -----------------------
template<int W>
__global__ __launch_bounds__(256) void softmax_rows(float* __restrict__ A)
{
    constexpr int VPT = W / 256;
    float* a = A + (long)blockIdx.x * W;
    int t = threadIdx.x;
    float v[VPT];
    float mx = -1e30f;
    __shared__ float red[32];
#pragma unroll
    for (int i = 0; i < VPT; i++) { v[i] = a[t + i * 256]; mx = fmaxf(mx, v[i]); }
    for (int o = 16; o > 0; o >>= 1) mx = fmaxf(mx, __shfl_xor_sync(~0u, mx, o));
    if ((t & 31) == 0) red[t >> 5] = mx;
    __syncthreads();
    if (t < 32) {
        float m2 = (t < 8) ? red[t] : -1e30f;
        for (int o = 4; o > 0; o >>= 1) m2 = fmaxf(m2, __shfl_xor_sync(~0u, m2, o));
        if (t == 0) red[0] = m2;
    }
    __syncthreads();
    mx = red[0];
    __syncthreads();
    float s = 0.f;
#pragma unroll
    for (int i = 0; i < VPT; i++) { v[i] = __expf(v[i] - mx); s += v[i]; }
    for (int o = 16; o > 0; o >>= 1) s += __shfl_xor_sync(~0u, s, o);
    if ((t & 31) == 0) red[t >> 5] = s;
    __syncthreads();
    if (t < 32) {
        float s2 = (t < 8) ? red[t] : 0.f;
        for (int o = 4; o > 0; o >>= 1) s2 += __shfl_xor_sync(~0u, s2, o);
        if (t == 0) red[0] = s2;
    }
    __syncthreads();
    float inv = 1.f / red[0];
#pragma unroll
    for (int i = 0; i < VPT; i++) a[t + i * 256] = v[i] * inv;
}

// ---------------- pinv init helpers ------------------------------------------
__global__ void init_colmax() { g_colmax = 0.f; }

__global__ __launch_bounds__(256) void colmax_kernel()
{
    int bh = blockIdx.x, j = threadIdx.x;
    const float* a = g_a2 + (long)bh * MM * MM;
    float s = 0.f;
    for (int i = 0; i < MM; i++) s += a[i * MM + j];
    __shared__ float red[32];
    float m = s;
    for (int o = 16; o > 0; o >>= 1) m = fmaxf(m, __shfl_xor_sync(~0u, m, o));
    if ((j & 31) == 0) red[j >> 5] = m;
    __syncthreads();
    if (j < 32) {
        float m2 = (j < 8) ? red[j] : -1e30f;
        for (int o = 4; o > 0; o >>= 1) m2 = fmaxf(m2, __shfl_xor_sync(~0u, m2, o));
        if (j == 0) atomicMax((int*)&g_colmax, __float_as_int(m2));
    }
}

__global__ void zinit()
{
    long i = (long)blockIdx.x * 256 + threadIdx.x;
    int col = i % MM; long r = i / MM;
    int row = r % MM; int bh = r / MM;
    float inv = 1.f / g_colmax;
    g_zA[i] = g_a2[((long)bh * MM + col) * MM + row] * inv;
}

// ---------------- fused reshape + depthwise conv ------------------------------
// att[b,n,h*64+d] = o[b,h,n,d] + sum_j rw[h,j] * v[b,h,n+j-16,d]
__global__ void att_conv(const float* __restrict__ rw)
{
    long i = (long)blockIdx.x * 256 + threadIdx.x;    // BB*NN*HH*16 (float4 granules)
    int dq = i % 16; long r = i / 16;
    int h = r % HH;  long r2 = r / HH;
    int n = r2 % NN; int b = r2 / NN;
    long bhbase = (long)(b * HH + h) * NN;
    const float4* v4 = (const float4*)(g_v + bhbase * DHD);
    float4 a = *(const float4*)(g_o + (bhbase + n) * DHD + dq * 4);
#pragma unroll
    for (int j = 0; j < KC; j++) {
        int tt = n + j - KC / 2;
        if (tt >= 0 && tt < NN) {
            float w = rw[h * KC + j];
            float4 vv = v4[(long)tt * 16 + dq];
            a.x += w * vv.x; a.y += w * vv.y; a.z += w * vv.z; a.w += w * vv.w;
        }
    }
    *(float4*)(g_qkv + ((long)(b * NN + n)) * DD + h * DHD + dq * 4) = a;
}

// ---------------- y = x + proj + b_out ----------------------------------------
__global__ void final_add(const float* __restrict__ x, const float* __restrict__ bout,
                          float* __restrict__ y)
{
    long i = (long)blockIdx.x * 256 + threadIdx.x;
    y[i] = x[i] + g_xn[i] + bout[i % DD];
}

// ---------------- host orchestration ------------------------------------------
extern "C" void kernel_launch(void* const* d_in, const int* in_sizes, int n_in,
                              void* d_out, int out_size)
{
    const float* x      = (const float*)d_in[0];
    const float* norm_w = (const float*)d_in[1];
    const float* norm_b = (const float*)d_in[2];
    const float* w_qkv  = (const float*)d_in[3];
    const float* w_out  = (const float*)d_in[4];
    const float* b_out  = (const float*)d_in[5];
    const float* res_w  = (const float*)d_in[6];
    float* y = (float*)d_out;

    float *p_xn, *p_qkv, *p_q, *p_k, *p_v, *p_o, *p_ql, *p_kl;
    float *p_a1, *p_a3, *p_a2, *p_zA, *p_zB, *p_xz, *p_t1, *p_t2, *p_a3v, *p_W;
    cudaGetSymbolAddress((void**)&p_xn,  g_xn);
    cudaGetSymbolAddress((void**)&p_qkv, g_qkv);
    cudaGetSymbolAddress((void**)&p_q,   g_q);
    cudaGetSymbolAddress((void**)&p_k,   g_k);
    cudaGetSymbolAddress((void**)&p_v,   g_v);
    cudaGetSymbolAddress((void**)&p_o,   g_o);
    cudaGetSymbolAddress((void**)&p_ql,  g_ql);
    cudaGetSymbolAddress((void**)&p_kl,  g_kl);
    cudaGetSymbolAddress((void**)&p_a1,  g_a1);
    cudaGetSymbolAddress((void**)&p_a3,  g_a3);
    cudaGetSymbolAddress((void**)&p_a2,  g_a2);
    cudaGetSymbolAddress((void**)&p_zA,  g_zA);
    cudaGetSymbolAddress((void**)&p_zB,  g_zB);
    cudaGetSymbolAddress((void**)&p_xz,  g_xz);
    cudaGetSymbolAddress((void**)&p_t1,  g_t1);
    cudaGetSymbolAddress((void**)&p_t2,  g_t2);
    cudaGetSymbolAddress((void**)&p_a3v, g_a3v);
    cudaGetSymbolAddress((void**)&p_W,   g_W);

    const long MM2 = (long)MM * MM;
    float* nul = nullptr;

    // 1. LayerNorm
    ln_kernel<<<BB * NN, 256>>>(x, norm_w, norm_b);
    // 2. qkv GEMM with fused head-split + q scale
    mmagemm2<false, 1><<<dim3((3 * DD) / 128, (BB * NN) / 128, 1), 256>>>(
        p_xn, w_qkv, nul, nul, p_q, p_k, p_v, BB * NN, 3 * DD, DD, 0, 0, 0, 1.f, 0.f);
    // 3. landmarks
    landmarks<<<(BH * MM * DHD) / 256, 256>>>();
    // 4. a2 = softmax(ql @ kl^T)  (fused)
    sim_softmax<<<dim3(MM / 64, 1, BH), 256>>>(
        p_ql, p_kl, p_a2, (long)MM * DHD, (long)MM * DHD, MM2);
    // 5. pinv init
    init_colmax<<<1, 1>>>();
    colmax_kernel<<<BH, 256>>>();
    zinit<<<(BH * MM * MM) / 256, 256>>>();
    // 6. Newton-Schulz, 6 iterations (aIminus fused into epilogues)
    float* zin = p_zA; float* zout = p_zB;
    for (int it = 0; it < NITER; it++) {
        mmagemm2<false, 0><<<dim3(MM / 128, MM / 128, BH), 256>>>(
            p_a2, zin, p_xz, p_t1, nul, nul, nul, MM, MM, MM, MM2, MM2, MM2, 1.f, 7.f);
        mmagemm2<false, 0><<<dim3(MM / 128, MM / 128, BH), 256>>>(
            p_xz, p_t1, nul, p_t2, nul, nul, nul, MM, MM, MM, MM2, MM2, MM2, 1.f, 15.f);
        mmagemm2<false, 0><<<dim3(MM / 128, MM / 128, BH), 256>>>(
            p_xz, p_t2, nul, p_t1, nul, nul, nul, MM, MM, MM, MM2, MM2, MM2, 1.f, 13.f);
        mmagemm2<false, 0><<<dim3(MM / 128, MM / 128, BH), 256>>>(
            zin, p_t1, zout, nul, nul, nul, nul, MM, MM, MM, MM2, MM2, MM2, 0.25f, 0.f);
        float* tmp = zin; zin = zout; zout = tmp;
    }
    // 7. a1 = softmax(q @ kl^T)  (fused)
    sim_softmax<<<dim3(NN / 64, 1, BH), 256>>>(
        p_q, p_kl, p_a1, (long)NN * DHD, (long)MM * DHD, (long)NN * MM);
    // 8. sim3 = ql @ k^T -> softmax -> a3
    mmagemm2<true, 0><<<dim3(NN / 128, MM / 128, BH), 256>>>(
        p_ql, p_k, p_a3, nul, nul, nul, nul, MM, NN, DHD,
        (long)MM * DHD, (long)NN * DHD, (long)MM * NN, 1.f, 0.f);
    softmax_rows<NN><<<BH * MM, 256>>>(p_a3);
    // 9. a3v = a3 @ v
    mmagemm<false><<<dim3(1, MM / 128, BH), 256>>>(
        p_a3, p_v, p_a3v, MM, DHD, NN, (long)MM * NN, (long)NN * DHD, (long)MM * DHD, 1.f);
    // 10. W = z @ a3v
    mmagemm<false><<<dim3(1, MM / 128, BH), 256>>>(
        zin, p_a3v, p_W, MM, DHD, MM, MM2, (long)MM * DHD, (long)MM * DHD, 1.f);
    // 11. out = a1 @ W
    mmagemm<false><<<dim3(1, NN / 128, BH), 256>>>(
        p_a1, p_W, p_o, NN, DHD, MM, (long)NN * MM, (long)MM * DHD, (long)NN * DHD, 1.f);
    // 12. fused reshape + depthwise conv -> att (g_qkv)
    att_conv<<<(BB * NN * HH * 16) / 256, 256>>>(res_w);
    // 13. proj = att @ w_out (into g_xn)
    mmagemm2<false, 0><<<dim3(DD / 128, (BB * NN) / 128, 1), 256>>>(
        p_qkv, w_out, p_xn, nul, nul, nul, nul, BB * NN, DD, DD, 0, 0, 0, 1.f, 0.f);
    // 14. y = x + proj + b_out
    final_add<<<(BB * NN * DD) / 256, 256>>>(x, b_out, y);
}

// round 6
// speedup vs baseline: 2.5193x; 1.0748x over previous
#include <cuda_runtime.h>
#include <cstdint>

#define BB 4
#define NN 4096
#define DD 512
#define HH 8
#define DHD 64
#define MM 256
#define LLm 16
#define NITER 6
#define KC 33
#define BH (BB*HH)
#define SN 64
#define NCH (NN/SN)

// ---------------- scratch ------------------------------------------------------
__device__ float g_xn [BB*NN*DD];
__device__ float g_qkv[BB*NN*3*DD];          // reused as att
__device__ float g_q  [BH*NN*DHD];
__device__ float g_k  [BH*NN*DHD];
__device__ float g_v  [BH*NN*DHD];
__device__ float g_o  [BH*NN*DHD];
__device__ float g_ql [BH*MM*DHD];
__device__ float g_kl [BH*MM*DHD];
__device__ float g_a1 [(long)BH*NN*MM];
__device__ float g_a2 [BH*MM*MM];
__device__ float g_zA [BH*MM*MM];
__device__ float g_zB [BH*MM*MM];
__device__ float g_xz [BH*MM*MM];
__device__ float g_t1 [BH*MM*MM];
__device__ float g_t2 [BH*MM*MM];
__device__ float g_a3v[BH*MM*DHD];
__device__ float g_W  [BH*MM*DHD];
__device__ float g_colmax;

// ---------------- TF32 helpers ------------------------------------------------
__device__ __forceinline__ uint32_t tf32r(float x) {
    uint32_t y;
    asm("cvt.rna.tf32.f32 %0, %1;" : "=r"(y) : "f"(x));
    return y;
}
__device__ __forceinline__ void mma_tf32(float* c, const uint32_t* a, const uint32_t* b) {
    asm volatile(
        "mma.sync.aligned.m16n8k8.row.col.f32.tf32.tf32.f32 "
        "{%0,%1,%2,%3}, {%4,%5,%6,%7}, {%8,%9}, {%0,%1,%2,%3};"
        : "+f"(c[0]), "+f"(c[1]), "+f"(c[2]), "+f"(c[3])
        : "r"(a[0]), "r"(a[1]), "r"(a[2]), "r"(a[3]), "r"(b[0]), "r"(b[1]));
}

// =============================================================================
// mmagemm2: 128x128x32 TF32 GEMM. 256 threads, 8 warps (4m x 2n), warp 32x64.
// MODE 0: Craw = alpha*acc (if non-null); Ct = dg*I - alpha*acc (if non-null)
// MODE 1: qkv split epilogue -> qp/kp/vp in [B,H,N,D], q scaled 0.125
// MODE 2: y(Craw) = acc + x(qp) + bout(kp)   (final residual fused)
// =============================================================================
template<bool TB, int MODE>
__global__ __launch_bounds__(256) void mmagemm2(
    const float* __restrict__ Ag, const float* __restrict__ Bg,
    float* __restrict__ Craw, float* __restrict__ Ct,
    const float* __restrict__ qp, const float* __restrict__ kp, float* __restrict__ vp,
    int Md, int Nd, int Kd, long sA, long sB, long sC,
    float alpha, float dg)
{
    __shared__ uint32_t As[128 * 32];   // idx = m*32 + (k ^ ((m&7)<<2))
    __shared__ uint32_t Bs[32 * 128];   // idx = k*128 + (n ^ ((k&7)<<3))

    const float* A = Ag + (long)blockIdx.z * sA;
    const float* B = Bg + (long)blockIdx.z * sB;
    const int m0 = blockIdx.y * 128;
    const int n0 = blockIdx.x * 128;
    const int tid = threadIdx.x;
    const int wid = tid >> 5, lane = tid & 31;
    const int warpm = wid & 3, warpn = wid >> 2;
    const int lg = lane >> 2, lt = lane & 3;

    float acc[2][8][4];
#pragma unroll
    for (int mt = 0; mt < 2; mt++)
#pragma unroll
        for (int nt = 0; nt < 8; nt++)
#pragma unroll
            for (int i = 0; i < 4; i++) acc[mt][nt][i] = 0.f;

    const int nk = Kd >> 5;

    {
#pragma unroll
        for (int j = 0; j < 4; j++) {
            int e = tid + j * 256;
            int row = e >> 3, c4 = (e & 7) << 2;
            float4 v = *(const float4*)(A + (long)(m0 + row) * Kd + c4);
            uint4 w = make_uint4(tf32r(v.x), tf32r(v.y), tf32r(v.z), tf32r(v.w));
            *(uint4*)(&As[row * 32 + (c4 ^ ((row & 7) << 2))]) = w;
        }
        if (!TB) {
#pragma unroll
            for (int j = 0; j < 4; j++) {
                int e = tid + j * 256;
                int row = e >> 5, c4 = (e & 31) << 2;
                float4 v = *(const float4*)(B + (long)row * Nd + n0 + c4);
                uint4 w = make_uint4(tf32r(v.x), tf32r(v.y), tf32r(v.z), tf32r(v.w));
                *(uint4*)(&Bs[row * 128 + (c4 ^ ((row & 7) << 3))]) = w;
            }
        } else {
#pragma unroll
            for (int j = 0; j < 4; j++) {
                int e = tid + j * 256;
                int n = e >> 3, c4 = (e & 7) << 2;
                float4 v = *(const float4*)(B + (long)(n0 + n) * Kd + c4);
                Bs[(c4 + 0) * 128 + (n ^ (((c4 + 0) & 7) << 3))] = tf32r(v.x);
                Bs[(c4 + 1) * 128 + (n ^ (((c4 + 1) & 7) << 3))] = tf32r(v.y);
                Bs[(c4 + 2) * 128 + (n ^ (((c4 + 2) & 7) << 3))] = tf32r(v.z);
                Bs[(c4 + 3) * 128 + (n ^ (((c4 + 3) & 7) << 3))] = tf32r(v.w);
            }
        }
    }
    __syncthreads();

    for (int kt = 0; kt < nk; kt++) {
        float4 pa[4], pb[4];
        const bool more = (kt + 1 < nk);
        if (more) {
            const int k0 = (kt + 1) << 5;
#pragma unroll
            for (int j = 0; j < 4; j++) {
                int e = tid + j * 256;
                int row = e >> 3, c4 = (e & 7) << 2;
                pa[j] = *(const float4*)(A + (long)(m0 + row) * Kd + k0 + c4);
            }
            if (!TB) {
#pragma unroll
                for (int j = 0; j < 4; j++) {
                    int e = tid + j * 256;
                    int row = e >> 5, c4 = (e & 31) << 2;
                    pb[j] = *(const float4*)(B + (long)(k0 + row) * Nd + n0 + c4);
                }
            } else {
#pragma unroll
                for (int j = 0; j < 4; j++) {
                    int e = tid + j * 256;
                    int n = e >> 3, c4 = (e & 7) << 2;
                    pb[j] = *(const float4*)(B + (long)(n0 + n) * Kd + k0 + c4);
                }
            }
        }

#pragma unroll
        for (int kk = 0; kk < 32; kk += 8) {
            uint32_t af[2][4], bf[8][2];
#pragma unroll
            for (int mt = 0; mt < 2; mt++) {
                int r = warpm * 32 + mt * 16 + lg;
                int k = kk + lt;
                af[mt][0] = As[r * 32 + (k ^ ((r & 7) << 2))];
                af[mt][1] = As[(r + 8) * 32 + (k ^ (((r + 8) & 7) << 2))];
                af[mt][2] = As[r * 32 + ((k + 4) ^ ((r & 7) << 2))];
                af[mt][3] = As[(r + 8) * 32 + ((k + 4) ^ (((r + 8) & 7) << 2))];
            }
#pragma unroll
            for (int nt = 0; nt < 8; nt++) {
                int c = warpn * 64 + nt * 8 + lg;
                int k = kk + lt;
                bf[nt][0] = Bs[k * 128 + (c ^ ((k & 7) << 3))];
                bf[nt][1] = Bs[(k + 4) * 128 + (c ^ (((k + 4) & 7) << 3))];
            }
#pragma unroll
            for (int mt = 0; mt < 2; mt++)
#pragma unroll
                for (int nt = 0; nt < 8; nt++)
                    mma_tf32(acc[mt][nt], af[mt], bf[nt]);
        }
        __syncthreads();

        if (more) {
#pragma unroll
            for (int j = 0; j < 4; j++) {
                int e = tid + j * 256;
                int row = e >> 3, c4 = (e & 7) << 2;
                uint4 w = make_uint4(tf32r(pa[j].x), tf32r(pa[j].y), tf32r(pa[j].z), tf32r(pa[j].w));
                *(uint4*)(&As[row * 32 + (c4 ^ ((row & 7) << 2))]) = w;
            }
            if (!TB) {
#pragma unroll
                for (int j = 0; j < 4; j++) {
                    int e = tid + j * 256;
                    int row = e >> 5, c4 = (e & 31) << 2;
                    uint4 w = make_uint4(tf32r(pb[j].x), tf32r(pb[j].y), tf32r(pb[j].z), tf32r(pb[j].w));
                    *(uint4*)(&Bs[row * 128 + (c4 ^ ((row & 7) << 3))]) = w;
                }
            } else {
#pragma unroll
                for (int j = 0; j < 4; j++) {
                    int e = tid + j * 256;
                    int n = e >> 3, c4 = (e & 7) << 2;
                    Bs[(c4 + 0) * 128 + (n ^ (((c4 + 0) & 7) << 3))] = tf32r(pb[j].x);
                    Bs[(c4 + 1) * 128 + (n ^ (((c4 + 1) & 7) << 3))] = tf32r(pb[j].y);
                    Bs[(c4 + 2) * 128 + (n ^ (((c4 + 2) & 7) << 3))] = tf32r(pb[j].z);
                    Bs[(c4 + 3) * 128 + (n ^ (((c4 + 3) & 7) << 3))] = tf32r(pb[j].w);
                }
            }
            __syncthreads();
        }
    }

    if (MODE == 0) {
        float* CrawB = Craw ? Craw + (long)blockIdx.z * sC : nullptr;
        float* CtB   = Ct   ? Ct   + (long)blockIdx.z * sC : nullptr;
#pragma unroll
        for (int mt = 0; mt < 2; mt++) {
#pragma unroll
            for (int nt = 0; nt < 8; nt++) {
                int r = m0 + warpm * 32 + mt * 16 + lg;
                int c = n0 + warpn * 64 + nt * 8 + 2 * lt;
                float v00 = acc[mt][nt][0] * alpha;
                float v01 = acc[mt][nt][1] * alpha;
                float v10 = acc[mt][nt][2] * alpha;
                float v11 = acc[mt][nt][3] * alpha;
                if (CrawB) {
                    *(float2*)(CrawB + (long)r * Nd + c)       = make_float2(v00, v01);
                    *(float2*)(CrawB + (long)(r + 8) * Nd + c) = make_float2(v10, v11);
                }
                if (CtB) {
                    float t00 = ((r == c)         ? dg : 0.f) - v00;
                    float t01 = ((r == c + 1)     ? dg : 0.f) - v01;
                    float t10 = ((r + 8 == c)     ? dg : 0.f) - v10;
                    float t11 = ((r + 8 == c + 1) ? dg : 0.f) - v11;
                    *(float2*)(CtB + (long)r * Nd + c)       = make_float2(t00, t01);
                    *(float2*)(CtB + (long)(r + 8) * Nd + c) = make_float2(t10, t11);
                }
            }
        }
    } else if (MODE == 1) {
#pragma unroll
        for (int mt = 0; mt < 2; mt++) {
#pragma unroll
            for (int nt = 0; nt < 8; nt++) {
                int c = n0 + warpn * 64 + nt * 8 + 2 * lt;
                int which = c >> 9, cc = c & 511;
                int h = cc >> 6, d = cc & 63;
                float* dstb = (which == 0) ? (float*)qp : (which == 1) ? (float*)kp : vp;
                float sc = (which == 0) ? 0.125f : 1.f;
#pragma unroll
                for (int half = 0; half < 2; half++) {
                    int m = m0 + warpm * 32 + mt * 16 + half * 8 + lg;
                    int b = m >> 12, n = m & 4095;
                    long dst = (((long)(b * HH + h) * NN + n)) * DHD + d;
                    *(float2*)(dstb + dst) = make_float2(acc[mt][nt][half*2] * sc,
                                                         acc[mt][nt][half*2+1] * sc);
                }
            }
        }
    } else {
        // MODE 2: y = acc + x + bout
#pragma unroll
        for (int mt = 0; mt < 2; mt++) {
#pragma unroll
            for (int nt = 0; nt < 8; nt++) {
                int r = m0 + warpm * 32 + mt * 16 + lg;
                int c = n0 + warpn * 64 + nt * 8 + 2 * lt;
                float b0 = kp[c], b1 = kp[c + 1];
                float2 x0 = *(const float2*)(qp + (long)r * Nd + c);
                float2 x1 = *(const float2*)(qp + (long)(r + 8) * Nd + c);
                *(float2*)(Craw + (long)r * Nd + c) =
                    make_float2(acc[mt][nt][0] + x0.x + b0, acc[mt][nt][1] + x0.y + b1);
                *(float2*)(Craw + (long)(r + 8) * Nd + c) =
                    make_float2(acc[mt][nt][2] + x1.x + b0, acc[mt][nt][3] + x1.y + b1);
            }
        }
    }
}

// =============================================================================
// BN=64 GEMM for W and out. Double-buffered.
// =============================================================================
template<bool TB>
__global__ __launch_bounds__(256) void mmagemm(
    const float* __restrict__ Ag, const float* __restrict__ Bg,
    float* __restrict__ Craw,
    int Md, int Nd, int Kd, long sA, long sB, long sC, float alpha)
{
    __shared__ uint32_t As[2][128 * 32];
    __shared__ uint32_t Bs[2][32 * 64];

    const float* A = Ag + (long)blockIdx.z * sA;
    const float* B = Bg + (long)blockIdx.z * sB;
    const int m0 = blockIdx.y * 128;
    const int n0 = blockIdx.x * 64;
    const int tid = threadIdx.x;
    const int wid = tid >> 5, lane = tid & 31;
    const int warpm = wid & 3, warpn = wid >> 2;
    const int lg = lane >> 2, lt = lane & 3;

    float acc[2][4][4];
#pragma unroll
    for (int mt = 0; mt < 2; mt++)
#pragma unroll
        for (int nt = 0; nt < 4; nt++)
#pragma unroll
            for (int i = 0; i < 4; i++) acc[mt][nt][i] = 0.f;

    const int nk = Kd >> 5;

    {
#pragma unroll
        for (int j = 0; j < 4; j++) {
            int e = tid + j * 256;
            int row = e >> 3, c4 = (e & 7) << 2;
            float4 v = *(const float4*)(A + (long)(m0 + row) * Kd + c4);
            uint4 w = make_uint4(tf32r(v.x), tf32r(v.y), tf32r(v.z), tf32r(v.w));
            *(uint4*)(&As[0][row * 32 + (c4 ^ ((row & 7) << 2))]) = w;
        }
        if (!TB) {
#pragma unroll
            for (int j = 0; j < 2; j++) {
                int e = tid + j * 256;
                int row = e >> 4, c4 = (e & 15) << 2;
                float4 v = *(const float4*)(B + (long)row * Nd + n0 + c4);
                uint4 w = make_uint4(tf32r(v.x), tf32r(v.y), tf32r(v.z), tf32r(v.w));
                *(uint4*)(&Bs[0][row * 64 + (c4 ^ ((row & 7) << 3))]) = w;
            }
        } else {
#pragma unroll
            for (int j = 0; j < 2; j++) {
                int e = tid + j * 256;
                int n = e >> 3, c4 = (e & 7) << 2;
                float4 v = *(const float4*)(B + (long)(n0 + n) * Kd + c4);
                Bs[0][(c4 + 0) * 64 + (n ^ (((c4 + 0) & 7) << 3))] = tf32r(v.x);
                Bs[0][(c4 + 1) * 64 + (n ^ (((c4 + 1) & 7) << 3))] = tf32r(v.y);
                Bs[0][(c4 + 2) * 64 + (n ^ (((c4 + 2) & 7) << 3))] = tf32r(v.z);
                Bs[0][(c4 + 3) * 64 + (n ^ (((c4 + 3) & 7) << 3))] = tf32r(v.w);
            }
        }
    }
    __syncthreads();

    for (int kt = 0; kt < nk; kt++) {
        const int st = kt & 1;
        float4 pa[4], pb[2];
        const bool more = (kt + 1 < nk);
        if (more) {
            const int k0 = (kt + 1) << 5;
#pragma unroll
            for (int j = 0; j < 4; j++) {
                int e = tid + j * 256;
                int row = e >> 3, c4 = (e & 7) << 2;
                pa[j] = *(const float4*)(A + (long)(m0 + row) * Kd + k0 + c4);
            }
            if (!TB) {
#pragma unroll
                for (int j = 0; j < 2; j++) {
                    int e = tid + j * 256;
                    int row = e >> 4, c4 = (e & 15) << 2;
                    pb[j] = *(const float4*)(B + (long)(k0 + row) * Nd + n0 + c4);
                }
            } else {
#pragma unroll
                for (int j = 0; j < 2; j++) {
                    int e = tid + j * 256;
                    int n = e >> 3, c4 = (e & 7) << 2;
                    pb[j] = *(const float4*)(B + (long)(n0 + n) * Kd + k0 + c4);
                }
            }
        }

#pragma unroll
        for (int kk = 0; kk < 32; kk += 8) {
            uint32_t af[2][4], bf[4][2];
#pragma unroll
            for (int mt = 0; mt < 2; mt++) {
                int r = warpm * 32 + mt * 16 + lg;
                int k = kk + lt;
                af[mt][0] = As[st][r * 32 + (k ^ ((r & 7) << 2))];
                af[mt][1] = As[st][(r + 8) * 32 + (k ^ (((r + 8) & 7) << 2))];
                af[mt][2] = As[st][r * 32 + ((k + 4) ^ ((r & 7) << 2))];
                af[mt][3] = As[st][(r + 8) * 32 + ((k + 4) ^ (((r + 8) & 7) << 2))];
            }
#pragma unroll
            for (int nt = 0; nt < 4; nt++) {
                int c = warpn * 32 + nt * 8 + lg;
                int k = kk + lt;
                bf[nt][0] = Bs[st][k * 64 + (c ^ ((k & 7) << 3))];
                bf[nt][1] = Bs[st][(k + 4) * 64 + (c ^ (((k + 4) & 7) << 3))];
            }
#pragma unroll
            for (int mt = 0; mt < 2; mt++)
#pragma unroll
                for (int nt = 0; nt < 4; nt++)
                    mma_tf32(acc[mt][nt], af[mt], bf[nt]);
        }

        if (more) {
            const int ns = st ^ 1;
#pragma unroll
            for (int j = 0; j < 4; j++) {
                int e = tid + j * 256;
                int row = e >> 3, c4 = (e & 7) << 2;
                uint4 w = make_uint4(tf32r(pa[j].x), tf32r(pa[j].y), tf32r(pa[j].z), tf32r(pa[j].w));
                *(uint4*)(&As[ns][row * 32 + (c4 ^ ((row & 7) << 2))]) = w;
            }
            if (!TB) {
#pragma unroll
                for (int j = 0; j < 2; j++) {
                    int e = tid + j * 256;
                    int row = e >> 4, c4 = (e & 15) << 2;
                    uint4 w = make_uint4(tf32r(pb[j].x), tf32r(pb[j].y), tf32r(pb[j].z), tf32r(pb[j].w));
                    *(uint4*)(&Bs[ns][row * 64 + (c4 ^ ((row & 7) << 3))]) = w;
                }
            } else {
#pragma unroll
                for (int j = 0; j < 2; j++) {
                    int e = tid + j * 256;
                    int n = e >> 3, c4 = (e & 7) << 2;
                    Bs[ns][(c4 + 0) * 64 + (n ^ (((c4 + 0) & 7) << 3))] = tf32r(pb[j].x);
                    Bs[ns][(c4 + 1) * 64 + (n ^ (((c4 + 1) & 7) << 3))] = tf32r(pb[j].y);
                    Bs[ns][(c4 + 2) * 64 + (n ^ (((c4 + 2) & 7) << 3))] = tf32r(pb[j].z);
                    Bs[ns][(c4 + 3) * 64 + (n ^ (((c4 + 3) & 7) << 3))] = tf32r(pb[j].w);
                }
            }
        }
        __syncthreads();
    }

    float* CrawB = Craw + (long)blockIdx.z * sC;
#pragma unroll
    for (int mt = 0; mt < 2; mt++) {
#pragma unroll
        for (int nt = 0; nt < 4; nt++) {
            int r = m0 + warpm * 32 + mt * 16 + lg;
            int c = n0 + warpn * 32 + nt * 8 + 2 * lt;
            *(float2*)(CrawB + (long)r * Nd + c) =
                make_float2(acc[mt][nt][0] * alpha, acc[mt][nt][1] * alpha);
            *(float2*)(CrawB + (long)(r + 8) * Nd + c) =
                make_float2(acc[mt][nt][2] * alpha, acc[mt][nt][3] * alpha);
        }
    }
}

// =============================================================================
// sim_softmax: Out = softmax_row(A @ B^T), A [Md x 64], B [256 x 64]
// =============================================================================
__global__ __launch_bounds__(256) void sim_softmax(
    const float* __restrict__ Ag, const float* __restrict__ Bg,
    float* __restrict__ Og, long sA, long sB, long sO)
{
    __shared__ uint32_t As[64 * 32];
    __shared__ uint32_t Bs[32 * 256];
    __shared__ float redm[64 * 4];
    __shared__ float reds[64 * 4];

    const float* A = Ag + (long)blockIdx.z * sA;
    const float* B = Bg + (long)blockIdx.z * sB;
    float*       O = Og + (long)blockIdx.z * sO;
    const int m0 = blockIdx.x * 64;
    const int tid = threadIdx.x;
    const int wid = tid >> 5, lane = tid & 31;
    const int warpm = wid & 1, warpn = wid >> 1;
    const int lg = lane >> 2, lt = lane & 3;

    float acc[2][8][4];
#pragma unroll
    for (int mt = 0; mt < 2; mt++)
#pragma unroll
        for (int nt = 0; nt < 8; nt++)
#pragma unroll
            for (int i = 0; i < 4; i++) acc[mt][nt][i] = 0.f;

#pragma unroll
    for (int kt = 0; kt < 2; kt++) {
        const int k0 = kt * 32;
#pragma unroll
        for (int j = 0; j < 2; j++) {
            int e = tid + j * 256;
            int row = e >> 3, c4 = (e & 7) << 2;
            float4 v = *(const float4*)(A + (long)(m0 + row) * DHD + k0 + c4);
            uint4 w = make_uint4(tf32r(v.x), tf32r(v.y), tf32r(v.z), tf32r(v.w));
            *(uint4*)(&As[row * 32 + (c4 ^ ((row & 7) << 2))]) = w;
        }
#pragma unroll
        for (int j = 0; j < 8; j++) {
            int e = tid + j * 256;
            int n = e >> 3, c4 = (e & 7) << 2;
            float4 v = *(const float4*)(B + (long)n * DHD + k0 + c4);
            Bs[(c4 + 0) * 256 + (n ^ (((c4 + 0) & 7) << 3))] = tf32r(v.x);
            Bs[(c4 + 1) * 256 + (n ^ (((c4 + 1) & 7) << 3))] = tf32r(v.y);
            Bs[(c4 + 2) * 256 + (n ^ (((c4 + 2) & 7) << 3))] = tf32r(v.z);
            Bs[(c4 + 3) * 256 + (n ^ (((c4 + 3) & 7) << 3))] = tf32r(v.w);
        }
        __syncthreads();

#pragma unroll
        for (int kk = 0; kk < 32; kk += 8) {
            uint32_t af[2][4], bf[8][2];
#pragma unroll
            for (int mt = 0; mt < 2; mt++) {
                int r = warpm * 32 + mt * 16 + lg;
                int k = kk + lt;
                af[mt][0] = As[r * 32 + (k ^ ((r & 7) << 2))];
                af[mt][1] = As[(r + 8) * 32 + (k ^ (((r + 8) & 7) << 2))];
                af[mt][2] = As[r * 32 + ((k + 4) ^ ((r & 7) << 2))];
                af[mt][3] = As[(r + 8) * 32 + ((k + 4) ^ (((r + 8) & 7) << 2))];
            }
#pragma unroll
            for (int nt = 0; nt < 8; nt++) {
                int c = warpn * 64 + nt * 8 + lg;
                int k = kk + lt;
                bf[nt][0] = Bs[k * 256 + (c ^ ((k & 7) << 3))];
                bf[nt][1] = Bs[(k + 4) * 256 + (c ^ (((k + 4) & 7) << 3))];
            }
#pragma unroll
            for (int mt = 0; mt < 2; mt++)
#pragma unroll
                for (int nt = 0; nt < 8; nt++)
                    mma_tf32(acc[mt][nt], af[mt], bf[nt]);
        }
        __syncthreads();
    }

#pragma unroll
    for (int mt = 0; mt < 2; mt++)
#pragma unroll
        for (int half = 0; half < 2; half++) {
            float mx = -1e30f;
#pragma unroll
            for (int nt = 0; nt < 8; nt++) {
                mx = fmaxf(mx, acc[mt][nt][half * 2]);
                mx = fmaxf(mx, acc[mt][nt][half * 2 + 1]);
            }
            mx = fmaxf(mx, __shfl_xor_sync(~0u, mx, 1));
            mx = fmaxf(mx, __shfl_xor_sync(~0u, mx, 2));
            int rloc = warpm * 32 + mt * 16 + half * 8 + lg;
            if (lt == 0) redm[rloc * 4 + warpn] = mx;
        }
    __syncthreads();
#pragma unroll
    for (int mt = 0; mt < 2; mt++)
#pragma unroll
        for (int half = 0; half < 2; half++) {
            int rloc = warpm * 32 + mt * 16 + half * 8 + lg;
            float m4 = fmaxf(fmaxf(redm[rloc * 4 + 0], redm[rloc * 4 + 1]),
                             fmaxf(redm[rloc * 4 + 2], redm[rloc * 4 + 3]));
            float s = 0.f;
#pragma unroll
            for (int nt = 0; nt < 8; nt++) {
                float e0 = __expf(acc[mt][nt][half * 2]     - m4);
                float e1 = __expf(acc[mt][nt][half * 2 + 1] - m4);
                acc[mt][nt][half * 2]     = e0;
                acc[mt][nt][half * 2 + 1] = e1;
                s += e0 + e1;
            }
            s += __shfl_xor_sync(~0u, s, 1);
            s += __shfl_xor_sync(~0u, s, 2);
            if (lt == 0) reds[rloc * 4 + warpn] = s;
        }
    __syncthreads();
#pragma unroll
    for (int mt = 0; mt < 2; mt++)
#pragma unroll
        for (int half = 0; half < 2; half++) {
            int rloc = warpm * 32 + mt * 16 + half * 8 + lg;
            float tot = reds[rloc * 4 + 0] + reds[rloc * 4 + 1]
                      + reds[rloc * 4 + 2] + reds[rloc * 4 + 3];
            float inv = 1.f / tot;
            int r = m0 + rloc;
#pragma unroll
            for (int nt = 0; nt < 8; nt++) {
                int c = warpn * 64 + nt * 8 + 2 * lt;
                *(float2*)(O + (long)r * MM + c) =
                    make_float2(acc[mt][nt][half * 2] * inv, acc[mt][nt][half * 2 + 1] * inv);
            }
        }
}

// =============================================================================
// a3v_flash: a3v = softmax_row(ql @ k^T) @ v, online softmax over N=4096.
// 256 threads, 8 warps (4 row-groups of 16 x 2 token/d halves of 32).
// Grid: (MM/64, 1, BH). Chunk SN=64 tokens.
// =============================================================================
__global__ __launch_bounds__(256) void a3v_flash()
{
    __shared__ uint32_t Ks[64 * 64];   // [d][tok]; reused as Ps [m][tok]
    __shared__ uint32_t Vs[64 * 64];   // [tok][d]
    __shared__ float redm[64 * 2];
    __shared__ float reds[64 * 2];

    const int bh = blockIdx.z;
    const int m0 = blockIdx.x * 64;
    const float* ql = g_ql + (long)bh * MM * DHD;
    const float* kg = g_k  + (long)bh * NN * DHD;
    const float* vg = g_v  + (long)bh * NN * DHD;

    const int tid = threadIdx.x;
    const int wid = tid >> 5, lane = tid & 31;
    const int warpm = wid & 3, warpn = wid >> 2;
    const int lg = lane >> 2, lt = lane & 3;

    // persistent ql A-fragments (K=64 -> 8 k-steps)
    uint32_t aq[8][4];
    {
        int mr = m0 + warpm * 16;
#pragma unroll
        for (int kk = 0; kk < 8; kk++) {
            aq[kk][0] = tf32r(ql[(long)(mr + lg)     * DHD + kk * 8 + lt]);
            aq[kk][1] = tf32r(ql[(long)(mr + 8 + lg) * DHD + kk * 8 + lt]);
            aq[kk][2] = tf32r(ql[(long)(mr + lg)     * DHD + kk * 8 + lt + 4]);
            aq[kk][3] = tf32r(ql[(long)(mr + 8 + lg) * DHD + kk * 8 + lt + 4]);
        }
    }

    float oacc[4][4];
#pragma unroll
    for (int nt = 0; nt < 4; nt++)
#pragma unroll
        for (int i = 0; i < 4; i++) oacc[nt][i] = 0.f;
    float mprev[2] = {-1e30f, -1e30f};
    float lsum[2]  = {0.f, 0.f};

    // prefetch chunk 0
    float4 kpre[4], vpre[4];
#pragma unroll
    for (int j = 0; j < 4; j++) {
        int e = tid + j * 256;
        int tok = e >> 4, d4 = (e & 15) << 2;
        kpre[j] = *(const float4*)(kg + (long)tok * DHD + d4);
        vpre[j] = *(const float4*)(vg + (long)tok * DHD + d4);
    }

    for (int ch = 0; ch < NCH; ch++) {
        __syncthreads();   // prev Ps/Vs consumed
#pragma unroll
        for (int j = 0; j < 4; j++) {
            int e = tid + j * 256;
            int tok = e >> 4, d4 = (e & 15) << 2;
            Ks[(d4 + 0) * 64 + (tok ^ (((d4 + 0) & 7) << 3))] = tf32r(kpre[j].x);
            Ks[(d4 + 1) * 64 + (tok ^ (((d4 + 1) & 7) << 3))] = tf32r(kpre[j].y);
            Ks[(d4 + 2) * 64 + (tok ^ (((d4 + 2) & 7) << 3))] = tf32r(kpre[j].z);
            Ks[(d4 + 3) * 64 + (tok ^ (((d4 + 3) & 7) << 3))] = tf32r(kpre[j].w);
            uint4 w = make_uint4(tf32r(vpre[j].x), tf32r(vpre[j].y),
                                 tf32r(vpre[j].z), tf32r(vpre[j].w));
            *(uint4*)(&Vs[tok * 64 + (d4 ^ ((tok & 7) << 3))]) = w;
        }
        if (ch + 1 < NCH) {
            const float* kc = kg + (long)(ch + 1) * SN * DHD;
            const float* vc = vg + (long)(ch + 1) * SN * DHD;
#pragma unroll
            for (int j = 0; j < 4; j++) {
                int e = tid + j * 256;
                int tok = e >> 4, d4 = (e & 15) << 2;
                kpre[j] = *(const float4*)(kc + (long)tok * DHD + d4);
                vpre[j] = *(const float4*)(vc + (long)tok * DHD + d4);
            }
        }
        __syncthreads();

        // S = ql @ k_chunk^T : 16 rows x 32 tokens per warp
        float sacc[4][4];
#pragma unroll
        for (int nt = 0; nt < 4; nt++)
#pragma unroll
            for (int i = 0; i < 4; i++) sacc[nt][i] = 0.f;
#pragma unroll
        for (int kk = 0; kk < 8; kk++) {
            uint32_t bf[4][2];
#pragma unroll
            for (int nt = 0; nt < 4; nt++) {
                int c = warpn * 32 + nt * 8 + lg;
                int k = kk * 8 + lt;
                bf[nt][0] = Ks[k * 64 + (c ^ ((k & 7) << 3))];
                bf[nt][1] = Ks[(k + 4) * 64 + (c ^ (((k + 4) & 7) << 3))];
            }
#pragma unroll
            for (int nt = 0; nt < 4; nt++)
                mma_tf32(sacc[nt], aq[kk], bf[nt]);
        }

        // partial row max (this warp's 32 tokens)
#pragma unroll
        for (int half = 0; half < 2; half++) {
            float mx = -1e30f;
#pragma unroll
            for (int nt = 0; nt < 4; nt++) {
                mx = fmaxf(mx, sacc[nt][half * 2]);
                mx = fmaxf(mx, sacc[nt][half * 2 + 1]);
            }
            mx = fmaxf(mx, __shfl_xor_sync(~0u, mx, 1));
            mx = fmaxf(mx, __shfl_xor_sync(~0u, mx, 2));
            if (lt == 0) redm[(warpm * 16 + half * 8 + lg) * 2 + warpn] = mx;
        }
        __syncthreads();

        float scale[2];
#pragma unroll
        for (int half = 0; half < 2; half++) {
            int row = warpm * 16 + half * 8 + lg;
            float mch  = fmaxf(redm[row * 2], redm[row * 2 + 1]);
            float mnew = fmaxf(mprev[half], mch);
            scale[half] = __expf(mprev[half] - mnew);
            mprev[half] = mnew;
            float s = 0.f;
#pragma unroll
            for (int nt = 0; nt < 4; nt++) {
                float e0 = __expf(sacc[nt][half * 2]     - mnew);
                float e1 = __expf(sacc[nt][half * 2 + 1] - mnew);
                sacc[nt][half * 2]     = e0;
                sacc[nt][half * 2 + 1] = e1;
                s += e0 + e1;
            }
            s += __shfl_xor_sync(~0u, s, 1);
            s += __shfl_xor_sync(~0u, s, 2);
            if (lt == 0) reds[row * 2 + warpn] = s;
            // store P into Ps (= Ks region), layout [m][tok]
#pragma unroll
            for (int nt = 0; nt < 4; nt++) {
                int ccol = warpn * 32 + nt * 8 + 2 * lt;
                uint2 pw = make_uint2(tf32r(sacc[nt][half * 2]),
                                      tf32r(sacc[nt][half * 2 + 1]));
                *(uint2*)(&Ks[row * 64 + (ccol ^ ((row & 7) << 3))]) = pw;
            }
        }
        __syncthreads();

#pragma unroll
        for (int half = 0; half < 2; half++) {
            int row = warpm * 16 + half * 8 + lg;
            lsum[half] = lsum[half] * scale[half] + reds[row * 2] + reds[row * 2 + 1];
        }
#pragma unroll
        for (int nt = 0; nt < 4; nt++) {
            oacc[nt][0] *= scale[0]; oacc[nt][1] *= scale[0];
            oacc[nt][2] *= scale[1]; oacc[nt][3] *= scale[1];
        }

        // O += P @ V : rows 16, d-cols 32 per warp, K = 64 tokens
#pragma unroll
        for (int kk = 0; kk < 8; kk++) {
            int mr = warpm * 16 + lg;
            int k = kk * 8 + lt;
            uint32_t af[4];
            af[0] = Ks[mr * 64 + (k ^ ((mr & 7) << 3))];
            af[1] = Ks[(mr + 8) * 64 + (k ^ (((mr + 8) & 7) << 3))];
            af[2] = Ks[mr * 64 + ((k + 4) ^ ((mr & 7) << 3))];
            af[3] = Ks[(mr + 8) * 64 + ((k + 4) ^ (((mr + 8) & 7) << 3))];
            uint32_t bf[4][2];
#pragma unroll
            for (int nt = 0; nt < 4; nt++) {
                int d = warpn * 32 + nt * 8 + lg;
                bf[nt][0] = Vs[k * 64 + (d ^ ((k & 7) << 3))];
                bf[nt][1] = Vs[(k + 4) * 64 + (d ^ (((k + 4) & 7) << 3))];
            }
#pragma unroll
            for (int nt = 0; nt < 4; nt++)
                mma_tf32(oacc[nt], af, bf[nt]);
        }
    }

    float* outb = g_a3v + (long)bh * MM * DHD;
#pragma unroll
    for (int half = 0; half < 2; half++) {
        float inv = 1.f / lsum[half];
        int r = m0 + warpm * 16 + half * 8 + lg;
#pragma unroll
        for (int nt = 0; nt < 4; nt++) {
            int d = warpn * 32 + nt * 8 + 2 * lt;
            *(float2*)(outb + (long)r * DHD + d) =
                make_float2(oacc[nt][half * 2] * inv, oacc[nt][half * 2 + 1] * inv);
        }
    }
}

// ---------------- LayerNorm ----------------------------------------------------
__global__ __launch_bounds__(256) void ln_kernel(
    const float* __restrict__ x, const float* __restrict__ w, const float* __restrict__ b)
{
    long row = blockIdx.x;
    const float* xr = x + row * DD;
    int t = threadIdx.x;
    float v0 = xr[t], v1 = xr[t + 256];
    __shared__ float red[32];

    float s = v0 + v1;
    for (int o = 16; o > 0; o >>= 1) s += __shfl_xor_sync(~0u, s, o);
    if ((t & 31) == 0) red[t >> 5] = s;
    __syncthreads();
    if (t < 32) {
        float ss = (t < 8) ? red[t] : 0.f;
        for (int o = 4; o > 0; o >>= 1) ss += __shfl_xor_sync(~0u, ss, o);
        if (t == 0) red[0] = ss;
    }
    __syncthreads();
    float mu = red[0] * (1.f / DD);
    __syncthreads();

    float d0 = v0 - mu, d1 = v1 - mu;
    float q = d0 * d0 + d1 * d1;
    for (int o = 16; o > 0; o >>= 1) q += __shfl_xor_sync(~0u, q, o);
    if ((t & 31) == 0) red[t >> 5] = q;
    __syncthreads();
    if (t < 32) {
        float ss = (t < 8) ? red[t] : 0.f;
        for (int o = 4; o > 0; o >>= 1) ss += __shfl_xor_sync(~0u, ss, o);
        if (t == 0) red[0] = ss;
    }
    __syncthreads();
    float inv = rsqrtf(red[0] * (1.f / DD) + 1e-5f);
    g_xn[row * DD + t]       = d0 * inv * w[t]       + b[t];
    g_xn[row * DD + t + 256] = d1 * inv * w[t + 256] + b[t + 256];
}

// ---------------- landmarks ----------------------------------------------------
__global__ void landmarks()
{
    long i = (long)blockIdx.x * 256 + threadIdx.x;
    int d = i % DHD; long r = i / DHD;
    int m = r % MM;  int bh = r / MM;
    long base = ((long)bh * NN + m * LLm) * DHD + d;
    float sq = 0.f, sk = 0.f;
#pragma unroll
    for (int u = 0; u < LLm; u++) { sq += g_q[base + u * DHD]; sk += g_k[base + u * DHD]; }
    g_ql[i] = sq * (1.f / LLm);
    g_kl[i] = sk * (1.f / LLm);
}

// ---------------- pinv init ----------------------------------------------------
__global__ void init_colmax() { g_colmax = 0.f; }

__global__ __launch_bounds__(256) void colmax_kernel()
{
    int bh = blockIdx.x, j = threadIdx.x;
    const float* a = g_a2 + (long)bh * MM * MM;
    float s = 0.f;
    for (int i = 0; i < MM; i++) s += a[i * MM + j];
    __shared__ float red[32];
    float m = s;
    for (int o = 16; o > 0; o >>= 1) m = fmaxf(m, __shfl_xor_sync(~0u, m, o));
    if ((j & 31) == 0) red[j >> 5] = m;
    __syncthreads();
    if (j < 32) {
        float m2 = (j < 8) ? red[j] : -1e30f;
        for (int o = 4; o > 0; o >>= 1) m2 = fmaxf(m2, __shfl_xor_sync(~0u, m2, o));
        if (j == 0) atomicMax((int*)&g_colmax, __float_as_int(m2));
    }
}

__global__ void zinit()
{
    long i = (long)blockIdx.x * 256 + threadIdx.x;
    int col = i % MM; long r = i / MM;
    int row = r % MM; int bh = r / MM;
    float inv = 1.f / g_colmax;
    g_zA[i] = g_a2[((long)bh * MM + col) * MM + row] * inv;
}

// ---------------- fused reshape + depthwise conv -------------------------------
__global__ void att_conv(const float* __restrict__ rw)
{
    long i = (long)blockIdx.x * 256 + threadIdx.x;
    int dq = i % 16; long r = i / 16;
    int h = r % HH;  long r2 = r / HH;
    int n = r2 % NN; int b = r2 / NN;
    long bhbase = (long)(b * HH + h) * NN;
    const float4* v4 = (const float4*)(g_v + bhbase * DHD);
    float4 a = *(const float4*)(g_o + (bhbase + n) * DHD + dq * 4);
#pragma unroll
    for (int j = 0; j < KC; j++) {
        int tt = n + j - KC / 2;
        if (tt >= 0 && tt < NN) {
            float w = rw[h * KC + j];
            float4 vv = v4[(long)tt * 16 + dq];
            a.x += w * vv.x; a.y += w * vv.y; a.z += w * vv.z; a.w += w * vv.w;
        }
    }
    *(float4*)(g_qkv + ((long)(b * NN + n)) * DD + h * DHD + dq * 4) = a;
}

// ---------------- host orchestration -------------------------------------------
extern "C" void kernel_launch(void* const* d_in, const int* in_sizes, int n_in,
                              void* d_out, int out_size)
{
    const float* x      = (const float*)d_in[0];
    const float* norm_w = (const float*)d_in[1];
    const float* norm_b = (const float*)d_in[2];
    const float* w_qkv  = (const float*)d_in[3];
    const float* w_out  = (const float*)d_in[4];
    const float* b_out  = (const float*)d_in[5];
    const float* res_w  = (const float*)d_in[6];
    float* y = (float*)d_out;

    float *p_xn, *p_qkv, *p_q, *p_k, *p_v, *p_o, *p_ql, *p_kl;
    float *p_a1, *p_a2, *p_zA, *p_zB, *p_xz, *p_t1, *p_t2, *p_a3v, *p_W;
    cudaGetSymbolAddress((void**)&p_xn,  g_xn);
    cudaGetSymbolAddress((void**)&p_qkv, g_qkv);
    cudaGetSymbolAddress((void**)&p_q,   g_q);
    cudaGetSymbolAddress((void**)&p_k,   g_k);
    cudaGetSymbolAddress((void**)&p_v,   g_v);
    cudaGetSymbolAddress((void**)&p_o,   g_o);
    cudaGetSymbolAddress((void**)&p_ql,  g_ql);
    cudaGetSymbolAddress((void**)&p_kl,  g_kl);
    cudaGetSymbolAddress((void**)&p_a1,  g_a1);
    cudaGetSymbolAddress((void**)&p_a2,  g_a2);
    cudaGetSymbolAddress((void**)&p_zA,  g_zA);
    cudaGetSymbolAddress((void**)&p_zB,  g_zB);
    cudaGetSymbolAddress((void**)&p_xz,  g_xz);
    cudaGetSymbolAddress((void**)&p_t1,  g_t1);
    cudaGetSymbolAddress((void**)&p_t2,  g_t2);
    cudaGetSymbolAddress((void**)&p_a3v, g_a3v);
    cudaGetSymbolAddress((void**)&p_W,   g_W);

    const long MM2 = (long)MM * MM;
    float* nul = nullptr;

    // 1. LayerNorm
    ln_kernel<<<BB * NN, 256>>>(x, norm_w, norm_b);
    // 2. qkv GEMM with fused head-split + q scale
    mmagemm2<false, 1><<<dim3((3 * DD) / 128, (BB * NN) / 128, 1), 256>>>(
        p_xn, w_qkv, nul, nul, p_q, p_k, p_v, BB * NN, 3 * DD, DD, 0, 0, 0, 1.f, 0.f);
    // 3. landmarks
    landmarks<<<(BH * MM * DHD) / 256, 256>>>();
    // 4. a2 = softmax(ql @ kl^T)
    sim_softmax<<<dim3(MM / 64, 1, BH), 256>>>(
        p_ql, p_kl, p_a2, (long)MM * DHD, (long)MM * DHD, MM2);
    // 5. pinv init
    init_colmax<<<1, 1>>>();
    colmax_kernel<<<BH, 256>>>();
    zinit<<<(BH * MM * MM) / 256, 256>>>();
    // 6. Newton-Schulz (aIminus fused)
    float* zin = p_zA; float* zout = p_zB;
    for (int it = 0; it < NITER; it++) {
        mmagemm2<false, 0><<<dim3(MM / 128, MM / 128, BH), 256>>>(
            p_a2, zin, p_xz, p_t1, nul, nul, nul, MM, MM, MM, MM2, MM2, MM2, 1.f, 7.f);
        mmagemm2<false, 0><<<dim3(MM / 128, MM / 128, BH), 256>>>(
            p_xz, p_t1, nul, p_t2, nul, nul, nul, MM, MM, MM, MM2, MM2, MM2, 1.f, 15.f);
        mmagemm2<false, 0><<<dim3(MM / 128, MM / 128, BH), 256>>>(
            p_xz, p_t2, nul, p_t1, nul, nul, nul, MM, MM, MM, MM2, MM2, MM2, 1.f, 13.f);
        mmagemm2<false, 0><<<dim3(MM / 128, MM / 128, BH), 256>>>(
            zin, p_t1, zout, nul, nul, nul, nul, MM, MM, MM, MM2, MM2, MM2, 0.25f, 0.f);
        float* tmp = zin; zin = zout; zout = tmp;
    }
    // 7. a1 = softmax(q @ kl^T)
    sim_softmax<<<dim3(NN / 64, 1, BH), 256>>>(
        p_q, p_kl, p_a1, (long)NN * DHD, (long)MM * DHD, (long)NN * MM);
    // 8. a3v = softmax(ql @ k^T) @ v  (flash, fully fused)
    a3v_flash<<<dim3(MM / 64, 1, BH), 256>>>();
    // 9. W = z @ a3v
    mmagemm<false><<<dim3(1, MM / 128, BH), 256>>>(
        zin, p_a3v, p_W, MM, DHD, MM, MM2, (long)MM * DHD, (long)MM * DHD, 1.f);
    // 10. out = a1 @ W
    mmagemm<false><<<dim3(1, NN / 128, BH), 256>>>(
        p_a1, p_W, p_o, NN, DHD, MM, (long)NN * MM, (long)MM * DHD, (long)NN * DHD, 1.f);
    // 11. fused reshape + depthwise conv -> att
    att_conv<<<(BB * NN * HH * 16) / 256, 256>>>(res_w);
    // 12. proj + residual + bias -> y  (fused)
    mmagemm2<false, 2><<<dim3(DD / 128, (BB * NN) / 128, 1), 256>>>(
        p_qkv, w_out, y, nul, x, b_out, nul, BB * NN, DD, DD, 0, 0, 0, 1.f, 0.f);
}

// round 8
// speedup vs baseline: 2.6500x; 1.0519x over previous
#include <cuda_runtime.h>
#include <cstdint>

#define BB 4
#define NN 4096
#define DD 512
#define HH 8
#define DHD 64
#define MM 256
#define LLm 16
#define NITER 6
#define KC 33
#define BH (BB*HH)
#define SN 64
#define NCH (NN/SN)

// ---------------- scratch ------------------------------------------------------
__device__ float g_xn [BB*NN*DD];
__device__ float g_qkv[BB*NN*3*DD];          // reused as att
__device__ float g_q  [BH*NN*DHD];
__device__ float g_k  [BH*NN*DHD];
__device__ float g_v  [BH*NN*DHD];
__device__ float g_o  [BH*NN*DHD];
__device__ float g_ql [BH*MM*DHD];
__device__ float g_kl [BH*MM*DHD];
__device__ float g_a1 [(long)BH*NN*MM];
__device__ float g_a2 [BH*MM*MM];
__device__ float g_zA [BH*MM*MM];
__device__ float g_zB [BH*MM*MM];
__device__ float g_xz [BH*MM*MM];
__device__ float g_t1 [BH*MM*MM];
__device__ float g_t2 [BH*MM*MM];
__device__ float g_a3v[BH*MM*DHD];
__device__ float g_W  [BH*MM*DHD];
__device__ float g_colmax;

// ---------------- helpers ------------------------------------------------------
__device__ __forceinline__ uint32_t tf32r(float x) {
    uint32_t y;
    asm("cvt.rna.tf32.f32 %0, %1;" : "=r"(y) : "f"(x));
    return y;
}
// same, but input is an fp32 bit-pattern held in a u32 (smem-resident values)
__device__ __forceinline__ uint32_t tf32b(uint32_t x) {
    uint32_t y;
    asm("cvt.rna.tf32.f32 %0, %1;" : "=r"(y) : "f"(__uint_as_float(x)));
    return y;
}
__device__ __forceinline__ void mma_tf32(float* c, const uint32_t* a, const uint32_t* b) {
    asm volatile(
        "mma.sync.aligned.m16n8k8.row.col.f32.tf32.tf32.f32 "
        "{%0,%1,%2,%3}, {%4,%5,%6,%7}, {%8,%9}, {%0,%1,%2,%3};"
        : "+f"(c[0]), "+f"(c[1]), "+f"(c[2]), "+f"(c[3])
        : "r"(a[0]), "r"(a[1]), "r"(a[2]), "r"(a[3]), "r"(b[0]), "r"(b[1]));
}
__device__ __forceinline__ void cpa16(uint32_t dst, const void* src) {
    asm volatile("cp.async.cg.shared.global [%0], [%1], 16;" :: "r"(dst), "l"(src));
}
#define CP_COMMIT() asm volatile("cp.async.commit_group;")

// =============================================================================
// gemm_ca: C = alpha * A @ B (+epilogues). BM=128, BN=64, BK=32.
// cp.async double-buffered (raw fp32 in smem); cvt.rna at fragment load.
// 2 blocks/SM. 8 warps: 4m x 2n, warp tile 32x32.
// MODE 0: Craw = alpha*acc (if non-null); Ct = dg*I - alpha*acc (if non-null)
// MODE 1: qkv split -> qp/kp/vp in [B,H,N,D], q scaled 0.125
// MODE 2: Craw(y) = acc + xp + bp
// =============================================================================
template<int MODE>
__global__ __launch_bounds__(256, 2) void gemm_ca(
    const float* __restrict__ Ag, const float* __restrict__ Bg,
    float* __restrict__ Craw, float* __restrict__ Ct,
    const float* __restrict__ xp, const float* __restrict__ bp,
    float* __restrict__ qp, float* __restrict__ kp, float* __restrict__ vp,
    int Nd, int Kd, long sA, long sB, long sC, float alpha, float dg)
{
    __shared__ uint32_t As[2][128 * 32];   // idx = m*32 + (k ^ ((m&7)<<2))
    __shared__ uint32_t Bs[2][32 * 64];    // idx = k*64 + (n ^ ((k&7)<<3))

    const float* A = Ag + (long)blockIdx.z * sA;
    const float* B = Bg + (long)blockIdx.z * sB;
    const int m0 = blockIdx.y * 128;
    const int n0 = blockIdx.x * 64;
    const int tid = threadIdx.x;
    const int wid = tid >> 5, lane = tid & 31;
    const int warpm = wid & 3, warpn = wid >> 2;
    const int lg = lane >> 2, lt = lane & 3;

    const uint32_t asmb = (uint32_t)__cvta_generic_to_shared(&As[0][0]);
    const uint32_t bsmb = (uint32_t)__cvta_generic_to_shared(&Bs[0][0]);

    const int ar = tid >> 3, ac4 = (tid & 7) << 2;          // + j*32 rows
    const int br = tid >> 4, bc4 = (tid & 15) << 2;         // + j*16 rows

    float acc[2][4][4];
#pragma unroll
    for (int mt = 0; mt < 2; mt++)
#pragma unroll
        for (int nt = 0; nt < 4; nt++)
#pragma unroll
            for (int i = 0; i < 4; i++) acc[mt][nt][i] = 0.f;

    const int nk = Kd >> 5;

#define LOAD_TILE(kt, st) do {                                                  \
    const int k0_ = (kt) << 5;                                                  \
    _Pragma("unroll")                                                           \
    for (int j = 0; j < 4; j++) {                                               \
        int row = ar + j * 32;                                                  \
        uint32_t d = asmb + (uint32_t)(((st) * 4096 + row * 32 +                \
                     (ac4 ^ ((row & 7) << 2))) << 2);                           \
        cpa16(d, A + (long)(m0 + row) * Kd + k0_ + ac4);                        \
    }                                                                           \
    _Pragma("unroll")                                                           \
    for (int j = 0; j < 2; j++) {                                               \
        int row = br + j * 16;                                                  \
        uint32_t d = bsmb + (uint32_t)(((st) * 2048 + row * 64 +                \
                     (bc4 ^ ((row & 7) << 3))) << 2);                           \
        cpa16(d, B + (long)(k0_ + row) * Nd + n0 + bc4);                        \
    }                                                                           \
    CP_COMMIT();                                                                \
} while (0)

    LOAD_TILE(0, 0);

    for (int kt = 0; kt < nk; kt++) {
        const int st = kt & 1;
        if (kt + 1 < nk) {
            LOAD_TILE(kt + 1, st ^ 1);
            asm volatile("cp.async.wait_group 1;");
        } else {
            asm volatile("cp.async.wait_group 0;");
        }
        __syncthreads();

#pragma unroll
        for (int kk = 0; kk < 32; kk += 8) {
            uint32_t af[2][4], bf[4][2];
#pragma unroll
            for (int mt = 0; mt < 2; mt++) {
                int r = warpm * 32 + mt * 16 + lg;
                int k = kk + lt;
                af[mt][0] = tf32b(As[st][r * 32 + (k ^ ((r & 7) << 2))]);
                af[mt][1] = tf32b(As[st][(r + 8) * 32 + (k ^ (((r + 8) & 7) << 2))]);
                af[mt][2] = tf32b(As[st][r * 32 + ((k + 4) ^ ((r & 7) << 2))]);
                af[mt][3] = tf32b(As[st][(r + 8) * 32 + ((k + 4) ^ (((r + 8) & 7) << 2))]);
            }
#pragma unroll
            for (int nt = 0; nt < 4; nt++) {
                int c = warpn * 32 + nt * 8 + lg;
                int k = kk + lt;
                bf[nt][0] = tf32b(Bs[st][k * 64 + (c ^ ((k & 7) << 3))]);
                bf[nt][1] = tf32b(Bs[st][(k + 4) * 64 + (c ^ (((k + 4) & 7) << 3))]);
            }
#pragma unroll
            for (int mt = 0; mt < 2; mt++)
#pragma unroll
                for (int nt = 0; nt < 4; nt++)
                    mma_tf32(acc[mt][nt], af[mt], bf[nt]);
        }
        __syncthreads();
    }
#undef LOAD_TILE

    if (MODE == 0) {
        float* CrawB = Craw ? Craw + (long)blockIdx.z * sC : nullptr;
        float* CtB   = Ct   ? Ct   + (long)blockIdx.z * sC : nullptr;
#pragma unroll
        for (int mt = 0; mt < 2; mt++) {
#pragma unroll
            for (int nt = 0; nt < 4; nt++) {
                int r = m0 + warpm * 32 + mt * 16 + lg;
                int c = n0 + warpn * 32 + nt * 8 + 2 * lt;
                float v00 = acc[mt][nt][0] * alpha;
                float v01 = acc[mt][nt][1] * alpha;
                float v10 = acc[mt][nt][2] * alpha;
                float v11 = acc[mt][nt][3] * alpha;
                if (CrawB) {
                    *(float2*)(CrawB + (long)r * Nd + c)       = make_float2(v00, v01);
                    *(float2*)(CrawB + (long)(r + 8) * Nd + c) = make_float2(v10, v11);
                }
                if (CtB) {
                    float t00 = ((r == c)         ? dg : 0.f) - v00;
                    float t01 = ((r == c + 1)     ? dg : 0.f) - v01;
                    float t10 = ((r + 8 == c)     ? dg : 0.f) - v10;
                    float t11 = ((r + 8 == c + 1) ? dg : 0.f) - v11;
                    *(float2*)(CtB + (long)r * Nd + c)       = make_float2(t00, t01);
                    *(float2*)(CtB + (long)(r + 8) * Nd + c) = make_float2(t10, t11);
                }
            }
        }
    } else if (MODE == 1) {
#pragma unroll
        for (int mt = 0; mt < 2; mt++) {
#pragma unroll
            for (int nt = 0; nt < 4; nt++) {
                int c = n0 + warpn * 32 + nt * 8 + 2 * lt;
                int which = c >> 9, cc = c & 511;
                int h = cc >> 6, d = cc & 63;
                float* dstb = (which == 0) ? qp : (which == 1) ? kp : vp;
                float sc = (which == 0) ? 0.125f : 1.f;
#pragma unroll
                for (int half = 0; half < 2; half++) {
                    int m = m0 + warpm * 32 + mt * 16 + half * 8 + lg;
                    int b = m >> 12, n = m & 4095;
                    long dst = ((long)(b * HH + h) * NN + n) * DHD + d;
                    *(float2*)(dstb + dst) = make_float2(acc[mt][nt][half*2] * sc,
                                                         acc[mt][nt][half*2+1] * sc);
                }
            }
        }
    } else {
#pragma unroll
        for (int mt = 0; mt < 2; mt++) {
#pragma unroll
            for (int nt = 0; nt < 4; nt++) {
                int r = m0 + warpm * 32 + mt * 16 + lg;
                int c = n0 + warpn * 32 + nt * 8 + 2 * lt;
                float b0 = bp[c], b1 = bp[c + 1];
                float2 x0 = *(const float2*)(xp + (long)r * Nd + c);
                float2 x1 = *(const float2*)(xp + (long)(r + 8) * Nd + c);
                *(float2*)(Craw + (long)r * Nd + c) =
                    make_float2(acc[mt][nt][0] + x0.x + b0, acc[mt][nt][1] + x0.y + b1);
                *(float2*)(Craw + (long)(r + 8) * Nd + c) =
                    make_float2(acc[mt][nt][2] + x1.x + b0, acc[mt][nt][3] + x1.y + b1);
            }
        }
    }
}

// =============================================================================
// sim_softmax: Out = softmax_row(A @ B^T), A [Md x 64], B [256 x 64]
// cvt.rna at smem store (round-6 style).
// =============================================================================
__global__ __launch_bounds__(256, 2) void sim_softmax(
    const float* __restrict__ Ag, const float* __restrict__ Bg,
    float* __restrict__ Og, long sA, long sB, long sO)
{
    __shared__ uint32_t As[64 * 32];
    __shared__ uint32_t Bs[32 * 256];
    __shared__ float redm[64 * 4];
    __shared__ float reds[64 * 4];

    const float* A = Ag + (long)blockIdx.z * sA;
    const float* B = Bg + (long)blockIdx.z * sB;
    float*       O = Og + (long)blockIdx.z * sO;
    const int m0 = blockIdx.x * 64;
    const int tid = threadIdx.x;
    const int wid = tid >> 5, lane = tid & 31;
    const int warpm = wid & 1, warpn = wid >> 1;
    const int lg = lane >> 2, lt = lane & 3;

    float acc[2][8][4];
#pragma unroll
    for (int mt = 0; mt < 2; mt++)
#pragma unroll
        for (int nt = 0; nt < 8; nt++)
#pragma unroll
            for (int i = 0; i < 4; i++) acc[mt][nt][i] = 0.f;

#pragma unroll
    for (int kt = 0; kt < 2; kt++) {
        const int k0 = kt * 32;
#pragma unroll
        for (int j = 0; j < 2; j++) {
            int e = tid + j * 256;
            int row = e >> 3, c4 = (e & 7) << 2;
            float4 v = *(const float4*)(A + (long)(m0 + row) * DHD + k0 + c4);
            uint4 w = make_uint4(tf32r(v.x), tf32r(v.y), tf32r(v.z), tf32r(v.w));
            *(uint4*)(&As[row * 32 + (c4 ^ ((row & 7) << 2))]) = w;
        }
#pragma unroll
        for (int j = 0; j < 8; j++) {
            int e = tid + j * 256;
            int n = e >> 3, c4 = (e & 7) << 2;
            float4 v = *(const float4*)(B + (long)n * DHD + k0 + c4);
            Bs[(c4 + 0) * 256 + (n ^ (((c4 + 0) & 7) << 3))] = tf32r(v.x);
            Bs[(c4 + 1) * 256 + (n ^ (((c4 + 1) & 7) << 3))] = tf32r(v.y);
            Bs[(c4 + 2) * 256 + (n ^ (((c4 + 2) & 7) << 3))] = tf32r(v.z);
            Bs[(c4 + 3) * 256 + (n ^ (((c4 + 3) & 7) << 3))] = tf32r(v.w);
        }
        __syncthreads();

#pragma unroll
        for (int kk = 0; kk < 32; kk += 8) {
            uint32_t af[2][4], bf[8][2];
#pragma unroll
            for (int mt = 0; mt < 2; mt++) {
                int r = warpm * 32 + mt * 16 + lg;
                int k = kk + lt;
                af[mt][0] = As[r * 32 + (k ^ ((r & 7) << 2))];
                af[mt][1] = As[(r + 8) * 32 + (k ^ (((r + 8) & 7) << 2))];
                af[mt][2] = As[r * 32 + ((k + 4) ^ ((r & 7) << 2))];
                af[mt][3] = As[(r + 8) * 32 + ((k + 4) ^ (((r + 8) & 7) << 2))];
            }
#pragma unroll
            for (int nt = 0; nt < 8; nt++) {
                int c = warpn * 64 + nt * 8 + lg;
                int k = kk + lt;
                bf[nt][0] = Bs[k * 256 + (c ^ ((k & 7) << 3))];
                bf[nt][1] = Bs[(k + 4) * 256 + (c ^ (((k + 4) & 7) << 3))];
            }
#pragma unroll
            for (int mt = 0; mt < 2; mt++)
#pragma unroll
                for (int nt = 0; nt < 8; nt++)
                    mma_tf32(acc[mt][nt], af[mt], bf[nt]);
        }
        __syncthreads();
    }

#pragma unroll
    for (int mt = 0; mt < 2; mt++)
#pragma unroll
        for (int half = 0; half < 2; half++) {
            float mx = -1e30f;
#pragma unroll
            for (int nt = 0; nt < 8; nt++) {
                mx = fmaxf(mx, acc[mt][nt][half * 2]);
                mx = fmaxf(mx, acc[mt][nt][half * 2 + 1]);
            }
            mx = fmaxf(mx, __shfl_xor_sync(~0u, mx, 1));
            mx = fmaxf(mx, __shfl_xor_sync(~0u, mx, 2));
            int rloc = warpm * 32 + mt * 16 + half * 8 + lg;
            if (lt == 0) redm[rloc * 4 + warpn] = mx;
        }
    __syncthreads();
#pragma unroll
    for (int mt = 0; mt < 2; mt++)
#pragma unroll
        for (int half = 0; half < 2; half++) {
            int rloc = warpm * 32 + mt * 16 + half * 8 + lg;
            float m4 = fmaxf(fmaxf(redm[rloc * 4 + 0], redm[rloc * 4 + 1]),
                             fmaxf(redm[rloc * 4 + 2], redm[rloc * 4 + 3]));
            float s = 0.f;
#pragma unroll
            for (int nt = 0; nt < 8; nt++) {
                float e0 = __expf(acc[mt][nt][half * 2]     - m4);
                float e1 = __expf(acc[mt][nt][half * 2 + 1] - m4);
                acc[mt][nt][half * 2]     = e0;
                acc[mt][nt][half * 2 + 1] = e1;
                s += e0 + e1;
            }
            s += __shfl_xor_sync(~0u, s, 1);
            s += __shfl_xor_sync(~0u, s, 2);
            if (lt == 0) reds[rloc * 4 + warpn] = s;
        }
    __syncthreads();
#pragma unroll
    for (int mt = 0; mt < 2; mt++)
#pragma unroll
        for (int half = 0; half < 2; half++) {
            int rloc = warpm * 32 + mt * 16 + half * 8 + lg;
            float tot = reds[rloc * 4 + 0] + reds[rloc * 4 + 1]
                      + reds[rloc * 4 + 2] + reds[rloc * 4 + 3];
            float inv = 1.f / tot;
            int r = m0 + rloc;
#pragma unroll
            for (int nt = 0; nt < 8; nt++) {
                int c = warpn * 64 + nt * 8 + 2 * lt;
                *(float2*)(O + (long)r * MM + c) =
                    make_float2(acc[mt][nt][half * 2] * inv, acc[mt][nt][half * 2 + 1] * inv);
            }
        }
}

// =============================================================================
// a3v_flash: a3v = softmax_row(ql @ k^T) @ v, online softmax over N=4096.
// 32 rows/block, grid 256, 2 blocks/SM. cvt.rna at smem stores + frag init.
// =============================================================================
__global__ __launch_bounds__(256, 2) void a3v_flash()
{
    __shared__ uint32_t Ks[64 * 64];   // K^T [d][tok]; rows 0-31 reused as Ps [m][tok]
    __shared__ uint32_t Vs[64 * 64];   // [tok][d]
    __shared__ float redm[32 * 4];
    __shared__ float reds[32 * 4];

    const int bh = blockIdx.z;
    const int m0 = blockIdx.x * 32;
    const float* ql = g_ql + (long)bh * MM * DHD;
    const float* kg = g_k  + (long)bh * NN * DHD;
    const float* vg = g_v  + (long)bh * NN * DHD;

    const int tid = threadIdx.x;
    const int wid = tid >> 5, lane = tid & 31;
    const int warpm = wid & 1, warpn = wid >> 1;
    const int lg = lane >> 2, lt = lane & 3;

    uint32_t aq[8][4];
    {
        int mr = m0 + warpm * 16;
#pragma unroll
        for (int kk = 0; kk < 8; kk++) {
            aq[kk][0] = tf32r(ql[(long)(mr + lg)     * DHD + kk * 8 + lt]);
            aq[kk][1] = tf32r(ql[(long)(mr + 8 + lg) * DHD + kk * 8 + lt]);
            aq[kk][2] = tf32r(ql[(long)(mr + lg)     * DHD + kk * 8 + lt + 4]);
            aq[kk][3] = tf32r(ql[(long)(mr + 8 + lg) * DHD + kk * 8 + lt + 4]);
        }
    }

    float oacc[2][4];
#pragma unroll
    for (int nt = 0; nt < 2; nt++)
#pragma unroll
        for (int i = 0; i < 4; i++) oacc[nt][i] = 0.f;
    float mprev[2] = {-1e30f, -1e30f};
    float lsum[2]  = {0.f, 0.f};

    float4 kpre[4], vpre[4];
#pragma unroll
    for (int j = 0; j < 4; j++) {
        int e = tid + j * 256;
        int tok = e >> 4, d4 = (e & 15) << 2;
        kpre[j] = *(const float4*)(kg + (long)tok * DHD + d4);
        vpre[j] = *(const float4*)(vg + (long)tok * DHD + d4);
    }

    for (int ch = 0; ch < NCH; ch++) {
        __syncthreads();
#pragma unroll
        for (int j = 0; j < 4; j++) {
            int e = tid + j * 256;
            int tok = e >> 4, d4 = (e & 15) << 2;
            Ks[(d4 + 0) * 64 + (tok ^ (((d4 + 0) & 7) << 3))] = tf32r(kpre[j].x);
            Ks[(d4 + 1) * 64 + (tok ^ (((d4 + 1) & 7) << 3))] = tf32r(kpre[j].y);
            Ks[(d4 + 2) * 64 + (tok ^ (((d4 + 2) & 7) << 3))] = tf32r(kpre[j].z);
            Ks[(d4 + 3) * 64 + (tok ^ (((d4 + 3) & 7) << 3))] = tf32r(kpre[j].w);
            uint4 w = make_uint4(tf32r(vpre[j].x), tf32r(vpre[j].y),
                                 tf32r(vpre[j].z), tf32r(vpre[j].w));
            *(uint4*)(&Vs[tok * 64 + (d4 ^ ((tok & 7) << 3))]) = w;
        }
        if (ch + 1 < NCH) {
            const float* kc = kg + (long)(ch + 1) * SN * DHD;
            const float* vc = vg + (long)(ch + 1) * SN * DHD;
#pragma unroll
            for (int j = 0; j < 4; j++) {
                int e = tid + j * 256;
                int tok = e >> 4, d4 = (e & 15) << 2;
                kpre[j] = *(const float4*)(kc + (long)tok * DHD + d4);
                vpre[j] = *(const float4*)(vc + (long)tok * DHD + d4);
            }
        }
        __syncthreads();

        // S = ql @ K^T : 16 rows x 16 tokens per warp
        float sacc[2][4];
#pragma unroll
        for (int nt = 0; nt < 2; nt++)
#pragma unroll
            for (int i = 0; i < 4; i++) sacc[nt][i] = 0.f;
#pragma unroll
        for (int kk = 0; kk < 8; kk++) {
            uint32_t bf[2][2];
#pragma unroll
            for (int nt = 0; nt < 2; nt++) {
                int c = warpn * 16 + nt * 8 + lg;
                int k = kk * 8 + lt;
                bf[nt][0] = Ks[k * 64 + (c ^ ((k & 7) << 3))];
                bf[nt][1] = Ks[(k + 4) * 64 + (c ^ (((k + 4) & 7) << 3))];
            }
#pragma unroll
            for (int nt = 0; nt < 2; nt++)
                mma_tf32(sacc[nt], aq[kk], bf[nt]);
        }

#pragma unroll
        for (int half = 0; half < 2; half++) {
            float mx = -1e30f;
#pragma unroll
            for (int nt = 0; nt < 2; nt++) {
                mx = fmaxf(mx, sacc[nt][half * 2]);
                mx = fmaxf(mx, sacc[nt][half * 2 + 1]);
            }
            mx = fmaxf(mx, __shfl_xor_sync(~0u, mx, 1));
            mx = fmaxf(mx, __shfl_xor_sync(~0u, mx, 2));
            if (lt == 0) redm[(warpm * 16 + half * 8 + lg) * 4 + warpn] = mx;
        }
        __syncthreads();

        float scale[2];
#pragma unroll
        for (int half = 0; half < 2; half++) {
            int row = warpm * 16 + half * 8 + lg;
            float mch = fmaxf(fmaxf(redm[row * 4 + 0], redm[row * 4 + 1]),
                              fmaxf(redm[row * 4 + 2], redm[row * 4 + 3]));
            float mnew = fmaxf(mprev[half], mch);
            scale[half] = __expf(mprev[half] - mnew);
            mprev[half] = mnew;
            float s = 0.f;
#pragma unroll
            for (int nt = 0; nt < 2; nt++) {
                float e0 = __expf(sacc[nt][half * 2]     - mnew);
                float e1 = __expf(sacc[nt][half * 2 + 1] - mnew);
                sacc[nt][half * 2]     = e0;
                sacc[nt][half * 2 + 1] = e1;
                s += e0 + e1;
            }
            s += __shfl_xor_sync(~0u, s, 1);
            s += __shfl_xor_sync(~0u, s, 2);
            if (lt == 0) reds[row * 4 + warpn] = s;
#pragma unroll
            for (int nt = 0; nt < 2; nt++) {
                int ccol = warpn * 16 + nt * 8 + 2 * lt;
                uint2 pw = make_uint2(tf32r(sacc[nt][half * 2]),
                                      tf32r(sacc[nt][half * 2 + 1]));
                *(uint2*)(&Ks[row * 64 + (ccol ^ ((row & 7) << 3))]) = pw;
            }
        }
        __syncthreads();

#pragma unroll
        for (int half = 0; half < 2; half++) {
            int row = warpm * 16 + half * 8 + lg;
            lsum[half] = lsum[half] * scale[half]
                       + reds[row * 4 + 0] + reds[row * 4 + 1]
                       + reds[row * 4 + 2] + reds[row * 4 + 3];
        }
#pragma unroll
        for (int nt = 0; nt < 2; nt++) {
            oacc[nt][0] *= scale[0]; oacc[nt][1] *= scale[0];
            oacc[nt][2] *= scale[1]; oacc[nt][3] *= scale[1];
        }

        // O += P @ V : 16 rows x 16 d per warp, K = 64 tokens
#pragma unroll
        for (int kk = 0; kk < 8; kk++) {
            int mr = warpm * 16 + lg;
            int k = kk * 8 + lt;
            uint32_t af[4];
            af[0] = Ks[mr * 64 + (k ^ ((mr & 7) << 3))];
            af[1] = Ks[(mr + 8) * 64 + (k ^ (((mr + 8) & 7) << 3))];
            af[2] = Ks[mr * 64 + ((k + 4) ^ ((mr & 7) << 3))];
            af[3] = Ks[(mr + 8) * 64 + ((k + 4) ^ (((mr + 8) & 7) << 3))];
            uint32_t bf[2][2];
#pragma unroll
            for (int nt = 0; nt < 2; nt++) {
                int d = warpn * 16 + nt * 8 + lg;
                bf[nt][0] = Vs[k * 64 + (d ^ ((k & 7) << 3))];
                bf[nt][1] = Vs[(k + 4) * 64 + (d ^ (((k + 4) & 7) << 3))];
            }
#pragma unroll
            for (int nt = 0; nt < 2; nt++)
                mma_tf32(oacc[nt], af, bf[nt]);
        }
    }

    float* outb = g_a3v + (long)bh * MM * DHD;
#pragma unroll
    for (int half = 0; half < 2; half++) {
        float inv = 1.f / lsum[half];
        int r = m0 + warpm * 16 + half * 8 + lg;
#pragma unroll
        for (int nt = 0; nt < 2; nt++) {
            int d = warpn * 16 + nt * 8 + 2 * lt;
            *(float2*)(outb + (long)r * DHD + d) =
                make_float2(oacc[nt][half * 2] * inv, oacc[nt][half * 2 + 1] * inv);
        }
    }
}

// ---------------- LayerNorm ----------------------------------------------------
__global__ __launch_bounds__(256) void ln_kernel(
    const float* __restrict__ x, const float* __restrict__ w, const float* __restrict__ b)
{
    long row = blockIdx.x;
    const float* xr = x + row * DD;
    int t = threadIdx.x;
    float v0 = xr[t], v1 = xr[t + 256];
    __shared__ float red[32];

    float s = v0 + v1;
    for (int o = 16; o > 0; o >>= 1) s += __shfl_xor_sync(~0u, s, o);
    if ((t & 31) == 0) red[t >> 5] = s;
    __syncthreads();
    if (t < 32) {
        float ss = (t < 8) ? red[t] : 0.f;
        for (int o = 4; o > 0; o >>= 1) ss += __shfl_xor_sync(~0u, ss, o);
        if (t == 0) red[0] = ss;
    }
    __syncthreads();
    float mu = red[0] * (1.f / DD);
    __syncthreads();

    float d0 = v0 - mu, d1 = v1 - mu;
    float q = d0 * d0 + d1 * d1;
    for (int o = 16; o > 0; o >>= 1) q += __shfl_xor_sync(~0u, q, o);
    if ((t & 31) == 0) red[t >> 5] = q;
    __syncthreads();
    if (t < 32) {
        float ss = (t < 8) ? red[t] : 0.f;
        for (int o = 4; o > 0; o >>= 1) ss += __shfl_xor_sync(~0u, ss, o);
        if (t == 0) red[0] = ss;
    }
    __syncthreads();
    float inv = rsqrtf(red[0] * (1.f / DD) + 1e-5f);
    g_xn[row * DD + t]       = d0 * inv * w[t]       + b[t];
    g_xn[row * DD + t + 256] = d1 * inv * w[t + 256] + b[t + 256];
}

// ---------------- landmarks ----------------------------------------------------
__global__ void landmarks()
{
    long i = (long)blockIdx.x * 256 + threadIdx.x;
    int d = i % DHD; long r = i / DHD;
    int m = r % MM;  int bh = r / MM;
    long base = ((long)bh * NN + m * LLm) * DHD + d;
    float sq = 0.f, sk = 0.f;
#pragma unroll
    for (int u = 0; u < LLm; u++) { sq += g_q[base + u * DHD]; sk += g_k[base + u * DHD]; }
    g_ql[i] = sq * (1.f / LLm);
    g_kl[i] = sk * (1.f / LLm);
}

// ---------------- pinv init ----------------------------------------------------
__global__ void init_colmax() { g_colmax = 0.f; }

__global__ __launch_bounds__(256) void colmax_kernel()
{
    int bh = blockIdx.x, j = threadIdx.x;
    const float* a = g_a2 + (long)bh * MM * MM;
    float s = 0.f;
    for (int i = 0; i < MM; i++) s += a[i * MM + j];
    __shared__ float red[32];
    float m = s;
    for (int o = 16; o > 0; o >>= 1) m = fmaxf(m, __shfl_xor_sync(~0u, m, o));
    if ((j & 31) == 0) red[j >> 5] = m;
    __syncthreads();
    if (j < 32) {
        float m2 = (j < 8) ? red[j] : -1e30f;
        for (int o = 4; o > 0; o >>= 1) m2 = fmaxf(m2, __shfl_xor_sync(~0u, m2, o));
        if (j == 0) atomicMax((int*)&g_colmax, __float_as_int(m2));
    }
}

__global__ void zinit()
{
    long i = (long)blockIdx.x * 256 + threadIdx.x;
    int col = i % MM; long r = i / MM;
    int row = r % MM; int bh = r / MM;
    float inv = 1.f / g_colmax;
    g_zA[i] = g_a2[((long)bh * MM + col) * MM + row] * inv;
}

// ---------------- fused reshape + depthwise conv -------------------------------
__global__ void att_conv(const float* __restrict__ rw)
{
    long i = (long)blockIdx.x * 256 + threadIdx.x;
    int dq = i % 16; long r = i / 16;
    int h = r % HH;  long r2 = r / HH;
    int n = r2 % NN; int b = r2 / NN;
    long bhbase = (long)(b * HH + h) * NN;
    const float4* v4 = (const float4*)(g_v + bhbase * DHD);
    float4 a = *(const float4*)(g_o + (bhbase + n) * DHD + dq * 4);
#pragma unroll
    for (int j = 0; j < KC; j++) {
        int tt = n + j - KC / 2;
        if (tt >= 0 && tt < NN) {
            float w = rw[h * KC + j];
            float4 vv = v4[(long)tt * 16 + dq];
            a.x += w * vv.x; a.y += w * vv.y; a.z += w * vv.z; a.w += w * vv.w;
        }
    }
    *(float4*)(g_qkv + ((long)(b * NN + n)) * DD + h * DHD + dq * 4) = a;
}

// ---------------- host orchestration -------------------------------------------
extern "C" void kernel_launch(void* const* d_in, const int* in_sizes, int n_in,
                              void* d_out, int out_size)
{
    const float* x      = (const float*)d_in[0];
    const float* norm_w = (const float*)d_in[1];
    const float* norm_b = (const float*)d_in[2];
    const float* w_qkv  = (const float*)d_in[3];
    const float* w_out  = (const float*)d_in[4];
    const float* b_out  = (const float*)d_in[5];
    const float* res_w  = (const float*)d_in[6];
    float* y = (float*)d_out;

    float *p_xn, *p_qkv, *p_q, *p_k, *p_v, *p_o, *p_ql, *p_kl;
    float *p_a1, *p_a2, *p_zA, *p_zB, *p_xz, *p_t1, *p_t2, *p_a3v, *p_W;
    cudaGetSymbolAddress((void**)&p_xn,  g_xn);
    cudaGetSymbolAddress((void**)&p_qkv, g_qkv);
    cudaGetSymbolAddress((void**)&p_q,   g_q);
    cudaGetSymbolAddress((void**)&p_k,   g_k);
    cudaGetSymbolAddress((void**)&p_v,   g_v);
    cudaGetSymbolAddress((void**)&p_o,   g_o);
    cudaGetSymbolAddress((void**)&p_ql,  g_ql);
    cudaGetSymbolAddress((void**)&p_kl,  g_kl);
    cudaGetSymbolAddress((void**)&p_a1,  g_a1);
    cudaGetSymbolAddress((void**)&p_a2,  g_a2);
    cudaGetSymbolAddress((void**)&p_zA,  g_zA);
    cudaGetSymbolAddress((void**)&p_zB,  g_zB);
    cudaGetSymbolAddress((void**)&p_xz,  g_xz);
    cudaGetSymbolAddress((void**)&p_t1,  g_t1);
    cudaGetSymbolAddress((void**)&p_t2,  g_t2);
    cudaGetSymbolAddress((void**)&p_a3v, g_a3v);
    cudaGetSymbolAddress((void**)&p_W,   g_W);

    const long MM2 = (long)MM * MM;
    float* nul = nullptr;
    const float* cnul = nullptr;

    // 1. LayerNorm
    ln_kernel<<<BB * NN, 256>>>(x, norm_w, norm_b);
    // 2. qkv GEMM with fused head-split + q scale
    gemm_ca<1><<<dim3((3 * DD) / 64, (BB * NN) / 128, 1), 256>>>(
        p_xn, w_qkv, nul, nul, cnul, cnul, p_q, p_k, p_v,
        3 * DD, DD, 0, 0, 0, 1.f, 0.f);
    // 3. landmarks
    landmarks<<<(BH * MM * DHD) / 256, 256>>>();
    // 4. a2 = softmax(ql @ kl^T)
    sim_softmax<<<dim3(MM / 64, 1, BH), 256>>>(
        p_ql, p_kl, p_a2, (long)MM * DHD, (long)MM * DHD, MM2);
    // 5. pinv init
    init_colmax<<<1, 1>>>();
    colmax_kernel<<<BH, 256>>>();
    zinit<<<(BH * MM * MM) / 256, 256>>>();
    // 6. Newton-Schulz (aIminus fused)
    float* zin = p_zA; float* zout = p_zB;
    for (int it = 0; it < NITER; it++) {
        gemm_ca<0><<<dim3(MM / 64, MM / 128, BH), 256>>>(
            p_a2, zin, p_xz, p_t1, cnul, cnul, nul, nul, nul,
            MM, MM, MM2, MM2, MM2, 1.f, 7.f);
        gemm_ca<0><<<dim3(MM / 64, MM / 128, BH), 256>>>(
            p_xz, p_t1, nul, p_t2, cnul, cnul, nul, nul, nul,
            MM, MM, MM2, MM2, MM2, 1.f, 15.f);
        gemm_ca<0><<<dim3(MM / 64, MM / 128, BH), 256>>>(
            p_xz, p_t2, nul, p_t1, cnul, cnul, nul, nul, nul,
            MM, MM, MM2, MM2, MM2, 1.f, 13.f);
        gemm_ca<0><<<dim3(MM / 64, MM / 128, BH), 256>>>(
            zin, p_t1, zout, nul, cnul, cnul, nul, nul, nul,
            MM, MM, MM2, MM2, MM2, 0.25f, 0.f);
        float* tmp = zin; zin = zout; zout = tmp;
    }
    // 7. a1 = softmax(q @ kl^T)
    sim_softmax<<<dim3(NN / 64, 1, BH), 256>>>(
        p_q, p_kl, p_a1, (long)NN * DHD, (long)MM * DHD, (long)NN * MM);
    // 8. a3v = softmax(ql @ k^T) @ v  (flash)
    a3v_flash<<<dim3(MM / 32, 1, BH), 256>>>();
    // 9. W = z @ a3v
    gemm_ca<0><<<dim3(1, MM / 128, BH), 256>>>(
        zin, p_a3v, p_W, nul, cnul, cnul, nul, nul, nul,
        DHD, MM, MM2, (long)MM * DHD, (long)MM * DHD, 1.f, 0.f);
    // 10. out = a1 @ W
    gemm_ca<0><<<dim3(1, NN / 128, BH), 256>>>(
        p_a1, p_W, p_o, nul, cnul, cnul, nul, nul, nul,
        DHD, MM, (long)NN * MM, (long)MM * DHD, (long)NN * DHD, 1.f, 0.f);
    // 11. fused reshape + depthwise conv -> att
    att_conv<<<(BB * NN * HH * 16) / 256, 256>>>(res_w);
    // 12. proj + residual + bias -> y
    gemm_ca<2><<<dim3(DD / 64, (BB * NN) / 128, 1), 256>>>(
        p_qkv, w_out, y, nul, x, b_out, nul, nul, nul,
        DD, DD, 0, 0, 0, 1.f, 0.f);
}

// round 9
// speedup vs baseline: 3.7219x; 1.4045x over previous
#include <cuda_runtime.h>
#include <cuda_fp16.h>
#include <cstdint>

#define BB 4
#define NN 4096
#define DD 512
#define HH 8
#define DHD 64
#define MM 256
#define LLm 16
#define NITER 6
#define KC 33
#define BH (BB*HH)
#define SN 64
#define NCH (NN/SN)

// ---------------- scratch ------------------------------------------------------
__device__ float g_xn [BB*NN*DD];
__device__ float g_qkv[BB*NN*3*DD];          // reused as att
__device__ float g_q  [BH*NN*DHD];
__device__ float g_k  [BH*NN*DHD];
__device__ float g_v  [BH*NN*DHD];
__device__ float g_o  [BH*NN*DHD];
__device__ float g_ql [BH*MM*DHD];
__device__ float g_kl [BH*MM*DHD];
__device__ float g_a1 [(long)BH*NN*MM];
__device__ float g_a2 [BH*MM*MM];
__device__ float g_zA [BH*MM*MM];
__device__ float g_zB [BH*MM*MM];
__device__ float g_xz [BH*MM*MM];
__device__ float g_t1 [BH*MM*MM];
__device__ float g_t2 [BH*MM*MM];
__device__ float g_a3v[BH*MM*DHD];
__device__ float g_W  [BH*MM*DHD];
__device__ float g_colmax;

// ---------------- helpers ------------------------------------------------------
__device__ __forceinline__ uint32_t h2pack(float a, float b) {
    __half2 h = __floats2half2_rn(a, b);
    return *reinterpret_cast<uint32_t*>(&h);
}
__device__ __forceinline__ void mma_f16(float* c, const uint32_t* a, const uint32_t* b) {
    asm volatile(
        "mma.sync.aligned.m16n8k16.row.col.f32.f16.f16.f32 "
        "{%0,%1,%2,%3}, {%4,%5,%6,%7}, {%8,%9}, {%0,%1,%2,%3};"
        : "+f"(c[0]), "+f"(c[1]), "+f"(c[2]), "+f"(c[3])
        : "r"(a[0]), "r"(a[1]), "r"(a[2]), "r"(a[3]), "r"(b[0]), "r"(b[1]));
}

// =============================================================================
// gemm_f16: C = alpha * A @ B (+epilogues). BM=128, BN=64, BK=32, fp16 MMA.
// smem half2-packed along k. Register-prefetch double buffer. 2 blocks/SM.
// 8 warps: 4m x 2n, warp tile 32x32. MMA m16n8k16: 16 per K=32 block.
// MODE 0: Craw = alpha*acc (if non-null); Ct = dg*I - alpha*acc (if non-null)
// MODE 1: qkv split -> qp/kp/vp in [B,H,N,D], q scaled 0.125
// MODE 2: Craw(y) = acc + xp + bp
// =============================================================================
template<int MODE>
__global__ __launch_bounds__(256, 2) void gemm_f16(
    const float* __restrict__ Ag, const float* __restrict__ Bg,
    float* __restrict__ Craw, float* __restrict__ Ct,
    const float* __restrict__ xp, const float* __restrict__ bp,
    float* __restrict__ qp, float* __restrict__ kpp, float* __restrict__ vp,
    int Nd, int Kd, long sA, long sB, long sC, float alpha, float dg)
{
    __shared__ uint32_t As2[128 * 16];   // [row][kp ^ ((row&7)<<1)], half2 along k
    __shared__ uint32_t Bs2[16 * 64];    // [kp][n ^ ((kp&3)<<3)],  half2 along k

    const float* A = Ag + (long)blockIdx.z * sA;
    const float* B = Bg + (long)blockIdx.z * sB;
    const int m0 = blockIdx.y * 128;
    const int n0 = blockIdx.x * 64;
    const int tid = threadIdx.x;
    const int wid = tid >> 5, lane = tid & 31;
    const int warpm = wid & 3, warpn = wid >> 2;
    const int lg = lane >> 2, lt = lane & 3;

    const int ar = tid >> 3, ac4 = (tid & 7) << 2;   // A: rows ar + j*32, cols ac4..+3
    const int bkp = tid >> 4, bn4 = (tid & 15) << 2; // B: kpair bkp, cols bn4..+3

    float acc[2][4][4];
#pragma unroll
    for (int mt = 0; mt < 2; mt++)
#pragma unroll
        for (int nt = 0; nt < 4; nt++)
#pragma unroll
            for (int i = 0; i < 4; i++) acc[mt][nt][i] = 0.f;

    const int nk = Kd >> 5;

    // ---- initial tile into smem ----
    {
#pragma unroll
        for (int j = 0; j < 4; j++) {
            int row = ar + j * 32;
            float4 v = *(const float4*)(A + (long)(m0 + row) * Kd + ac4);
            int kp0 = ac4 >> 1, sw = (row & 7) << 1;
            uint2 w = make_uint2(h2pack(v.x, v.y), h2pack(v.z, v.w));
            *(uint2*)&As2[row * 16 + (kp0 ^ sw)] = w;
        }
        {
            float4 v0 = *(const float4*)(B + (long)(2 * bkp) * Nd + n0 + bn4);
            float4 v1 = *(const float4*)(B + (long)(2 * bkp + 1) * Nd + n0 + bn4);
            int swb = (bkp & 3) << 3;
            uint4 w = make_uint4(h2pack(v0.x, v1.x), h2pack(v0.y, v1.y),
                                 h2pack(v0.z, v1.z), h2pack(v0.w, v1.w));
            *(uint4*)&Bs2[bkp * 64 + (bn4 ^ swb)] = w;
        }
    }
    __syncthreads();

    for (int kt = 0; kt < nk; kt++) {
        float4 pa[4], pb0, pb1;
        const bool more = (kt + 1 < nk);
        if (more) {
            const int k0 = (kt + 1) << 5;
#pragma unroll
            for (int j = 0; j < 4; j++) {
                int row = ar + j * 32;
                pa[j] = *(const float4*)(A + (long)(m0 + row) * Kd + k0 + ac4);
            }
            pb0 = *(const float4*)(B + (long)(k0 + 2 * bkp) * Nd + n0 + bn4);
            pb1 = *(const float4*)(B + (long)(k0 + 2 * bkp + 1) * Nd + n0 + bn4);
        }

#pragma unroll
        for (int kk = 0; kk < 2; kk++) {
            const int kp0 = kk * 8;
            uint32_t af[2][4], bf[4][2];
#pragma unroll
            for (int mt = 0; mt < 2; mt++) {
                int r = warpm * 32 + mt * 16 + lg;
                int sw = (r & 7) << 1;
                af[mt][0] = As2[r * 16 + ((kp0 + lt) ^ sw)];
                af[mt][1] = As2[(r + 8) * 16 + ((kp0 + lt) ^ sw)];
                af[mt][2] = As2[r * 16 + ((kp0 + lt + 4) ^ sw)];
                af[mt][3] = As2[(r + 8) * 16 + ((kp0 + lt + 4) ^ sw)];
            }
#pragma unroll
            for (int nt = 0; nt < 4; nt++) {
                int c = warpn * 32 + nt * 8 + lg;
                bf[nt][0] = Bs2[(kp0 + lt) * 64 + (c ^ (lt << 3))];
                bf[nt][1] = Bs2[(kp0 + lt + 4) * 64 + (c ^ (lt << 3))];
            }
#pragma unroll
            for (int mt = 0; mt < 2; mt++)
#pragma unroll
                for (int nt = 0; nt < 4; nt++)
                    mma_f16(acc[mt][nt], af[mt], bf[nt]);
        }
        __syncthreads();

        if (more) {
#pragma unroll
            for (int j = 0; j < 4; j++) {
                int row = ar + j * 32;
                int kp0 = ac4 >> 1, sw = (row & 7) << 1;
                uint2 w = make_uint2(h2pack(pa[j].x, pa[j].y), h2pack(pa[j].z, pa[j].w));
                *(uint2*)&As2[row * 16 + (kp0 ^ sw)] = w;
            }
            {
                int swb = (bkp & 3) << 3;
                uint4 w = make_uint4(h2pack(pb0.x, pb1.x), h2pack(pb0.y, pb1.y),
                                     h2pack(pb0.z, pb1.z), h2pack(pb0.w, pb1.w));
                *(uint4*)&Bs2[bkp * 64 + (bn4 ^ swb)] = w;
            }
            __syncthreads();
        }
    }

    if (MODE == 0) {
        float* CrawB = Craw ? Craw + (long)blockIdx.z * sC : nullptr;
        float* CtB   = Ct   ? Ct   + (long)blockIdx.z * sC : nullptr;
#pragma unroll
        for (int mt = 0; mt < 2; mt++) {
#pragma unroll
            for (int nt = 0; nt < 4; nt++) {
                int r = m0 + warpm * 32 + mt * 16 + lg;
                int c = n0 + warpn * 32 + nt * 8 + 2 * lt;
                float v00 = acc[mt][nt][0] * alpha;
                float v01 = acc[mt][nt][1] * alpha;
                float v10 = acc[mt][nt][2] * alpha;
                float v11 = acc[mt][nt][3] * alpha;
                if (CrawB) {
                    *(float2*)(CrawB + (long)r * Nd + c)       = make_float2(v00, v01);
                    *(float2*)(CrawB + (long)(r + 8) * Nd + c) = make_float2(v10, v11);
                }
                if (CtB) {
                    float t00 = ((r == c)         ? dg : 0.f) - v00;
                    float t01 = ((r == c + 1)     ? dg : 0.f) - v01;
                    float t10 = ((r + 8 == c)     ? dg : 0.f) - v10;
                    float t11 = ((r + 8 == c + 1) ? dg : 0.f) - v11;
                    *(float2*)(CtB + (long)r * Nd + c)       = make_float2(t00, t01);
                    *(float2*)(CtB + (long)(r + 8) * Nd + c) = make_float2(t10, t11);
                }
            }
        }
    } else if (MODE == 1) {
#pragma unroll
        for (int mt = 0; mt < 2; mt++) {
#pragma unroll
            for (int nt = 0; nt < 4; nt++) {
                int c = n0 + warpn * 32 + nt * 8 + 2 * lt;
                int which = c >> 9, cc = c & 511;
                int h = cc >> 6, d = cc & 63;
                float* dstb = (which == 0) ? qp : (which == 1) ? kpp : vp;
                float sc = (which == 0) ? 0.125f : 1.f;
#pragma unroll
                for (int half = 0; half < 2; half++) {
                    int m = m0 + warpm * 32 + mt * 16 + half * 8 + lg;
                    int b = m >> 12, n = m & 4095;
                    long dst = ((long)(b * HH + h) * NN + n) * DHD + d;
                    *(float2*)(dstb + dst) = make_float2(acc[mt][nt][half*2] * sc,
                                                         acc[mt][nt][half*2+1] * sc);
                }
            }
        }
    } else {
#pragma unroll
        for (int mt = 0; mt < 2; mt++) {
#pragma unroll
            for (int nt = 0; nt < 4; nt++) {
                int r = m0 + warpm * 32 + mt * 16 + lg;
                int c = n0 + warpn * 32 + nt * 8 + 2 * lt;
                float b0 = bp[c], b1 = bp[c + 1];
                float2 x0 = *(const float2*)(xp + (long)r * Nd + c);
                float2 x1 = *(const float2*)(xp + (long)(r + 8) * Nd + c);
                *(float2*)(Craw + (long)r * Nd + c) =
                    make_float2(acc[mt][nt][0] + x0.x + b0, acc[mt][nt][1] + x0.y + b1);
                *(float2*)(Craw + (long)(r + 8) * Nd + c) =
                    make_float2(acc[mt][nt][2] + x1.x + b0, acc[mt][nt][3] + x1.y + b1);
            }
        }
    }
}

// =============================================================================
// sim_softmax: Out = softmax_row(A @ B^T), A [Md x 64], B [256 x 64], fp16 MMA.
// =============================================================================
__global__ __launch_bounds__(256, 2) void sim_softmax(
    const float* __restrict__ Ag, const float* __restrict__ Bg,
    float* __restrict__ Og, long sA, long sB, long sO)
{
    __shared__ uint32_t As2[64 * 16];    // [row][kp ^ ((row&7)<<1)]
    __shared__ uint32_t Bs2[16 * 256];   // [kp][n ^ ((kp&3)<<3)]
    __shared__ float redm[64 * 4];
    __shared__ float reds[64 * 4];

    const float* A = Ag + (long)blockIdx.z * sA;
    const float* B = Bg + (long)blockIdx.z * sB;
    float*       O = Og + (long)blockIdx.z * sO;
    const int m0 = blockIdx.x * 64;
    const int tid = threadIdx.x;
    const int wid = tid >> 5, lane = tid & 31;
    const int warpm = wid & 1, warpn = wid >> 1;
    const int lg = lane >> 2, lt = lane & 3;

    float acc[2][8][4];
#pragma unroll
    for (int mt = 0; mt < 2; mt++)
#pragma unroll
        for (int nt = 0; nt < 8; nt++)
#pragma unroll
            for (int i = 0; i < 4; i++) acc[mt][nt][i] = 0.f;

#pragma unroll
    for (int kt = 0; kt < 2; kt++) {
        const int k0 = kt * 32;
#pragma unroll
        for (int j = 0; j < 2; j++) {
            int e = tid + j * 256;
            int row = e >> 3, c4 = (e & 7) << 2;
            float4 v = *(const float4*)(A + (long)(m0 + row) * DHD + k0 + c4);
            int kp0 = c4 >> 1, sw = (row & 7) << 1;
            uint2 w = make_uint2(h2pack(v.x, v.y), h2pack(v.z, v.w));
            *(uint2*)&As2[row * 16 + (kp0 ^ sw)] = w;
        }
#pragma unroll
        for (int j = 0; j < 8; j++) {
            int e = tid + j * 256;
            int n = e >> 3, c4 = (e & 7) << 2;
            float4 v = *(const float4*)(B + (long)n * DHD + k0 + c4);
            int kp0 = c4 >> 1;
            Bs2[kp0 * 256 + (n ^ ((kp0 & 3) << 3))]             = h2pack(v.x, v.y);
            Bs2[(kp0 + 1) * 256 + (n ^ (((kp0 + 1) & 3) << 3))] = h2pack(v.z, v.w);
        }
        __syncthreads();

#pragma unroll
        for (int kk = 0; kk < 2; kk++) {
            const int kp0 = kk * 8;
            uint32_t af[2][4], bf[8][2];
#pragma unroll
            for (int mt = 0; mt < 2; mt++) {
                int r = warpm * 32 + mt * 16 + lg;
                int sw = (r & 7) << 1;
                af[mt][0] = As2[r * 16 + ((kp0 + lt) ^ sw)];
                af[mt][1] = As2[(r + 8) * 16 + ((kp0 + lt) ^ sw)];
                af[mt][2] = As2[r * 16 + ((kp0 + lt + 4) ^ sw)];
                af[mt][3] = As2[(r + 8) * 16 + ((kp0 + lt + 4) ^ sw)];
            }
#pragma unroll
            for (int nt = 0; nt < 8; nt++) {
                int c = warpn * 64 + nt * 8 + lg;
                bf[nt][0] = Bs2[(kp0 + lt) * 256 + (c ^ (lt << 3))];
                bf[nt][1] = Bs2[(kp0 + lt + 4) * 256 + (c ^ (lt << 3))];
            }
#pragma unroll
            for (int mt = 0; mt < 2; mt++)
#pragma unroll
                for (int nt = 0; nt < 8; nt++)
                    mma_f16(acc[mt][nt], af[mt], bf[nt]);
        }
        __syncthreads();
    }

#pragma unroll
    for (int mt = 0; mt < 2; mt++)
#pragma unroll
        for (int half = 0; half < 2; half++) {
            float mx = -1e30f;
#pragma unroll
            for (int nt = 0; nt < 8; nt++) {
                mx = fmaxf(mx, acc[mt][nt][half * 2]);
                mx = fmaxf(mx, acc[mt][nt][half * 2 + 1]);
            }
            mx = fmaxf(mx, __shfl_xor_sync(~0u, mx, 1));
            mx = fmaxf(mx, __shfl_xor_sync(~0u, mx, 2));
            int rloc = warpm * 32 + mt * 16 + half * 8 + lg;
            if (lt == 0) redm[rloc * 4 + warpn] = mx;
        }
    __syncthreads();
#pragma unroll
    for (int mt = 0; mt < 2; mt++)
#pragma unroll
        for (int half = 0; half < 2; half++) {
            int rloc = warpm * 32 + mt * 16 + half * 8 + lg;
            float m4 = fmaxf(fmaxf(redm[rloc * 4 + 0], redm[rloc * 4 + 1]),
                             fmaxf(redm[rloc * 4 + 2], redm[rloc * 4 + 3]));
            float s = 0.f;
#pragma unroll
            for (int nt = 0; nt < 8; nt++) {
                float e0 = __expf(acc[mt][nt][half * 2]     - m4);
                float e1 = __expf(acc[mt][nt][half * 2 + 1] - m4);
                acc[mt][nt][half * 2]     = e0;
                acc[mt][nt][half * 2 + 1] = e1;
                s += e0 + e1;
            }
            s += __shfl_xor_sync(~0u, s, 1);
            s += __shfl_xor_sync(~0u, s, 2);
            if (lt == 0) reds[rloc * 4 + warpn] = s;
        }
    __syncthreads();
#pragma unroll
    for (int mt = 0; mt < 2; mt++)
#pragma unroll
        for (int half = 0; half < 2; half++) {
            int rloc = warpm * 32 + mt * 16 + half * 8 + lg;
            float tot = reds[rloc * 4 + 0] + reds[rloc * 4 + 1]
                      + reds[rloc * 4 + 2] + reds[rloc * 4 + 3];
            float inv = 1.f / tot;
            int r = m0 + rloc;
#pragma unroll
            for (int nt = 0; nt < 8; nt++) {
                int c = warpn * 64 + nt * 8 + 2 * lt;
                *(float2*)(O + (long)r * MM + c) =
                    make_float2(acc[mt][nt][half * 2] * inv, acc[mt][nt][half * 2 + 1] * inv);
            }
        }
}

// =============================================================================
// a3v_flash: a3v = softmax_row(ql @ k^T) @ v, online softmax over N=4096. fp16.
// 32 rows/block, grid (MM/32,1,BH) = 256 blocks, 2 blocks/SM.
// =============================================================================
__global__ __launch_bounds__(256, 2) void a3v_flash()
{
    __shared__ uint32_t Ks2[32 * 64];   // K^T: [kp_d][tok ^ ((kp&3)<<3)]; rows 0-31 reused as Ps [m][kp_tok ^ ((m&7)<<2)]
    __shared__ uint32_t Vs2[32 * 64];   // [kp_tok][d ^ ((kp&3)<<3)]
    __shared__ float redm[32 * 4];
    __shared__ float reds[32 * 4];

    const int bh = blockIdx.z;
    const int m0 = blockIdx.x * 32;
    const float* ql = g_ql + (long)bh * MM * DHD;
    const float* kg = g_k  + (long)bh * NN * DHD;
    const float* vg = g_v  + (long)bh * NN * DHD;

    const int tid = threadIdx.x;
    const int wid = tid >> 5, lane = tid & 31;
    const int warpm = wid & 1, warpn = wid >> 1;
    const int lg = lane >> 2, lt = lane & 3;

    // ql A-fragments: 4 k16 steps over d=64
    uint32_t aq[4][4];
    {
        int mr = m0 + warpm * 16;
#pragma unroll
        for (int s = 0; s < 4; s++) {
            int d0 = s * 16 + 2 * lt;
            aq[s][0] = h2pack(ql[(long)(mr + lg) * DHD + d0],     ql[(long)(mr + lg) * DHD + d0 + 1]);
            aq[s][1] = h2pack(ql[(long)(mr + 8 + lg) * DHD + d0], ql[(long)(mr + 8 + lg) * DHD + d0 + 1]);
            aq[s][2] = h2pack(ql[(long)(mr + lg) * DHD + d0 + 8], ql[(long)(mr + lg) * DHD + d0 + 9]);
            aq[s][3] = h2pack(ql[(long)(mr + 8 + lg) * DHD + d0 + 8], ql[(long)(mr + 8 + lg) * DHD + d0 + 9]);
        }
    }

    float oacc[2][4];
#pragma unroll
    for (int nt = 0; nt < 2; nt++)
#pragma unroll
        for (int i = 0; i < 4; i++) oacc[nt][i] = 0.f;
    float mprev[2] = {-1e30f, -1e30f};
    float lsum[2]  = {0.f, 0.f};

    // prefetch chunk 0
    float4 kpre[4], vpreA[2], vpreB[2];
#pragma unroll
    for (int j = 0; j < 4; j++) {
        int e = tid + j * 256;
        int tok = e >> 4, d4 = (e & 15) << 2;
        kpre[j] = *(const float4*)(kg + (long)tok * DHD + d4);
    }
#pragma unroll
    for (int j = 0; j < 2; j++) {
        int e = tid + j * 256;
        int kpt = e >> 4, d4 = (e & 15) << 2;
        vpreA[j] = *(const float4*)(vg + (long)(2 * kpt) * DHD + d4);
        vpreB[j] = *(const float4*)(vg + (long)(2 * kpt + 1) * DHD + d4);
    }

    for (int ch = 0; ch < NCH; ch++) {
        __syncthreads();
        // store K chunk: Ks2[kp_d][tok]
#pragma unroll
        for (int j = 0; j < 4; j++) {
            int e = tid + j * 256;
            int tok = e >> 4, d4 = (e & 15) << 2;
            int kp0 = d4 >> 1;
            Ks2[kp0 * 64 + (tok ^ ((kp0 & 3) << 3))]             = h2pack(kpre[j].x, kpre[j].y);
            Ks2[(kp0 + 1) * 64 + (tok ^ (((kp0 + 1) & 3) << 3))] = h2pack(kpre[j].z, kpre[j].w);
        }
        // store V chunk: Vs2[kp_tok][d]
#pragma unroll
        for (int j = 0; j < 2; j++) {
            int e = tid + j * 256;
            int kpt = e >> 4, d4 = (e & 15) << 2;
            int swv = (kpt & 3) << 3;
            uint4 w = make_uint4(h2pack(vpreA[j].x, vpreB[j].x), h2pack(vpreA[j].y, vpreB[j].y),
                                 h2pack(vpreA[j].z, vpreB[j].z), h2pack(vpreA[j].w, vpreB[j].w));
            *(uint4*)&Vs2[kpt * 64 + (d4 ^ swv)] = w;
        }
        if (ch + 1 < NCH) {
            const float* kc = kg + (long)(ch + 1) * SN * DHD;
            const float* vc = vg + (long)(ch + 1) * SN * DHD;
#pragma unroll
            for (int j = 0; j < 4; j++) {
                int e = tid + j * 256;
                int tok = e >> 4, d4 = (e & 15) << 2;
                kpre[j] = *(const float4*)(kc + (long)tok * DHD + d4);
            }
#pragma unroll
            for (int j = 0; j < 2; j++) {
                int e = tid + j * 256;
                int kpt = e >> 4, d4 = (e & 15) << 2;
                vpreA[j] = *(const float4*)(vc + (long)(2 * kpt) * DHD + d4);
                vpreB[j] = *(const float4*)(vc + (long)(2 * kpt + 1) * DHD + d4);
            }
        }
        __syncthreads();

        // S = ql @ K^T : 16 rows x 16 tokens per warp, K=64 -> 4 k16 steps
        float sacc[2][4];
#pragma unroll
        for (int nt = 0; nt < 2; nt++)
#pragma unroll
            for (int i = 0; i < 4; i++) sacc[nt][i] = 0.f;
#pragma unroll
        for (int s = 0; s < 4; s++) {
            const int kp0 = s * 8;
            uint32_t bf[2][2];
#pragma unroll
            for (int nt = 0; nt < 2; nt++) {
                int c = warpn * 16 + nt * 8 + lg;
                bf[nt][0] = Ks2[(kp0 + lt) * 64 + (c ^ (lt << 3))];
                bf[nt][1] = Ks2[(kp0 + lt + 4) * 64 + (c ^ (lt << 3))];
            }
#pragma unroll
            for (int nt = 0; nt < 2; nt++)
                mma_f16(sacc[nt], aq[s], bf[nt]);
        }

#pragma unroll
        for (int half = 0; half < 2; half++) {
            float mx = -1e30f;
#pragma unroll
            for (int nt = 0; nt < 2; nt++) {
                mx = fmaxf(mx, sacc[nt][half * 2]);
                mx = fmaxf(mx, sacc[nt][half * 2 + 1]);
            }
            mx = fmaxf(mx, __shfl_xor_sync(~0u, mx, 1));
            mx = fmaxf(mx, __shfl_xor_sync(~0u, mx, 2));
            if (lt == 0) redm[(warpm * 16 + half * 8 + lg) * 4 + warpn] = mx;
        }
        __syncthreads();

        float scale[2];
#pragma unroll
        for (int half = 0; half < 2; half++) {
            int row = warpm * 16 + half * 8 + lg;
            float mch = fmaxf(fmaxf(redm[row * 4 + 0], redm[row * 4 + 1]),
                              fmaxf(redm[row * 4 + 2], redm[row * 4 + 3]));
            float mnew = fmaxf(mprev[half], mch);
            scale[half] = __expf(mprev[half] - mnew);
            mprev[half] = mnew;
            float s = 0.f;
#pragma unroll
            for (int nt = 0; nt < 2; nt++) {
                float e0 = __expf(sacc[nt][half * 2]     - mnew);
                float e1 = __expf(sacc[nt][half * 2 + 1] - mnew);
                sacc[nt][half * 2]     = e0;
                sacc[nt][half * 2 + 1] = e1;
                s += e0 + e1;
            }
            s += __shfl_xor_sync(~0u, s, 1);
            s += __shfl_xor_sync(~0u, s, 2);
            if (lt == 0) reds[row * 4 + warpn] = s;
            // pack P half2 (adjacent token cols) into Ps (= Ks2 rows 0..31)
#pragma unroll
            for (int nt = 0; nt < 2; nt++) {
                int kp = warpn * 8 + nt * 4 + lt;   // token-pair index
                Ks2[row * 32 + (kp ^ ((row & 7) << 2))] =
                    h2pack(sacc[nt][half * 2], sacc[nt][half * 2 + 1]);
            }
        }
        __syncthreads();

#pragma unroll
        for (int half = 0; half < 2; half++) {
            int row = warpm * 16 + half * 8 + lg;
            lsum[half] = lsum[half] * scale[half]
                       + reds[row * 4 + 0] + reds[row * 4 + 1]
                       + reds[row * 4 + 2] + reds[row * 4 + 3];
        }
#pragma unroll
        for (int nt = 0; nt < 2; nt++) {
            oacc[nt][0] *= scale[0]; oacc[nt][1] *= scale[0];
            oacc[nt][2] *= scale[1]; oacc[nt][3] *= scale[1];
        }

        // O += P @ V : 16 rows x 16 d per warp, K=64 tokens -> 4 k16 steps
#pragma unroll
        for (int s = 0; s < 4; s++) {
            const int kp0 = s * 8;
            int mr = warpm * 16 + lg;
            int sw = (mr & 7) << 2;
            uint32_t af[4];
            af[0] = Ks2[mr * 32 + ((kp0 + lt) ^ sw)];
            af[1] = Ks2[(mr + 8) * 32 + ((kp0 + lt) ^ sw)];
            af[2] = Ks2[mr * 32 + ((kp0 + lt + 4) ^ sw)];
            af[3] = Ks2[(mr + 8) * 32 + ((kp0 + lt + 4) ^ sw)];
            uint32_t bf[2][2];
#pragma unroll
            for (int nt = 0; nt < 2; nt++) {
                int d = warpn * 16 + nt * 8 + lg;
                bf[nt][0] = Vs2[(kp0 + lt) * 64 + (d ^ (lt << 3))];
                bf[nt][1] = Vs2[(kp0 + lt + 4) * 64 + (d ^ (lt << 3))];
            }
#pragma unroll
            for (int nt = 0; nt < 2; nt++)
                mma_f16(oacc[nt], af, bf[nt]);
        }
    }

    float* outb = g_a3v + (long)bh * MM * DHD;
#pragma unroll
    for (int half = 0; half < 2; half++) {
        float inv = 1.f / lsum[half];
        int r = m0 + warpm * 16 + half * 8 + lg;
#pragma unroll
        for (int nt = 0; nt < 2; nt++) {
            int d = warpn * 16 + nt * 8 + 2 * lt;
            *(float2*)(outb + (long)r * DHD + d) =
                make_float2(oacc[nt][half * 2] * inv, oacc[nt][half * 2 + 1] * inv);
        }
    }
}

// ---------------- LayerNorm ----------------------------------------------------
__global__ __launch_bounds__(256) void ln_kernel(
    const float* __restrict__ x, const float* __restrict__ w, const float* __restrict__ b)
{
    long row = blockIdx.x;
    const float* xr = x + row * DD;
    int t = threadIdx.x;
    float v0 = xr[t], v1 = xr[t + 256];
    __shared__ float red[32];

    float s = v0 + v1;
    for (int o = 16; o > 0; o >>= 1) s += __shfl_xor_sync(~0u, s, o);
    if ((t & 31) == 0) red[t >> 5] = s;
    __syncthreads();
    if (t < 32) {
        float ss = (t < 8) ? red[t] : 0.f;
        for (int o = 4; o > 0; o >>= 1) ss += __shfl_xor_sync(~0u, ss, o);
        if (t == 0) red[0] = ss;
    }
    __syncthreads();
    float mu = red[0] * (1.f / DD);
    __syncthreads();

    float d0 = v0 - mu, d1 = v1 - mu;
    float q = d0 * d0 + d1 * d1;
    for (int o = 16; o > 0; o >>= 1) q += __shfl_xor_sync(~0u, q, o);
    if ((t & 31) == 0) red[t >> 5] = q;
    __syncthreads();
    if (t < 32) {
        float ss = (t < 8) ? red[t] : 0.f;
        for (int o = 4; o > 0; o >>= 1) ss += __shfl_xor_sync(~0u, ss, o);
        if (t == 0) red[0] = ss;
    }
    __syncthreads();
    float inv = rsqrtf(red[0] * (1.f / DD) + 1e-5f);
    g_xn[row * DD + t]       = d0 * inv * w[t]       + b[t];
    g_xn[row * DD + t + 256] = d1 * inv * w[t + 256] + b[t + 256];
}

// ---------------- landmarks ----------------------------------------------------
__global__ void landmarks()
{
    long i = (long)blockIdx.x * 256 + threadIdx.x;
    int d = i % DHD; long r = i / DHD;
    int m = r % MM;  int bh = r / MM;
    long base = ((long)bh * NN + m * LLm) * DHD + d;
    float sq = 0.f, sk = 0.f;
#pragma unroll
    for (int u = 0; u < LLm; u++) { sq += g_q[base + u * DHD]; sk += g_k[base + u * DHD]; }
    g_ql[i] = sq * (1.f / LLm);
    g_kl[i] = sk * (1.f / LLm);
}

// ---------------- pinv init ----------------------------------------------------
__global__ void init_colmax() { g_colmax = 0.f; }

__global__ __launch_bounds__(256) void colmax_kernel()
{
    int bh = blockIdx.x, j = threadIdx.x;
    const float* a = g_a2 + (long)bh * MM * MM;
    float s = 0.f;
    for (int i = 0; i < MM; i++) s += a[i * MM + j];
    __shared__ float red[32];
    float m = s;
    for (int o = 16; o > 0; o >>= 1) m = fmaxf(m, __shfl_xor_sync(~0u, m, o));
    if ((j & 31) == 0) red[j >> 5] = m;
    __syncthreads();
    if (j < 32) {
        float m2 = (j < 8) ? red[j] : -1e30f;
        for (int o = 4; o > 0; o >>= 1) m2 = fmaxf(m2, __shfl_xor_sync(~0u, m2, o));
        if (j == 0) atomicMax((int*)&g_colmax, __float_as_int(m2));
    }
}

__global__ void zinit()
{
    long i = (long)blockIdx.x * 256 + threadIdx.x;
    int col = i % MM; long r = i / MM;
    int row = r % MM; int bh = r / MM;
    float inv = 1.f / g_colmax;
    g_zA[i] = g_a2[((long)bh * MM + col) * MM + row] * inv;
}

// ---------------- fused reshape + depthwise conv -------------------------------
__global__ void att_conv(const float* __restrict__ rw)
{
    long i = (long)blockIdx.x * 256 + threadIdx.x;
    int dq = i % 16; long r = i / 16;
    int h = r % HH;  long r2 = r / HH;
    int n = r2 % NN; int b = r2 / NN;
    long bhbase = (long)(b * HH + h) * NN;
    const float4* v4 = (const float4*)(g_v + bhbase * DHD);
    float4 a = *(const float4*)(g_o + (bhbase + n) * DHD + dq * 4);
#pragma unroll
    for (int j = 0; j < KC; j++) {
        int tt = n + j - KC / 2;
        if (tt >= 0 && tt < NN) {
            float w = rw[h * KC + j];
            float4 vv = v4[(long)tt * 16 + dq];
            a.x += w * vv.x; a.y += w * vv.y; a.z += w * vv.z; a.w += w * vv.w;
        }
    }
    *(float4*)(g_qkv + ((long)(b * NN + n)) * DD + h * DHD + dq * 4) = a;
}

// ---------------- host orchestration -------------------------------------------
extern "C" void kernel_launch(void* const* d_in, const int* in_sizes, int n_in,
                              void* d_out, int out_size)
{
    const float* x      = (const float*)d_in[0];
    const float* norm_w = (const float*)d_in[1];
    const float* norm_b = (const float*)d_in[2];
    const float* w_qkv  = (const float*)d_in[3];
    const float* w_out  = (const float*)d_in[4];
    const float* b_out  = (const float*)d_in[5];
    const float* res_w  = (const float*)d_in[6];
    float* y = (float*)d_out;

    float *p_xn, *p_qkv, *p_q, *p_k, *p_v, *p_o, *p_ql, *p_kl;
    float *p_a1, *p_a2, *p_zA, *p_zB, *p_xz, *p_t1, *p_t2, *p_a3v, *p_W;
    cudaGetSymbolAddress((void**)&p_xn,  g_xn);
    cudaGetSymbolAddress((void**)&p_qkv, g_qkv);
    cudaGetSymbolAddress((void**)&p_q,   g_q);
    cudaGetSymbolAddress((void**)&p_k,   g_k);
    cudaGetSymbolAddress((void**)&p_v,   g_v);
    cudaGetSymbolAddress((void**)&p_o,   g_o);
    cudaGetSymbolAddress((void**)&p_ql,  g_ql);
    cudaGetSymbolAddress((void**)&p_kl,  g_kl);
    cudaGetSymbolAddress((void**)&p_a1,  g_a1);
    cudaGetSymbolAddress((void**)&p_a2,  g_a2);
    cudaGetSymbolAddress((void**)&p_zA,  g_zA);
    cudaGetSymbolAddress((void**)&p_zB,  g_zB);
    cudaGetSymbolAddress((void**)&p_xz,  g_xz);
    cudaGetSymbolAddress((void**)&p_t1,  g_t1);
    cudaGetSymbolAddress((void**)&p_t2,  g_t2);
    cudaGetSymbolAddress((void**)&p_a3v, g_a3v);
    cudaGetSymbolAddress((void**)&p_W,   g_W);

    const long MM2 = (long)MM * MM;
    float* nul = nullptr;
    const float* cnul = nullptr;

    // 1. LayerNorm
    ln_kernel<<<BB * NN, 256>>>(x, norm_w, norm_b);
    // 2. qkv GEMM with fused head-split + q scale
    gemm_f16<1><<<dim3((3 * DD) / 64, (BB * NN) / 128, 1), 256>>>(
        p_xn, w_qkv, nul, nul, cnul, cnul, p_q, p_k, p_v,
        3 * DD, DD, 0, 0, 0, 1.f, 0.f);
    // 3. landmarks
    landmarks<<<(BH * MM * DHD) / 256, 256>>>();
    // 4. a2 = softmax(ql @ kl^T)
    sim_softmax<<<dim3(MM / 64, 1, BH), 256>>>(
        p_ql, p_kl, p_a2, (long)MM * DHD, (long)MM * DHD, MM2);
    // 5. pinv init
    init_colmax<<<1, 1>>>();
    colmax_kernel<<<BH, 256>>>();
    zinit<<<(BH * MM * MM) / 256, 256>>>();
    // 6. Newton-Schulz (aIminus fused)
    float* zin = p_zA; float* zout = p_zB;
    for (int it = 0; it < NITER; it++) {
        gemm_f16<0><<<dim3(MM / 64, MM / 128, BH), 256>>>(
            p_a2, zin, p_xz, p_t1, cnul, cnul, nul, nul, nul,
            MM, MM, MM2, MM2, MM2, 1.f, 7.f);
        gemm_f16<0><<<dim3(MM / 64, MM / 128, BH), 256>>>(
            p_xz, p_t1, nul, p_t2, cnul, cnul, nul, nul, nul,
            MM, MM, MM2, MM2, MM2, 1.f, 15.f);
        gemm_f16<0><<<dim3(MM / 64, MM / 128, BH), 256>>>(
            p_xz, p_t2, nul, p_t1, cnul, cnul, nul, nul, nul,
            MM, MM, MM2, MM2, MM2, 1.f, 13.f);
        gemm_f16<0><<<dim3(MM / 64, MM / 128, BH), 256>>>(
            zin, p_t1, zout, nul, cnul, cnul, nul, nul, nul,
            MM, MM, MM2, MM2, MM2, 0.25f, 0.f);
        float* tmp = zin; zin = zout; zout = tmp;
    }
    // 7. a1 = softmax(q @ kl^T)
    sim_softmax<<<dim3(NN / 64, 1, BH), 256>>>(
        p_q, p_kl, p_a1, (long)NN * DHD, (long)MM * DHD, (long)NN * MM);
    // 8. a3v = softmax(ql @ k^T) @ v  (flash)
    a3v_flash<<<dim3(MM / 32, 1, BH), 256>>>();
    // 9. W = z @ a3v
    gemm_f16<0><<<dim3(1, MM / 128, BH), 256>>>(
        zin, p_a3v, p_W, nul, cnul, cnul, nul, nul, nul,
        DHD, MM, MM2, (long)MM * DHD, (long)MM * DHD, 1.f, 0.f);
    // 10. out = a1 @ W
    gemm_f16<0><<<dim3(1, NN / 128, BH), 256>>>(
        p_a1, p_W, p_o, nul, cnul, cnul, nul, nul, nul,
        DHD, MM, (long)NN * MM, (long)MM * DHD, (long)NN * DHD, 1.f, 0.f);
    // 11. fused reshape + depthwise conv -> att
    att_conv<<<(BB * NN * HH * 16) / 256, 256>>>(res_w);
    // 12. proj + residual + bias -> y
    gemm_f16<2><<<dim3(DD / 64, (BB * NN) / 128, 1), 256>>>(
        p_qkv, w_out, y, nul, x, b_out, nul, nul, nul,
        DD, DD, 0, 0, 0, 1.f, 0.f);
}

// round 10
// speedup vs baseline: 4.6438x; 1.2477x over previous
#include <cuda_runtime.h>
#include <cuda_fp16.h>
#include <cstdint>

#define BB 4
#define NN 4096
#define DD 512
#define HH 8
#define DHD 64
#define MM 256
#define LLm 16
#define NITER 6
#define KC 33
#define BH (BB*HH)
#define SN 64
#define NCH (NN/SN)

// ---------------- scratch (half for MMA operands, fp32 where needed) -----------
__device__ __align__(16) __half h_xn   [BB*NN*DD];
__device__ __align__(16) __half h_wqkvT[3*DD*DD];     // [1536][512]
__device__ __align__(16) __half h_woutT[DD*DD];       // [512][512]
__device__ __align__(16) __half h_q  [BH*NN*DHD];
__device__ __align__(16) __half h_k  [BH*NN*DHD];
__device__ __align__(16) __half h_v  [BH*NN*DHD];
__device__ __align__(16) float  g_vf [BH*NN*DHD];     // fp32 v for conv
__device__ __align__(16) float  g_o  [BH*NN*DHD];
__device__ __align__(16) __half h_ql [BH*MM*DHD];
__device__ __align__(16) __half h_kl [BH*MM*DHD];
__device__ __align__(16) __half h_a1 [(long)BH*NN*MM];
__device__ __align__(16) __half h_a2 [BH*MM*MM];
__device__ __align__(16) __half h_z  [BH*MM*MM];
__device__ __align__(16) __half h_zT [BH*MM*MM];
__device__ __align__(16) __half h_z2 [BH*MM*MM];
__device__ __align__(16) __half h_z2T[BH*MM*MM];
__device__ __align__(16) __half h_xz [BH*MM*MM];
__device__ __align__(16) __half h_t1T[BH*MM*MM];
__device__ __align__(16) __half h_t2T[BH*MM*MM];
__device__ __align__(16) __half h_a3vT[BH*DHD*MM];    // [d][m]
__device__ __align__(16) __half h_WT [BH*DHD*MM];     // [d][m]
__device__ __align__(16) __half h_att[BB*NN*DD];
__device__ float g_colmax;

// ---------------- helpers ------------------------------------------------------
__device__ __forceinline__ uint32_t h2pack(float a, float b) {
    __half2 h = __floats2half2_rn(a, b);
    return *reinterpret_cast<uint32_t*>(&h);
}
__device__ __forceinline__ uint32_t prmtb(uint32_t a, uint32_t b, uint32_t sel) {
    uint32_t d;
    asm("prmt.b32 %0, %1, %2, %3;" : "=r"(d) : "r"(a), "r"(b), "r"(sel));
    return d;
}
__device__ __forceinline__ void mma_f16(float* c, const uint32_t* a, const uint32_t* b) {
    asm volatile(
        "mma.sync.aligned.m16n8k16.row.col.f32.f16.f16.f32 "
        "{%0,%1,%2,%3}, {%4,%5,%6,%7}, {%8,%9}, {%0,%1,%2,%3};"
        : "+f"(c[0]), "+f"(c[1]), "+f"(c[2]), "+f"(c[3])
        : "r"(a[0]), "r"(a[1]), "r"(a[2]), "r"(a[3]), "r"(b[0]), "r"(b[1]));
}
__device__ __forceinline__ void cpa16(uint32_t dst, const void* src) {
    asm volatile("cp.async.cg.shared.global [%0], [%1], 16;" :: "r"(dst), "l"(src));
}
#define CP_COMMIT() asm volatile("cp.async.commit_group;")

// =============================================================================
// gemm_h: C = alpha * A @ B^T, A [M][K] half, B [N][K] half (both k-contig).
// BM=128, BN template (64/128), BK=32. cp.async double-buffered, 2 blocks/SM.
// 8 warps 4m x 2n; warp tile 32 x (BN/2).
// MODE 0: p0 = float* C (normal, stride Nd), * alpha
// MODE 1: qkv split -> p0=h_q(x0.125) p1=h_k p2=h_v (half) p3=float* vf
// MODE 2: p0=float* y = acc + x(p1) + bout(p2)
// MODE 3: pinv: p0=half* Cn(normal, alpha*acc), p1=half* CtRaw(transposed, alpha*acc),
//               p2=half* CtDiag(transposed, dg*I - acc). strides: normal Nd, transposed Md.
// =============================================================================
template<int BN, int MODE>
__global__ __launch_bounds__(256, 2) void gemm_h(
    const __half* __restrict__ Ag, const __half* __restrict__ Bg,
    void* __restrict__ p0, void* __restrict__ p1, void* __restrict__ p2, void* __restrict__ p3,
    int Md, int Nd, int Kd, long sA, long sB, long sC,
    float alpha, float dg)
{
    constexpr int NT = BN / 16;          // n-tiles per warp (warp n-width = BN/2)
    constexpr int WN = BN / 2;
    constexpr int NBJ = BN / 64;         // B granule loads per thread

    __shared__ uint32_t As[2][128 * 16];
    __shared__ uint32_t Bs[2][BN * 16];

    const __half* A = Ag + (long)blockIdx.z * sA;
    const __half* Bp = Bg + (long)blockIdx.z * sB;
    const int m0 = blockIdx.y * 128;
    const int n0 = blockIdx.x * BN;
    const int tid = threadIdx.x;
    const int wid = tid >> 5, lane = tid & 31;
    const int warpm = wid & 3, warpn = wid >> 2;
    const int lg = lane >> 2, lt = lane & 3;
    const int swA = (lg >> 1) & 3;

    const uint32_t asmb = (uint32_t)__cvta_generic_to_shared(&As[0][0]);
    const uint32_t bsmb = (uint32_t)__cvta_generic_to_shared(&Bs[0][0]);

    float acc[2][NT][4];
#pragma unroll
    for (int mt = 0; mt < 2; mt++)
#pragma unroll
        for (int nt = 0; nt < NT; nt++)
#pragma unroll
            for (int i = 0; i < 4; i++) acc[mt][nt][i] = 0.f;

    const int nk = Kd >> 5;

#define LOADT(kt, st) do {                                                      \
    const int k0_ = (kt) << 5;                                                  \
    _Pragma("unroll")                                                           \
    for (int j = 0; j < 2; j++) {                                               \
        int e = tid + j * 256;                                                  \
        int row = e >> 2, g = e & 3;                                            \
        uint32_t d = asmb + (uint32_t)(((st) * 2048 + row * 16 +                \
                     4 * (g ^ ((row >> 1) & 3))) << 2);                         \
        cpa16(d, A + (long)(m0 + row) * Kd + k0_ + 8 * g);                      \
    }                                                                           \
    _Pragma("unroll")                                                           \
    for (int j = 0; j < NBJ; j++) {                                             \
        int e = tid + j * 256;                                                  \
        int n = e >> 2, g = e & 3;                                              \
        uint32_t d = bsmb + (uint32_t)(((st) * (BN * 16) + n * 16 +             \
                     4 * (g ^ ((n >> 1) & 3))) << 2);                           \
        cpa16(d, Bp + (long)(n0 + n) * Kd + k0_ + 8 * g);                       \
    }                                                                           \
    CP_COMMIT();                                                                \
} while (0)

    LOADT(0, 0);

    for (int kt = 0; kt < nk; kt++) {
        const int st = kt & 1;
        if (kt + 1 < nk) {
            LOADT(kt + 1, st ^ 1);
            asm volatile("cp.async.wait_group 1;");
        } else {
            asm volatile("cp.async.wait_group 0;");
        }
        __syncthreads();

#pragma unroll
        for (int s = 0; s < 2; s++) {
            const int sw0 = 4 * ((2 * s) ^ swA);
            const int sw1 = 4 * ((2 * s + 1) ^ swA);
            uint32_t af[2][4], bf[NT][2];
#pragma unroll
            for (int mt = 0; mt < 2; mt++) {
                int r = warpm * 32 + mt * 16 + lg;
                af[mt][0] = As[st][r * 16 + lt + sw0];
                af[mt][1] = As[st][(r + 8) * 16 + lt + sw0];
                af[mt][2] = As[st][r * 16 + lt + sw1];
                af[mt][3] = As[st][(r + 8) * 16 + lt + sw1];
            }
#pragma unroll
            for (int nt = 0; nt < NT; nt++) {
                int c = warpn * WN + nt * 8 + lg;
                bf[nt][0] = Bs[st][c * 16 + lt + sw0];
                bf[nt][1] = Bs[st][c * 16 + lt + sw1];
            }
#pragma unroll
            for (int mt = 0; mt < 2; mt++)
#pragma unroll
                for (int nt = 0; nt < NT; nt++)
                    mma_f16(acc[mt][nt], af[mt], bf[nt]);
        }
        __syncthreads();
    }
#undef LOADT

    // ---- epilogues ----
    if (MODE == 0) {
        float* C = (float*)p0 + (long)blockIdx.z * sC;
#pragma unroll
        for (int mt = 0; mt < 2; mt++)
#pragma unroll
            for (int nt = 0; nt < NT; nt++) {
                int r = m0 + warpm * 32 + mt * 16 + lg;
                int c = n0 + warpn * WN + nt * 8 + 2 * lt;
                *(float2*)(C + (long)r * Nd + c) =
                    make_float2(acc[mt][nt][0] * alpha, acc[mt][nt][1] * alpha);
                *(float2*)(C + (long)(r + 8) * Nd + c) =
                    make_float2(acc[mt][nt][2] * alpha, acc[mt][nt][3] * alpha);
            }
    } else if (MODE == 1) {
        __half* qh = (__half*)p0; __half* kh = (__half*)p1; __half* vh = (__half*)p2;
        float* vf = (float*)p3;
#pragma unroll
        for (int mt = 0; mt < 2; mt++)
#pragma unroll
            for (int nt = 0; nt < NT; nt++) {
                int c = n0 + warpn * WN + nt * 8 + 2 * lt;
                int which = c >> 9, cc = c & 511;
                int h = cc >> 6, d = cc & 63;
                float sc = (which == 0) ? 0.125f : 1.f;
                __half* dsth = (which == 0) ? qh : (which == 1) ? kh : vh;
#pragma unroll
                for (int half_ = 0; half_ < 2; half_++) {
                    int m = m0 + warpm * 32 + mt * 16 + half_ * 8 + lg;
                    int b = m >> 12, n = m & 4095;
                    long dst = ((long)(b * HH + h) * NN + n) * DHD + d;
                    float v0 = acc[mt][nt][half_ * 2] * sc;
                    float v1 = acc[mt][nt][half_ * 2 + 1] * sc;
                    *(uint32_t*)(dsth + dst) = h2pack(v0, v1);
                    if (which == 2)
                        *(float2*)(vf + dst) = make_float2(v0, v1);
                }
            }
    } else if (MODE == 2) {
        float* y = (float*)p0;
        const float* xp = (const float*)p1;
        const float* bp = (const float*)p2;
#pragma unroll
        for (int mt = 0; mt < 2; mt++)
#pragma unroll
            for (int nt = 0; nt < NT; nt++) {
                int r = m0 + warpm * 32 + mt * 16 + lg;
                int c = n0 + warpn * WN + nt * 8 + 2 * lt;
                float b0 = bp[c], b1 = bp[c + 1];
                float2 x0 = *(const float2*)(xp + (long)r * Nd + c);
                float2 x1 = *(const float2*)(xp + (long)(r + 8) * Nd + c);
                *(float2*)(y + (long)r * Nd + c) =
                    make_float2(acc[mt][nt][0] + x0.x + b0, acc[mt][nt][1] + x0.y + b1);
                *(float2*)(y + (long)(r + 8) * Nd + c) =
                    make_float2(acc[mt][nt][2] + x1.x + b0, acc[mt][nt][3] + x1.y + b1);
            }
    } else {
        __half* Cn = p0 ? (__half*)p0 + (long)blockIdx.z * sC : nullptr;
        __half* Ctr = p1 ? (__half*)p1 + (long)blockIdx.z * sC : nullptr;
        __half* Ctd = p2 ? (__half*)p2 + (long)blockIdx.z * sC : nullptr;
#pragma unroll
        for (int mt = 0; mt < 2; mt++)
#pragma unroll
            for (int nt = 0; nt < NT; nt++) {
                int r = m0 + warpm * 32 + mt * 16 + lg;
                int c = n0 + warpn * WN + nt * 8 + 2 * lt;
                float v00 = acc[mt][nt][0] * alpha;
                float v01 = acc[mt][nt][1] * alpha;
                float v10 = acc[mt][nt][2] * alpha;
                float v11 = acc[mt][nt][3] * alpha;
                if (Cn) {
                    *(uint32_t*)(Cn + (long)r * Nd + c)       = h2pack(v00, v01);
                    *(uint32_t*)(Cn + (long)(r + 8) * Nd + c) = h2pack(v10, v11);
                }
                if (Ctr) {
                    Ctr[(long)c * Md + r]           = __float2half(v00);
                    Ctr[(long)(c + 1) * Md + r]     = __float2half(v01);
                    Ctr[(long)c * Md + r + 8]       = __float2half(v10);
                    Ctr[(long)(c + 1) * Md + r + 8] = __float2half(v11);
                }
                if (Ctd) {
                    Ctd[(long)c * Md + r]           = __float2half(((r == c)         ? dg : 0.f) - v00);
                    Ctd[(long)(c + 1) * Md + r]     = __float2half(((r == c + 1)     ? dg : 0.f) - v01);
                    Ctd[(long)c * Md + r + 8]       = __float2half(((r + 8 == c)     ? dg : 0.f) - v10);
                    Ctd[(long)(c + 1) * Md + r + 8] = __float2half(((r + 8 == c + 1) ? dg : 0.f) - v11);
                }
            }
    }
}

// =============================================================================
// sim_softmax_h: Out(half) = softmax_row(A @ B^T), A [.][64] half, B [256][64] half.
// 64 rows/block; 8 warps 2m x 4n (warp 32x64).
// =============================================================================
__global__ __launch_bounds__(256, 2) void sim_softmax_h(
    const __half* __restrict__ Ag, const __half* __restrict__ Bg,
    __half* __restrict__ Og, long sA, long sB, long sO)
{
    __shared__ uint32_t As[64 * 16];
    __shared__ uint32_t Bs[256 * 16];
    __shared__ float redm[64 * 4];
    __shared__ float reds[64 * 4];

    const __half* A = Ag + (long)blockIdx.z * sA;
    const __half* B = Bg + (long)blockIdx.z * sB;
    __half*       O = Og + (long)blockIdx.z * sO;
    const int m0 = blockIdx.x * 64;
    const int tid = threadIdx.x;
    const int wid = tid >> 5, lane = tid & 31;
    const int warpm = wid & 1, warpn = wid >> 1;
    const int lg = lane >> 2, lt = lane & 3;
    const int swA = (lg >> 1) & 3;

    float acc[2][8][4];
#pragma unroll
    for (int mt = 0; mt < 2; mt++)
#pragma unroll
        for (int nt = 0; nt < 8; nt++)
#pragma unroll
            for (int i = 0; i < 4; i++) acc[mt][nt][i] = 0.f;

#pragma unroll
    for (int kt = 0; kt < 2; kt++) {
        const int k0 = kt * 32;
        {
            int row = tid >> 2, g = tid & 3;
            uint4 va = *(const uint4*)(A + (long)(m0 + row) * DHD + k0 + 8 * g);
            *(uint4*)&As[row * 16 + 4 * (g ^ ((row >> 1) & 3))] = va;
        }
#pragma unroll
        for (int j = 0; j < 4; j++) {
            int e = tid + j * 256;
            int n = e >> 2, g = e & 3;
            uint4 vb = *(const uint4*)(B + (long)n * DHD + k0 + 8 * g);
            *(uint4*)&Bs[n * 16 + 4 * (g ^ ((n >> 1) & 3))] = vb;
        }
        __syncthreads();

#pragma unroll
        for (int s = 0; s < 2; s++) {
            const int sw0 = 4 * ((2 * s) ^ swA);
            const int sw1 = 4 * ((2 * s + 1) ^ swA);
            uint32_t af[2][4], bf[8][2];
#pragma unroll
            for (int mt = 0; mt < 2; mt++) {
                int r = warpm * 32 + mt * 16 + lg;
                af[mt][0] = As[r * 16 + lt + sw0];
                af[mt][1] = As[(r + 8) * 16 + lt + sw0];
                af[mt][2] = As[r * 16 + lt + sw1];
                af[mt][3] = As[(r + 8) * 16 + lt + sw1];
            }
#pragma unroll
            for (int nt = 0; nt < 8; nt++) {
                int c = warpn * 64 + nt * 8 + lg;
                bf[nt][0] = Bs[c * 16 + lt + sw0];
                bf[nt][1] = Bs[c * 16 + lt + sw1];
            }
#pragma unroll
            for (int mt = 0; mt < 2; mt++)
#pragma unroll
                for (int nt = 0; nt < 8; nt++)
                    mma_f16(acc[mt][nt], af[mt], bf[nt]);
        }
        __syncthreads();
    }

#pragma unroll
    for (int mt = 0; mt < 2; mt++)
#pragma unroll
        for (int half_ = 0; half_ < 2; half_++) {
            float mx = -1e30f;
#pragma unroll
            for (int nt = 0; nt < 8; nt++) {
                mx = fmaxf(mx, acc[mt][nt][half_ * 2]);
                mx = fmaxf(mx, acc[mt][nt][half_ * 2 + 1]);
            }
            mx = fmaxf(mx, __shfl_xor_sync(~0u, mx, 1));
            mx = fmaxf(mx, __shfl_xor_sync(~0u, mx, 2));
            int rloc = warpm * 32 + mt * 16 + half_ * 8 + lg;
            if (lt == 0) redm[rloc * 4 + warpn] = mx;
        }
    __syncthreads();
#pragma unroll
    for (int mt = 0; mt < 2; mt++)
#pragma unroll
        for (int half_ = 0; half_ < 2; half_++) {
            int rloc = warpm * 32 + mt * 16 + half_ * 8 + lg;
            float m4 = fmaxf(fmaxf(redm[rloc * 4 + 0], redm[rloc * 4 + 1]),
                             fmaxf(redm[rloc * 4 + 2], redm[rloc * 4 + 3]));
            float s = 0.f;
#pragma unroll
            for (int nt = 0; nt < 8; nt++) {
                float e0 = __expf(acc[mt][nt][half_ * 2]     - m4);
                float e1 = __expf(acc[mt][nt][half_ * 2 + 1] - m4);
                acc[mt][nt][half_ * 2]     = e0;
                acc[mt][nt][half_ * 2 + 1] = e1;
                s += e0 + e1;
            }
            s += __shfl_xor_sync(~0u, s, 1);
            s += __shfl_xor_sync(~0u, s, 2);
            if (lt == 0) reds[rloc * 4 + warpn] = s;
        }
    __syncthreads();
#pragma unroll
    for (int mt = 0; mt < 2; mt++)
#pragma unroll
        for (int half_ = 0; half_ < 2; half_++) {
            int rloc = warpm * 32 + mt * 16 + half_ * 8 + lg;
            float tot = reds[rloc * 4 + 0] + reds[rloc * 4 + 1]
                      + reds[rloc * 4 + 2] + reds[rloc * 4 + 3];
            float inv = 1.f / tot;
            int r = m0 + rloc;
#pragma unroll
            for (int nt = 0; nt < 8; nt++) {
                int c = warpn * 64 + nt * 8 + 2 * lt;
                *(uint32_t*)(O + (long)r * MM + c) =
                    h2pack(acc[mt][nt][half_ * 2] * inv, acc[mt][nt][half_ * 2 + 1] * inv);
            }
        }
}

// =============================================================================
// a3v_flash_h: a3vT = (softmax_row(ql @ k^T) @ v)^T, online softmax, half inputs.
// 32 rows/block, grid (MM/32, 1, BH). Output transposed [d][m] half.
// =============================================================================
__global__ __launch_bounds__(256, 2) void a3v_flash_h()
{
    __shared__ uint32_t Ks[64 * 32];   // K [tok][32 u32]; rows 0-31 reused as P [m][32 kp]
    __shared__ uint32_t Vs[32 * 64];   // V interleaved [kp_tok][d]
    __shared__ float redm[32 * 4];
    __shared__ float reds[32 * 4];

    const int bh = blockIdx.z;
    const int m0 = blockIdx.x * 32;
    const __half* ql = h_ql + (long)bh * MM * DHD;
    const __half* kg = h_k  + (long)bh * NN * DHD;
    const __half* vg = h_v  + (long)bh * NN * DHD;

    const int tid = threadIdx.x;
    const int wid = tid >> 5, lane = tid & 31;
    const int warpm = wid & 1, warpn = wid >> 1;
    const int lg = lane >> 2, lt = lane & 3;

    uint32_t aq[4][4];
    {
        int mr = m0 + warpm * 16;
#pragma unroll
        for (int s = 0; s < 4; s++) {
            int d0 = s * 16 + 2 * lt;
            aq[s][0] = *(const uint32_t*)(ql + (long)(mr + lg) * DHD + d0);
            aq[s][1] = *(const uint32_t*)(ql + (long)(mr + 8 + lg) * DHD + d0);
            aq[s][2] = *(const uint32_t*)(ql + (long)(mr + lg) * DHD + d0 + 8);
            aq[s][3] = *(const uint32_t*)(ql + (long)(mr + 8 + lg) * DHD + d0 + 8);
        }
    }

    float oacc[2][4];
#pragma unroll
    for (int nt = 0; nt < 2; nt++)
#pragma unroll
        for (int i = 0; i < 4; i++) oacc[nt][i] = 0.f;
    float mprev[2] = {-1e30f, -1e30f};
    float lsum[2]  = {0.f, 0.f};

    // prefetch chunk 0
    uint4 kpre[2];
    uint2 vpa[2], vpb[2];
#pragma unroll
    for (int j = 0; j < 2; j++) {
        int e = tid + j * 256;
        { int tok = e >> 3, g = e & 7;
          kpre[j] = *(const uint4*)(kg + (long)tok * DHD + 8 * g); }
        { int kpt = e >> 4, d4 = (e & 15) << 2;
          vpa[j] = *(const uint2*)(vg + (long)(2 * kpt) * DHD + d4);
          vpb[j] = *(const uint2*)(vg + (long)(2 * kpt + 1) * DHD + d4); }
    }

    for (int ch = 0; ch < NCH; ch++) {
        __syncthreads();
#pragma unroll
        for (int j = 0; j < 2; j++) {
            int e = tid + j * 256;
            { int tok = e >> 3, g = e & 7;
              *(uint4*)&Ks[tok * 32 + 4 * (g ^ (tok & 7))] = kpre[j]; }
            { int kpt = e >> 4, d4 = (e & 15) << 2;
              uint4 w;
              w.x = prmtb(vpa[j].x, vpb[j].x, 0x5410);
              w.y = prmtb(vpa[j].x, vpb[j].x, 0x7632);
              w.z = prmtb(vpa[j].y, vpb[j].y, 0x5410);
              w.w = prmtb(vpa[j].y, vpb[j].y, 0x7632);
              *(uint4*)&Vs[kpt * 64 + (d4 ^ ((kpt & 3) << 3))] = w; }
        }
        if (ch + 1 < NCH) {
            const __half* kc = kg + (long)(ch + 1) * SN * DHD;
            const __half* vc = vg + (long)(ch + 1) * SN * DHD;
#pragma unroll
            for (int j = 0; j < 2; j++) {
                int e = tid + j * 256;
                { int tok = e >> 3, g = e & 7;
                  kpre[j] = *(const uint4*)(kc + (long)tok * DHD + 8 * g); }
                { int kpt = e >> 4, d4 = (e & 15) << 2;
                  vpa[j] = *(const uint2*)(vc + (long)(2 * kpt) * DHD + d4);
                  vpb[j] = *(const uint2*)(vc + (long)(2 * kpt + 1) * DHD + d4); }
            }
        }
        __syncthreads();

        // S = ql @ K^T : 16 rows x 16 tokens per warp, 4 k16 steps over d
        float sacc[2][4];
#pragma unroll
        for (int nt = 0; nt < 2; nt++)
#pragma unroll
            for (int i = 0; i < 4; i++) sacc[nt][i] = 0.f;
#pragma unroll
        for (int s = 0; s < 4; s++) {
            uint32_t bf[2][2];
#pragma unroll
            for (int nt = 0; nt < 2; nt++) {
                int c = warpn * 16 + nt * 8 + lg;
                bf[nt][0] = Ks[c * 32 + lt + 4 * ((2 * s) ^ (c & 7))];
                bf[nt][1] = Ks[c * 32 + lt + 4 * ((2 * s + 1) ^ (c & 7))];
            }
#pragma unroll
            for (int nt = 0; nt < 2; nt++)
                mma_f16(sacc[nt], aq[s], bf[nt]);
        }

#pragma unroll
        for (int half_ = 0; half_ < 2; half_++) {
            float mx = -1e30f;
#pragma unroll
            for (int nt = 0; nt < 2; nt++) {
                mx = fmaxf(mx, sacc[nt][half_ * 2]);
                mx = fmaxf(mx, sacc[nt][half_ * 2 + 1]);
            }
            mx = fmaxf(mx, __shfl_xor_sync(~0u, mx, 1));
            mx = fmaxf(mx, __shfl_xor_sync(~0u, mx, 2));
            if (lt == 0) redm[(warpm * 16 + half_ * 8 + lg) * 4 + warpn] = mx;
        }
        __syncthreads();

        float scale[2];
#pragma unroll
        for (int half_ = 0; half_ < 2; half_++) {
            int row = warpm * 16 + half_ * 8 + lg;
            float mch = fmaxf(fmaxf(redm[row * 4 + 0], redm[row * 4 + 1]),
                              fmaxf(redm[row * 4 + 2], redm[row * 4 + 3]));
            float mnew = fmaxf(mprev[half_], mch);
            scale[half_] = __expf(mprev[half_] - mnew);
            mprev[half_] = mnew;
            float s = 0.f;
#pragma unroll
            for (int nt = 0; nt < 2; nt++) {
                float e0 = __expf(sacc[nt][half_ * 2]     - mnew);
                float e1 = __expf(sacc[nt][half_ * 2 + 1] - mnew);
                sacc[nt][half_ * 2]     = e0;
                sacc[nt][half_ * 2 + 1] = e1;
                s += e0 + e1;
            }
            s += __shfl_xor_sync(~0u, s, 1);
            s += __shfl_xor_sync(~0u, s, 2);
            if (lt == 0) reds[row * 4 + warpn] = s;
#pragma unroll
            for (int nt = 0; nt < 2; nt++) {
                int kp = warpn * 8 + nt * 4 + lt;
                Ks[row * 32 + (kp ^ ((row & 7) << 2))] =
                    h2pack(sacc[nt][half_ * 2], sacc[nt][half_ * 2 + 1]);
            }
        }
        __syncthreads();

#pragma unroll
        for (int half_ = 0; half_ < 2; half_++) {
            int row = warpm * 16 + half_ * 8 + lg;
            lsum[half_] = lsum[half_] * scale[half_]
                        + reds[row * 4 + 0] + reds[row * 4 + 1]
                        + reds[row * 4 + 2] + reds[row * 4 + 3];
        }
#pragma unroll
        for (int nt = 0; nt < 2; nt++) {
            oacc[nt][0] *= scale[0]; oacc[nt][1] *= scale[0];
            oacc[nt][2] *= scale[1]; oacc[nt][3] *= scale[1];
        }

        // O += P @ V : 16 rows x 16 d per warp, 4 k16 steps over tokens
#pragma unroll
        for (int s = 0; s < 4; s++) {
            const int kp0 = s * 8;
            int mr = warpm * 16 + lg;
            uint32_t af[4];
            af[0] = Ks[mr * 32 + ((kp0 + lt) ^ ((mr & 7) << 2))];
            af[1] = Ks[(mr + 8) * 32 + ((kp0 + lt) ^ (((mr + 8) & 7) << 2))];
            af[2] = Ks[mr * 32 + ((kp0 + lt + 4) ^ ((mr & 7) << 2))];
            af[3] = Ks[(mr + 8) * 32 + ((kp0 + lt + 4) ^ (((mr + 8) & 7) << 2))];
            uint32_t bf[2][2];
#pragma unroll
            for (int nt = 0; nt < 2; nt++) {
                int d = warpn * 16 + nt * 8 + lg;
                bf[nt][0] = Vs[(kp0 + lt) * 64 + (d ^ (lt << 3))];
                bf[nt][1] = Vs[(kp0 + lt + 4) * 64 + (d ^ (lt << 3))];
            }
#pragma unroll
            for (int nt = 0; nt < 2; nt++)
                mma_f16(oacc[nt], af, bf[nt]);
        }
    }

    __half* outb = h_a3vT + (long)bh * DHD * MM;
#pragma unroll
    for (int half_ = 0; half_ < 2; half_++) {
        float inv = 1.f / lsum[half_];
        int r = m0 + warpm * 16 + half_ * 8 + lg;
#pragma unroll
        for (int nt = 0; nt < 2; nt++) {
            int d = warpn * 16 + nt * 8 + 2 * lt;
            outb[(long)d * MM + r]       = __float2half(oacc[nt][half_ * 2] * inv);
            outb[(long)(d + 1) * MM + r] = __float2half(oacc[nt][half_ * 2 + 1] * inv);
        }
    }
}

// ---------------- LayerNorm (half out) -----------------------------------------
__global__ __launch_bounds__(256) void ln_kernel(
    const float* __restrict__ x, const float* __restrict__ w, const float* __restrict__ b)
{
    long row = blockIdx.x;
    const float* xr = x + row * DD;
    int t = threadIdx.x;
    float v0 = xr[t], v1 = xr[t + 256];
    __shared__ float red[32];

    float s = v0 + v1;
    for (int o = 16; o > 0; o >>= 1) s += __shfl_xor_sync(~0u, s, o);
    if ((t & 31) == 0) red[t >> 5] = s;
    __syncthreads();
    if (t < 32) {
        float ss = (t < 8) ? red[t] : 0.f;
        for (int o = 4; o > 0; o >>= 1) ss += __shfl_xor_sync(~0u, ss, o);
        if (t == 0) red[0] = ss;
    }
    __syncthreads();
    float mu = red[0] * (1.f / DD);
    __syncthreads();

    float d0 = v0 - mu, d1 = v1 - mu;
    float q = d0 * d0 + d1 * d1;
    for (int o = 16; o > 0; o >>= 1) q += __shfl_xor_sync(~0u, q, o);
    if ((t & 31) == 0) red[t >> 5] = q;
    __syncthreads();
    if (t < 32) {
        float ss = (t < 8) ? red[t] : 0.f;
        for (int o = 4; o > 0; o >>= 1) ss += __shfl_xor_sync(~0u, ss, o);
        if (t == 0) red[0] = ss;
    }
    __syncthreads();
    float inv = rsqrtf(red[0] * (1.f / DD) + 1e-5f);
    h_xn[row * DD + t]       = __float2half(d0 * inv * w[t]       + b[t]);
    h_xn[row * DD + t + 256] = __float2half(d1 * inv * w[t + 256] + b[t + 256]);
}

// ---------------- weight conversion (transpose to [N][K] half) ----------------
__global__ void conv_weights(const float* __restrict__ wq, const float* __restrict__ wo)
{
    int i = blockIdx.x * 256 + threadIdx.x;           // 3*DD*DD
    {
        int n = i / DD, k2 = i % DD;
        h_wqkvT[i] = __float2half(wq[(long)k2 * (3 * DD) + n]);
    }
    if (i < DD * DD) {
        int n = i / DD, k2 = i % DD;
        h_woutT[i] = __float2half(wo[(long)k2 * DD + n]);
    }
}

// ---------------- landmarks ----------------------------------------------------
__global__ void landmarks()
{
    long i = (long)blockIdx.x * 256 + threadIdx.x;
    int d = i % DHD; long r = i / DHD;
    int m = r % MM;  int bh = r / MM;
    long base = ((long)bh * NN + m * LLm) * DHD + d;
    float sq = 0.f, sk = 0.f;
#pragma unroll
    for (int u = 0; u < LLm; u++) {
        sq += __half2float(h_q[base + u * DHD]);
        sk += __half2float(h_k[base + u * DHD]);
    }
    h_ql[i] = __float2half(sq * (1.f / LLm));
    h_kl[i] = __float2half(sk * (1.f / LLm));
}

// ---------------- pinv init ----------------------------------------------------
__global__ void init_colmax() { g_colmax = 0.f; }

__global__ __launch_bounds__(256) void colmax_kernel()
{
    int bh = blockIdx.x, j = threadIdx.x;
    const __half* a = h_a2 + (long)bh * MM * MM;
    float s = 0.f;
    for (int i = 0; i < MM; i++) s += __half2float(a[i * MM + j]);
    __shared__ float red[32];
    float m = s;
    for (int o = 16; o > 0; o >>= 1) m = fmaxf(m, __shfl_xor_sync(~0u, m, o));
    if ((j & 31) == 0) red[j >> 5] = m;
    __syncthreads();
    if (j < 32) {
        float m2 = (j < 8) ? red[j] : -1e30f;
        for (int o = 4; o > 0; o >>= 1) m2 = fmaxf(m2, __shfl_xor_sync(~0u, m2, o));
        if (j == 0) atomicMax((int*)&g_colmax, __float_as_int(m2));
    }
}

__global__ void zinit()
{
    long i = (long)blockIdx.x * 256 + threadIdx.x;    // BH*MM*MM
    int col = i % MM; long r = i / MM;
    int row = r % MM; int bh = r / MM;
    float inv = 1.f / g_colmax;
    // zT = a2 * inv (elementwise; z = a2^T * inv)
    h_zT[i] = __float2half(__half2float(h_a2[i]) * inv);
    h_z [i] = __float2half(__half2float(h_a2[((long)bh * MM + col) * MM + row]) * inv);
}

// ---------------- fused reshape + depthwise conv (fp32 in, half att out) -------
__global__ void att_conv(const float* __restrict__ rw)
{
    long i = (long)blockIdx.x * 256 + threadIdx.x;    // BH*NN*16 float4-granules
    int dq = i % 16; long r = i / 16;
    int h = r % HH;  long r2 = r / HH;
    int n = r2 % NN; int b = r2 / NN;
    long bhbase = (long)(b * HH + h) * NN;
    const float4* v4 = (const float4*)(g_vf + bhbase * DHD);
    float4 a = *(const float4*)(g_o + (bhbase + n) * DHD + dq * 4);
#pragma unroll
    for (int j = 0; j < KC; j++) {
        int tt = n + j - KC / 2;
        if (tt >= 0 && tt < NN) {
            float w = rw[h * KC + j];
            float4 vv = v4[(long)tt * 16 + dq];
            a.x += w * vv.x; a.y += w * vv.y; a.z += w * vv.z; a.w += w * vv.w;
        }
    }
    uint2 w2;
    w2.x = h2pack(a.x, a.y);
    w2.y = h2pack(a.z, a.w);
    *(uint2*)&h_att[((long)(b * NN + n)) * DD + h * DHD + dq * 4] = w2;
}

// ---------------- host orchestration -------------------------------------------
extern "C" void kernel_launch(void* const* d_in, const int* in_sizes, int n_in,
                              void* d_out, int out_size)
{
    const float* x      = (const float*)d_in[0];
    const float* norm_w = (const float*)d_in[1];
    const float* norm_b = (const float*)d_in[2];
    const float* w_qkv  = (const float*)d_in[3];
    const float* w_out  = (const float*)d_in[4];
    const float* b_out  = (const float*)d_in[5];
    const float* res_w  = (const float*)d_in[6];
    float* y = (float*)d_out;

    __half *p_xn, *p_wqkvT, *p_woutT, *p_q, *p_k, *p_v, *p_ql, *p_kl;
    __half *p_a1, *p_a2, *p_z, *p_zT, *p_z2, *p_z2T, *p_xz, *p_t1T, *p_t2T, *p_a3vT, *p_WT, *p_att;
    float *p_vf, *p_o;
    cudaGetSymbolAddress((void**)&p_xn,   h_xn);
    cudaGetSymbolAddress((void**)&p_wqkvT,h_wqkvT);
    cudaGetSymbolAddress((void**)&p_woutT,h_woutT);
    cudaGetSymbolAddress((void**)&p_q,    h_q);
    cudaGetSymbolAddress((void**)&p_k,    h_k);
    cudaGetSymbolAddress((void**)&p_v,    h_v);
    cudaGetSymbolAddress((void**)&p_ql,   h_ql);
    cudaGetSymbolAddress((void**)&p_kl,   h_kl);
    cudaGetSymbolAddress((void**)&p_a1,   h_a1);
    cudaGetSymbolAddress((void**)&p_a2,   h_a2);
    cudaGetSymbolAddress((void**)&p_z,    h_z);
    cudaGetSymbolAddress((void**)&p_zT,   h_zT);
    cudaGetSymbolAddress((void**)&p_z2,   h_z2);
    cudaGetSymbolAddress((void**)&p_z2T,  h_z2T);
    cudaGetSymbolAddress((void**)&p_xz,   h_xz);
    cudaGetSymbolAddress((void**)&p_t1T,  h_t1T);
    cudaGetSymbolAddress((void**)&p_t2T,  h_t2T);
    cudaGetSymbolAddress((void**)&p_a3vT, h_a3vT);
    cudaGetSymbolAddress((void**)&p_WT,   h_WT);
    cudaGetSymbolAddress((void**)&p_att,  h_att);
    cudaGetSymbolAddress((void**)&p_vf,   g_vf);
    cudaGetSymbolAddress((void**)&p_o,    g_o);

    const long MM2 = (long)MM * MM;
    void* nul = nullptr;

    // 1. LayerNorm -> h_xn; weight conversion
    ln_kernel<<<BB * NN, 256>>>(x, norm_w, norm_b);
    conv_weights<<<(3 * DD * DD) / 256, 256>>>(w_qkv, w_out);
    // 2. qkv = xn @ wqkvT^T with fused split
    gemm_h<128, 1><<<dim3((3 * DD) / 128, (BB * NN) / 128, 1), 256>>>(
        p_xn, p_wqkvT, p_q, p_k, p_v, p_vf,
        BB * NN, 3 * DD, DD, 0, 0, 0, 1.f, 0.f);
    // 3. landmarks
    landmarks<<<(BH * MM * DHD) / 256, 256>>>();
    // 4. a2 = softmax(ql @ kl^T)
    sim_softmax_h<<<dim3(MM / 64, 1, BH), 256>>>(
        p_ql, p_kl, p_a2, (long)MM * DHD, (long)MM * DHD, MM2);
    // 5. pinv init
    init_colmax<<<1, 1>>>();
    colmax_kernel<<<BH, 256>>>();
    zinit<<<(int)((long)BH * MM * MM / 256), 256>>>();
    // 6. Newton-Schulz
    __half *zin = p_z, *zinT = p_zT, *zout = p_z2, *zoutT = p_z2T;
    for (int it = 0; it < NITER; it++) {
        // xz = a2 @ z ; t1T = (7I - xz)^T
        gemm_h<64, 3><<<dim3(MM / 64, MM / 128, BH), 256>>>(
            p_a2, zinT, p_xz, nul, p_t1T, nul, MM, MM, MM, MM2, MM2, MM2, 1.f, 7.f);
        // t2T = (15I - xz @ t1)^T
        gemm_h<64, 3><<<dim3(MM / 64, MM / 128, BH), 256>>>(
            p_xz, p_t1T, nul, nul, p_t2T, nul, MM, MM, MM, MM2, MM2, MM2, 1.f, 15.f);
        // t1T = (13I - xz @ t2)^T
        gemm_h<64, 3><<<dim3(MM / 64, MM / 128, BH), 256>>>(
            p_xz, p_t2T, nul, nul, p_t1T, nul, MM, MM, MM, MM2, MM2, MM2, 1.f, 13.f);
        // zout = 0.25 * z @ t1  (normal + transposed)
        gemm_h<64, 3><<<dim3(MM / 64, MM / 128, BH), 256>>>(
            zin, p_t1T, zout, zoutT, nul, nul, MM, MM, MM, MM2, MM2, MM2, 0.25f, 0.f);
        __half* t;
        t = zin;  zin  = zout;  zout  = t;
        t = zinT; zinT = zoutT; zoutT = t;
    }
    // 7. a1 = softmax(q @ kl^T)
    sim_softmax_h<<<dim3(NN / 64, 1, BH), 256>>>(
        p_q, p_kl, p_a1, (long)NN * DHD, (long)MM * DHD, (long)NN * MM);
    // 8. a3vT = (softmax(ql @ k^T) @ v)^T  (flash)
    a3v_flash_h<<<dim3(MM / 32, 1, BH), 256>>>();
    // 9. WT = (z @ a3v)^T
    gemm_h<64, 3><<<dim3(1, MM / 128, BH), 256>>>(
        zin, p_a3vT, nul, p_WT, nul, nul, MM, DHD, MM,
        MM2, (long)DHD * MM, (long)DHD * MM, 1.f, 0.f);
    // 10. o = a1 @ W  (fp32 out)
    gemm_h<64, 0><<<dim3(1, NN / 128, BH), 256>>>(
        p_a1, p_WT, p_o, nul, nul, nul, NN, DHD, MM,
        (long)NN * MM, (long)DHD * MM, (long)NN * DHD, 1.f, 0.f);
    // 11. att = reshape(o) + conv(v)  (half out)
    att_conv<<<(BB * NN * HH * 16) / 256, 256>>>(res_w);
    // 12. y = att @ w_out + x + b_out
    gemm_h<128, 2><<<dim3(DD / 128, (BB * NN) / 128, 1), 256>>>(
        p_att, p_woutT, y, (void*)x, (void*)b_out, nul,
        BB * NN, DD, DD, 0, 0, 0, 1.f, 0.f);
}

// round 11
// speedup vs baseline: 4.9022x; 1.0556x over previous
#include <cuda_runtime.h>
#include <cuda_fp16.h>
#include <cstdint>

#define BB 4
#define NN 4096
#define DD 512
#define HH 8
#define DHD 64
#define MM 256
#define LLm 16
#define NITER 6
#define KC 33
#define BH (BB*HH)
#define SN 64
#define NCH (NN/SN)

// ---------------- scratch (half for MMA operands, fp32 where needed) -----------
__device__ __align__(16) __half h_xn   [BB*NN*DD];
__device__ __align__(16) __half h_wqkvT[3*DD*DD];     // [1536][512]
__device__ __align__(16) __half h_woutT[DD*DD];       // [512][512]
__device__ __align__(16) __half h_q  [BH*NN*DHD];
__device__ __align__(16) __half h_k  [BH*NN*DHD];
__device__ __align__(16) __half h_v  [BH*NN*DHD];
__device__ __align__(16) float  g_vf [BH*NN*DHD];     // fp32 v for conv
__device__ __align__(16) float  g_o  [BH*NN*DHD];
__device__ __align__(16) __half h_ql [BH*MM*DHD];
__device__ __align__(16) __half h_kl [BH*MM*DHD];
__device__ __align__(16) __half h_a1 [(long)BH*NN*MM];
__device__ __align__(16) __half h_a2 [BH*MM*MM];
__device__ __align__(16) __half h_z  [BH*MM*MM];
__device__ __align__(16) __half h_zT [BH*MM*MM];
__device__ __align__(16) __half h_z2 [BH*MM*MM];
__device__ __align__(16) __half h_z2T[BH*MM*MM];
__device__ __align__(16) __half h_xz [BH*MM*MM];
__device__ __align__(16) __half h_t1T[BH*MM*MM];
__device__ __align__(16) __half h_t2T[BH*MM*MM];
__device__ __align__(16) __half h_a3vT[BH*DHD*MM];    // [d][m]
__device__ __align__(16) __half h_WT [BH*DHD*MM];     // [d][m]
__device__ __align__(16) __half h_att[BB*NN*DD];
__device__ float g_colmax;

// ---------------- helpers ------------------------------------------------------
__device__ __forceinline__ uint32_t h2pack(float a, float b) {
    __half2 h = __floats2half2_rn(a, b);
    return *reinterpret_cast<uint32_t*>(&h);
}
__device__ __forceinline__ uint32_t prmtb(uint32_t a, uint32_t b, uint32_t sel) {
    uint32_t d;
    asm("prmt.b32 %0, %1, %2, %3;" : "=r"(d) : "r"(a), "r"(b), "r"(sel));
    return d;
}
__device__ __forceinline__ void mma_f16(float* c, const uint32_t* a, const uint32_t* b) {
    asm volatile(
        "mma.sync.aligned.m16n8k16.row.col.f32.f16.f16.f32 "
        "{%0,%1,%2,%3}, {%4,%5,%6,%7}, {%8,%9}, {%0,%1,%2,%3};"
        : "+f"(c[0]), "+f"(c[1]), "+f"(c[2]), "+f"(c[3])
        : "r"(a[0]), "r"(a[1]), "r"(a[2]), "r"(a[3]), "r"(b[0]), "r"(b[1]));
}
__device__ __forceinline__ void ldsm4(uint32_t* r, uint32_t saddr) {
    asm volatile("ldmatrix.sync.aligned.m8n8.x4.shared.b16 {%0,%1,%2,%3}, [%4];"
        : "=r"(r[0]), "=r"(r[1]), "=r"(r[2]), "=r"(r[3]) : "r"(saddr));
}
__device__ __forceinline__ void ldsm2(uint32_t* r, uint32_t saddr) {
    asm volatile("ldmatrix.sync.aligned.m8n8.x2.shared.b16 {%0,%1}, [%2];"
        : "=r"(r[0]), "=r"(r[1]) : "r"(saddr));
}
__device__ __forceinline__ void cpa16(uint32_t dst, const void* src) {
    asm volatile("cp.async.cg.shared.global [%0], [%1], 16;" :: "r"(dst), "l"(src));
}
#define CP_COMMIT() asm volatile("cp.async.commit_group;")

// =============================================================================
// gemm_h: C = alpha * A @ B^T, A [M][K] half, B [N][K] half (both k-contig).
// BM=128, BN template (64/128), BK=32. cp.async double-buffered, LDSM fragment
// loads, 2 blocks/SM. 8 warps 4m x 2n; warp tile 32 x (BN/2).
// MODE 0: p0 = float* C (normal, stride Nd), * alpha
// MODE 1: qkv split -> p0=h_q(x0.125) p1=h_k p2=h_v (half) p3=float* vf
// MODE 2: p0=float* y = acc + x(p1) + bout(p2)
// MODE 3: pinv: p0=half* Cn(normal), p1=half* CtRaw(transposed, alpha*acc),
//               p2=half* CtDiag(transposed, dg*I - acc).
// =============================================================================
template<int BN, int MODE>
__global__ __launch_bounds__(256, 2) void gemm_h(
    const __half* __restrict__ Ag, const __half* __restrict__ Bg,
    void* __restrict__ p0, void* __restrict__ p1, void* __restrict__ p2, void* __restrict__ p3,
    int Md, int Nd, int Kd, long sA, long sB, long sC,
    float alpha, float dg)
{
    constexpr int NT = BN / 16;
    constexpr int WN = BN / 2;
    constexpr int NBJ = BN / 64;

    __shared__ uint32_t As[2][128 * 16];
    __shared__ uint32_t Bs[2][BN * 16];

    const __half* A = Ag + (long)blockIdx.z * sA;
    const __half* Bp = Bg + (long)blockIdx.z * sB;
    const int m0 = blockIdx.y * 128;
    const int n0 = blockIdx.x * BN;
    const int tid = threadIdx.x;
    const int wid = tid >> 5, lane = tid & 31;
    const int warpm = wid & 3, warpn = wid >> 2;
    const int lg = lane >> 2, lt = lane & 3;

    const uint32_t asmb = (uint32_t)__cvta_generic_to_shared(&As[0][0]);
    const uint32_t bsmb = (uint32_t)__cvta_generic_to_shared(&Bs[0][0]);

    // LDSM lane addressing (precomputed)
    const int t4  = lane >> 3;               // tile index 0..3 (x4)
    const int agh = t4 >> 1;                 // A granule parity
    int aoff[2], asw[2];
#pragma unroll
    for (int mt = 0; mt < 2; mt++) {
        int rr = warpm * 32 + mt * 16 + (t4 & 1) * 8 + (lane & 7);
        aoff[mt] = rr * 64;
        asw[mt]  = (rr >> 1) & 3;
    }
    const int btb = t4 & 1;                  // B granule parity (x2)
    int boff[NT], bsw[NT];
#pragma unroll
    for (int nt = 0; nt < NT; nt++) {
        int n = warpn * WN + nt * 8 + (lane & 7);
        boff[nt] = n * 64;
        bsw[nt]  = (n >> 1) & 3;
    }

    float acc[2][NT][4];
#pragma unroll
    for (int mt = 0; mt < 2; mt++)
#pragma unroll
        for (int nt = 0; nt < NT; nt++)
#pragma unroll
            for (int i = 0; i < 4; i++) acc[mt][nt][i] = 0.f;

    const int nk = Kd >> 5;

#define LOADT(kt, st) do {                                                      \
    const int k0_ = (kt) << 5;                                                  \
    _Pragma("unroll")                                                           \
    for (int j = 0; j < 2; j++) {                                               \
        int e = tid + j * 256;                                                  \
        int row = e >> 2, g = e & 3;                                            \
        uint32_t d = asmb + (uint32_t)(((st) * 2048 + row * 16 +                \
                     4 * (g ^ ((row >> 1) & 3))) << 2);                         \
        cpa16(d, A + (long)(m0 + row) * Kd + k0_ + 8 * g);                      \
    }                                                                           \
    _Pragma("unroll")                                                           \
    for (int j = 0; j < NBJ; j++) {                                             \
        int e = tid + j * 256;                                                  \
        int n = e >> 2, g = e & 3;                                              \
        uint32_t d = bsmb + (uint32_t)(((st) * (BN * 16) + n * 16 +             \
                     4 * (g ^ ((n >> 1) & 3))) << 2);                           \
        cpa16(d, Bp + (long)(n0 + n) * Kd + k0_ + 8 * g);                       \
    }                                                                           \
    CP_COMMIT();                                                                \
} while (0)

    LOADT(0, 0);

    for (int kt = 0; kt < nk; kt++) {
        const int st = kt & 1;
        if (kt + 1 < nk) {
            LOADT(kt + 1, st ^ 1);
            asm volatile("cp.async.wait_group 1;");
        } else {
            asm volatile("cp.async.wait_group 0;");
        }
        __syncthreads();

        const uint32_t a_base = asmb + (uint32_t)((st * 2048) << 2);
        const uint32_t b_base = bsmb + (uint32_t)((st * (BN * 16)) << 2);
#pragma unroll
        for (int s = 0; s < 2; s++) {
            uint32_t af[2][4], bf[NT][2];
#pragma unroll
            for (int mt = 0; mt < 2; mt++)
                ldsm4(af[mt], a_base + (uint32_t)((aoff[mt] +
                      ((((s << 1) | agh) ^ asw[mt]) << 4))));
#pragma unroll
            for (int nt = 0; nt < NT; nt++)
                ldsm2(bf[nt], b_base + (uint32_t)((boff[nt] +
                      ((((s << 1) | btb) ^ bsw[nt]) << 4))));
#pragma unroll
            for (int mt = 0; mt < 2; mt++)
#pragma unroll
                for (int nt = 0; nt < NT; nt++)
                    mma_f16(acc[mt][nt], af[mt], bf[nt]);
        }
        __syncthreads();
    }
#undef LOADT

    // ---- epilogues ----
    if (MODE == 0) {
        float* C = (float*)p0 + (long)blockIdx.z * sC;
#pragma unroll
        for (int mt = 0; mt < 2; mt++)
#pragma unroll
            for (int nt = 0; nt < NT; nt++) {
                int r = m0 + warpm * 32 + mt * 16 + lg;
                int c = n0 + warpn * WN + nt * 8 + 2 * lt;
                *(float2*)(C + (long)r * Nd + c) =
                    make_float2(acc[mt][nt][0] * alpha, acc[mt][nt][1] * alpha);
                *(float2*)(C + (long)(r + 8) * Nd + c) =
                    make_float2(acc[mt][nt][2] * alpha, acc[mt][nt][3] * alpha);
            }
    } else if (MODE == 1) {
        __half* qh = (__half*)p0; __half* kh = (__half*)p1; __half* vh = (__half*)p2;
        float* vf = (float*)p3;
#pragma unroll
        for (int mt = 0; mt < 2; mt++)
#pragma unroll
            for (int nt = 0; nt < NT; nt++) {
                int c = n0 + warpn * WN + nt * 8 + 2 * lt;
                int which = c >> 9, cc = c & 511;
                int h = cc >> 6, d = cc & 63;
                float sc = (which == 0) ? 0.125f : 1.f;
                __half* dsth = (which == 0) ? qh : (which == 1) ? kh : vh;
#pragma unroll
                for (int half_ = 0; half_ < 2; half_++) {
                    int m = m0 + warpm * 32 + mt * 16 + half_ * 8 + lg;
                    int b = m >> 12, n = m & 4095;
                    long dst = ((long)(b * HH + h) * NN + n) * DHD + d;
                    float v0 = acc[mt][nt][half_ * 2] * sc;
                    float v1 = acc[mt][nt][half_ * 2 + 1] * sc;
                    *(uint32_t*)(dsth + dst) = h2pack(v0, v1);
                    if (which == 2)
                        *(float2*)(vf + dst) = make_float2(v0, v1);
                }
            }
    } else if (MODE == 2) {
        float* y = (float*)p0;
        const float* xp = (const float*)p1;
        const float* bp = (const float*)p2;
#pragma unroll
        for (int mt = 0; mt < 2; mt++)
#pragma unroll
            for (int nt = 0; nt < NT; nt++) {
                int r = m0 + warpm * 32 + mt * 16 + lg;
                int c = n0 + warpn * WN + nt * 8 + 2 * lt;
                float b0 = bp[c], b1 = bp[c + 1];
                float2 x0 = *(const float2*)(xp + (long)r * Nd + c);
                float2 x1 = *(const float2*)(xp + (long)(r + 8) * Nd + c);
                *(float2*)(y + (long)r * Nd + c) =
                    make_float2(acc[mt][nt][0] + x0.x + b0, acc[mt][nt][1] + x0.y + b1);
                *(float2*)(y + (long)(r + 8) * Nd + c) =
                    make_float2(acc[mt][nt][2] + x1.x + b0, acc[mt][nt][3] + x1.y + b1);
            }
    } else {
        __half* Cn = p0 ? (__half*)p0 + (long)blockIdx.z * sC : nullptr;
        __half* Ctr = p1 ? (__half*)p1 + (long)blockIdx.z * sC : nullptr;
        __half* Ctd = p2 ? (__half*)p2 + (long)blockIdx.z * sC : nullptr;
#pragma unroll
        for (int mt = 0; mt < 2; mt++)
#pragma unroll
            for (int nt = 0; nt < NT; nt++) {
                int r = m0 + warpm * 32 + mt * 16 + lg;
                int c = n0 + warpn * WN + nt * 8 + 2 * lt;
                float v00 = acc[mt][nt][0] * alpha;
                float v01 = acc[mt][nt][1] * alpha;
                float v10 = acc[mt][nt][2] * alpha;
                float v11 = acc[mt][nt][3] * alpha;
                if (Cn) {
                    *(uint32_t*)(Cn + (long)r * Nd + c)       = h2pack(v00, v01);
                    *(uint32_t*)(Cn + (long)(r + 8) * Nd + c) = h2pack(v10, v11);
                }
                if (Ctr) {
                    Ctr[(long)c * Md + r]           = __float2half(v00);
                    Ctr[(long)(c + 1) * Md + r]     = __float2half(v01);
                    Ctr[(long)c * Md + r + 8]       = __float2half(v10);
                    Ctr[(long)(c + 1) * Md + r + 8] = __float2half(v11);
                }
                if (Ctd) {
                    Ctd[(long)c * Md + r]           = __float2half(((r == c)         ? dg : 0.f) - v00);
                    Ctd[(long)(c + 1) * Md + r]     = __float2half(((r == c + 1)     ? dg : 0.f) - v01);
                    Ctd[(long)c * Md + r + 8]       = __float2half(((r + 8 == c)     ? dg : 0.f) - v10);
                    Ctd[(long)(c + 1) * Md + r + 8] = __float2half(((r + 8 == c + 1) ? dg : 0.f) - v11);
                }
            }
    }
}

// =============================================================================
// sim_softmax_h: Out(half) = softmax_row(A @ B^T), A [.][64] half, B [256][64].
// 64 rows/block; 8 warps 2m x 4n (warp 32x64). LDSM fragment loads.
// =============================================================================
__global__ __launch_bounds__(256, 2) void sim_softmax_h(
    const __half* __restrict__ Ag, const __half* __restrict__ Bg,
    __half* __restrict__ Og, long sA, long sB, long sO)
{
    __shared__ uint32_t As[64 * 16];
    __shared__ uint32_t Bs[256 * 16];
    __shared__ float redm[64 * 4];
    __shared__ float reds[64 * 4];

    const __half* A = Ag + (long)blockIdx.z * sA;
    const __half* B = Bg + (long)blockIdx.z * sB;
    __half*       O = Og + (long)blockIdx.z * sO;
    const int m0 = blockIdx.x * 64;
    const int tid = threadIdx.x;
    const int wid = tid >> 5, lane = tid & 31;
    const int warpm = wid & 1, warpn = wid >> 1;
    const int lg = lane >> 2, lt = lane & 3;

    const uint32_t asmb = (uint32_t)__cvta_generic_to_shared(&As[0]);
    const uint32_t bsmb = (uint32_t)__cvta_generic_to_shared(&Bs[0]);

    const int t4  = lane >> 3;
    const int agh = t4 >> 1;
    int aoff[2], asw[2];
#pragma unroll
    for (int mt = 0; mt < 2; mt++) {
        int rr = warpm * 32 + mt * 16 + (t4 & 1) * 8 + (lane & 7);
        aoff[mt] = rr * 64;
        asw[mt]  = (rr >> 1) & 3;
    }
    const int btb = t4 & 1;
    int boff[8], bsw[8];
#pragma unroll
    for (int nt = 0; nt < 8; nt++) {
        int n = warpn * 64 + nt * 8 + (lane & 7);
        boff[nt] = n * 64;
        bsw[nt]  = (n >> 1) & 3;
    }

    float acc[2][8][4];
#pragma unroll
    for (int mt = 0; mt < 2; mt++)
#pragma unroll
        for (int nt = 0; nt < 8; nt++)
#pragma unroll
            for (int i = 0; i < 4; i++) acc[mt][nt][i] = 0.f;

#pragma unroll
    for (int kt = 0; kt < 2; kt++) {
        const int k0 = kt * 32;
        {
            int row = tid >> 2, g = tid & 3;
            uint4 va = *(const uint4*)(A + (long)(m0 + row) * DHD + k0 + 8 * g);
            *(uint4*)&As[row * 16 + 4 * (g ^ ((row >> 1) & 3))] = va;
        }
#pragma unroll
        for (int j = 0; j < 4; j++) {
            int e = tid + j * 256;
            int n = e >> 2, g = e & 3;
            uint4 vb = *(const uint4*)(B + (long)n * DHD + k0 + 8 * g);
            *(uint4*)&Bs[n * 16 + 4 * (g ^ ((n >> 1) & 3))] = vb;
        }
        __syncthreads();

#pragma unroll
        for (int s = 0; s < 2; s++) {
            uint32_t af[2][4], bf[8][2];
#pragma unroll
            for (int mt = 0; mt < 2; mt++)
                ldsm4(af[mt], asmb + (uint32_t)(aoff[mt] +
                      ((((s << 1) | agh) ^ asw[mt]) << 4)));
#pragma unroll
            for (int nt = 0; nt < 8; nt++)
                ldsm2(bf[nt], bsmb + (uint32_t)(boff[nt] +
                      ((((s << 1) | btb) ^ bsw[nt]) << 4)));
#pragma unroll
            for (int mt = 0; mt < 2; mt++)
#pragma unroll
                for (int nt = 0; nt < 8; nt++)
                    mma_f16(acc[mt][nt], af[mt], bf[nt]);
        }
        __syncthreads();
    }

#pragma unroll
    for (int mt = 0; mt < 2; mt++)
#pragma unroll
        for (int half_ = 0; half_ < 2; half_++) {
            float mx = -1e30f;
#pragma unroll
            for (int nt = 0; nt < 8; nt++) {
                mx = fmaxf(mx, acc[mt][nt][half_ * 2]);
                mx = fmaxf(mx, acc[mt][nt][half_ * 2 + 1]);
            }
            mx = fmaxf(mx, __shfl_xor_sync(~0u, mx, 1));
            mx = fmaxf(mx, __shfl_xor_sync(~0u, mx, 2));
            int rloc = warpm * 32 + mt * 16 + half_ * 8 + lg;
            if (lt == 0) redm[rloc * 4 + warpn] = mx;
        }
    __syncthreads();
#pragma unroll
    for (int mt = 0; mt < 2; mt++)
#pragma unroll
        for (int half_ = 0; half_ < 2; half_++) {
            int rloc = warpm * 32 + mt * 16 + half_ * 8 + lg;
            float m4 = fmaxf(fmaxf(redm[rloc * 4 + 0], redm[rloc * 4 + 1]),
                             fmaxf(redm[rloc * 4 + 2], redm[rloc * 4 + 3]));
            float s = 0.f;
#pragma unroll
            for (int nt = 0; nt < 8; nt++) {
                float e0 = __expf(acc[mt][nt][half_ * 2]     - m4);
                float e1 = __expf(acc[mt][nt][half_ * 2 + 1] - m4);
                acc[mt][nt][half_ * 2]     = e0;
                acc[mt][nt][half_ * 2 + 1] = e1;
                s += e0 + e1;
            }
            s += __shfl_xor_sync(~0u, s, 1);
            s += __shfl_xor_sync(~0u, s, 2);
            if (lt == 0) reds[rloc * 4 + warpn] = s;
        }
    __syncthreads();
#pragma unroll
    for (int mt = 0; mt < 2; mt++)
#pragma unroll
        for (int half_ = 0; half_ < 2; half_++) {
            int rloc = warpm * 32 + mt * 16 + half_ * 8 + lg;
            float tot = reds[rloc * 4 + 0] + reds[rloc * 4 + 1]
                      + reds[rloc * 4 + 2] + reds[rloc * 4 + 3];
            float inv = 1.f / tot;
            int r = m0 + rloc;
#pragma unroll
            for (int nt = 0; nt < 8; nt++) {
                int c = warpn * 64 + nt * 8 + 2 * lt;
                *(uint32_t*)(O + (long)r * MM + c) =
                    h2pack(acc[mt][nt][half_ * 2] * inv, acc[mt][nt][half_ * 2 + 1] * inv);
            }
        }
}

// =============================================================================
// a3v_flash_h: a3vT = (softmax_row(ql @ k^T) @ v)^T, online softmax, half inputs.
// 32 rows/block, grid (MM/32, 1, BH). Output transposed [d][m] half.
// =============================================================================
__global__ __launch_bounds__(256, 2) void a3v_flash_h()
{
    __shared__ uint32_t Ks[64 * 32];   // K [tok][32 u32]; rows 0-31 reused as P [m][32 kp]
    __shared__ uint32_t Vs[32 * 64];   // V interleaved [kp_tok][d]
    __shared__ float redm[32 * 4];
    __shared__ float reds[32 * 4];

    const int bh = blockIdx.z;
    const int m0 = blockIdx.x * 32;
    const __half* ql = h_ql + (long)bh * MM * DHD;
    const __half* kg = h_k  + (long)bh * NN * DHD;
    const __half* vg = h_v  + (long)bh * NN * DHD;

    const int tid = threadIdx.x;
    const int wid = tid >> 5, lane = tid & 31;
    const int warpm = wid & 1, warpn = wid >> 1;
    const int lg = lane >> 2, lt = lane & 3;

    uint32_t aq[4][4];
    {
        int mr = m0 + warpm * 16;
#pragma unroll
        for (int s = 0; s < 4; s++) {
            int d0 = s * 16 + 2 * lt;
            aq[s][0] = *(const uint32_t*)(ql + (long)(mr + lg) * DHD + d0);
            aq[s][1] = *(const uint32_t*)(ql + (long)(mr + 8 + lg) * DHD + d0);
            aq[s][2] = *(const uint32_t*)(ql + (long)(mr + lg) * DHD + d0 + 8);
            aq[s][3] = *(const uint32_t*)(ql + (long)(mr + 8 + lg) * DHD + d0 + 8);
        }
    }

    float oacc[2][4];
#pragma unroll
    for (int nt = 0; nt < 2; nt++)
#pragma unroll
        for (int i = 0; i < 4; i++) oacc[nt][i] = 0.f;
    float mprev[2] = {-1e30f, -1e30f};
    float lsum[2]  = {0.f, 0.f};

    uint4 kpre[2];
    uint2 vpa[2], vpb[2];
#pragma unroll
    for (int j = 0; j < 2; j++) {
        int e = tid + j * 256;
        { int tok = e >> 3, g = e & 7;
          kpre[j] = *(const uint4*)(kg + (long)tok * DHD + 8 * g); }
        { int kpt = e >> 4, d4 = (e & 15) << 2;
          vpa[j] = *(const uint2*)(vg + (long)(2 * kpt) * DHD + d4);
          vpb[j] = *(const uint2*)(vg + (long)(2 * kpt + 1) * DHD + d4); }
    }

    for (int ch = 0; ch < NCH; ch++) {
        __syncthreads();
#pragma unroll
        for (int j = 0; j < 2; j++) {
            int e = tid + j * 256;
            { int tok = e >> 3, g = e & 7;
              *(uint4*)&Ks[tok * 32 + 4 * (g ^ (tok & 7))] = kpre[j]; }
            { int kpt = e >> 4, d4 = (e & 15) << 2;
              uint4 w;
              w.x = prmtb(vpa[j].x, vpb[j].x, 0x5410);
              w.y = prmtb(vpa[j].x, vpb[j].x, 0x7632);
              w.z = prmtb(vpa[j].y, vpb[j].y, 0x5410);
              w.w = prmtb(vpa[j].y, vpb[j].y, 0x7632);
              *(uint4*)&Vs[kpt * 64 + (d4 ^ ((kpt & 3) << 3))] = w; }
        }
        if (ch + 1 < NCH) {
            const __half* kc = kg + (long)(ch + 1) * SN * DHD;
            const __half* vc = vg + (long)(ch + 1) * SN * DHD;
#pragma unroll
            for (int j = 0; j < 2; j++) {
                int e = tid + j * 256;
                { int tok = e >> 3, g = e & 7;
                  kpre[j] = *(const uint4*)(kc + (long)tok * DHD + 8 * g); }
                { int kpt = e >> 4, d4 = (e & 15) << 2;
                  vpa[j] = *(const uint2*)(vc + (long)(2 * kpt) * DHD + d4);
                  vpb[j] = *(const uint2*)(vc + (long)(2 * kpt + 1) * DHD + d4); }
            }
        }
        __syncthreads();

        float sacc[2][4];
#pragma unroll
        for (int nt = 0; nt < 2; nt++)
#pragma unroll
            for (int i = 0; i < 4; i++) sacc[nt][i] = 0.f;
#pragma unroll
        for (int s = 0; s < 4; s++) {
            uint32_t bf[2][2];
#pragma unroll
            for (int nt = 0; nt < 2; nt++) {
                int c = warpn * 16 + nt * 8 + lg;
                bf[nt][0] = Ks[c * 32 + lt + 4 * ((2 * s) ^ (c & 7))];
                bf[nt][1] = Ks[c * 32 + lt + 4 * ((2 * s + 1) ^ (c & 7))];
            }
#pragma unroll
            for (int nt = 0; nt < 2; nt++)
                mma_f16(sacc[nt], aq[s], bf[nt]);
        }

#pragma unroll
        for (int half_ = 0; half_ < 2; half_++) {
            float mx = -1e30f;
#pragma unroll
            for (int nt = 0; nt < 2; nt++) {
                mx = fmaxf(mx, sacc[nt][half_ * 2]);
                mx = fmaxf(mx, sacc[nt][half_ * 2 + 1]);
            }
            mx = fmaxf(mx, __shfl_xor_sync(~0u, mx, 1));
            mx = fmaxf(mx, __shfl_xor_sync(~0u, mx, 2));
            if (lt == 0) redm[(warpm * 16 + half_ * 8 + lg) * 4 + warpn] = mx;
        }
        __syncthreads();

        float scale[2];
#pragma unroll
        for (int half_ = 0; half_ < 2; half_++) {
            int row = warpm * 16 + half_ * 8 + lg;
            float mch = fmaxf(fmaxf(redm[row * 4 + 0], redm[row * 4 + 1]),
                              fmaxf(redm[row * 4 + 2], redm[row * 4 + 3]));
            float mnew = fmaxf(mprev[half_], mch);
            scale[half_] = __expf(mprev[half_] - mnew);
            mprev[half_] = mnew;
            float s = 0.f;
#pragma unroll
            for (int nt = 0; nt < 2; nt++) {
                float e0 = __expf(sacc[nt][half_ * 2]     - mnew);
                float e1 = __expf(sacc[nt][half_ * 2 + 1] - mnew);
                sacc[nt][half_ * 2]     = e0;
                sacc[nt][half_ * 2 + 1] = e1;
                s += e0 + e1;
            }
            s += __shfl_xor_sync(~0u, s, 1);
            s += __shfl_xor_sync(~0u, s, 2);
            if (lt == 0) reds[row * 4 + warpn] = s;
#pragma unroll
            for (int nt = 0; nt < 2; nt++) {
                int kp = warpn * 8 + nt * 4 + lt;
                Ks[row * 32 + (kp ^ ((row & 7) << 2))] =
                    h2pack(sacc[nt][half_ * 2], sacc[nt][half_ * 2 + 1]);
            }
        }
        __syncthreads();

#pragma unroll
        for (int half_ = 0; half_ < 2; half_++) {
            int row = warpm * 16 + half_ * 8 + lg;
            lsum[half_] = lsum[half_] * scale[half_]
                        + reds[row * 4 + 0] + reds[row * 4 + 1]
                        + reds[row * 4 + 2] + reds[row * 4 + 3];
        }
#pragma unroll
        for (int nt = 0; nt < 2; nt++) {
            oacc[nt][0] *= scale[0]; oacc[nt][1] *= scale[0];
            oacc[nt][2] *= scale[1]; oacc[nt][3] *= scale[1];
        }

#pragma unroll
        for (int s = 0; s < 4; s++) {
            const int kp0 = s * 8;
            int mr = warpm * 16 + lg;
            uint32_t af[4];
            af[0] = Ks[mr * 32 + ((kp0 + lt) ^ ((mr & 7) << 2))];
            af[1] = Ks[(mr + 8) * 32 + ((kp0 + lt) ^ (((mr + 8) & 7) << 2))];
            af[2] = Ks[mr * 32 + ((kp0 + lt + 4) ^ ((mr & 7) << 2))];
            af[3] = Ks[(mr + 8) * 32 + ((kp0 + lt + 4) ^ (((mr + 8) & 7) << 2))];
            uint32_t bf[2][2];
#pragma unroll
            for (int nt = 0; nt < 2; nt++) {
                int d = warpn * 16 + nt * 8 + lg;
                bf[nt][0] = Vs[(kp0 + lt) * 64 + (d ^ (lt << 3))];
                bf[nt][1] = Vs[(kp0 + lt + 4) * 64 + (d ^ (lt << 3))];
            }
#pragma unroll
            for (int nt = 0; nt < 2; nt++)
                mma_f16(oacc[nt], af, bf[nt]);
        }
    }

    __half* outb = h_a3vT + (long)bh * DHD * MM;
#pragma unroll
    for (int half_ = 0; half_ < 2; half_++) {
        float inv = 1.f / lsum[half_];
        int r = m0 + warpm * 16 + half_ * 8 + lg;
#pragma unroll
        for (int nt = 0; nt < 2; nt++) {
            int d = warpn * 16 + nt * 8 + 2 * lt;
            outb[(long)d * MM + r]       = __float2half(oacc[nt][half_ * 2] * inv);
            outb[(long)(d + 1) * MM + r] = __float2half(oacc[nt][half_ * 2 + 1] * inv);
        }
    }
}

// ---------------- LayerNorm (half out) -----------------------------------------
__global__ __launch_bounds__(256) void ln_kernel(
    const float* __restrict__ x, const float* __restrict__ w, const float* __restrict__ b)
{
    long row = blockIdx.x;
    const float* xr = x + row * DD;
    int t = threadIdx.x;
    float v0 = xr[t], v1 = xr[t + 256];
    __shared__ float red[32];

    float s = v0 + v1;
    for (int o = 16; o > 0; o >>= 1) s += __shfl_xor_sync(~0u, s, o);
    if ((t & 31) == 0) red[t >> 5] = s;
    __syncthreads();
    if (t < 32) {
        float ss = (t < 8) ? red[t] : 0.f;
        for (int o = 4; o > 0; o >>= 1) ss += __shfl_xor_sync(~0u, ss, o);
        if (t == 0) red[0] = ss;
    }
    __syncthreads();
    float mu = red[0] * (1.f / DD);
    __syncthreads();

    float d0 = v0 - mu, d1 = v1 - mu;
    float q = d0 * d0 + d1 * d1;
    for (int o = 16; o > 0; o >>= 1) q += __shfl_xor_sync(~0u, q, o);
    if ((t & 31) == 0) red[t >> 5] = q;
    __syncthreads();
    if (t < 32) {
        float ss = (t < 8) ? red[t] : 0.f;
        for (int o = 4; o > 0; o >>= 1) ss += __shfl_xor_sync(~0u, ss, o);
        if (t == 0) red[0] = ss;
    }
    __syncthreads();
    float inv = rsqrtf(red[0] * (1.f / DD) + 1e-5f);
    h_xn[row * DD + t]       = __float2half(d0 * inv * w[t]       + b[t]);
    h_xn[row * DD + t + 256] = __float2half(d1 * inv * w[t + 256] + b[t + 256]);
}

// ---------------- weight conversion (transpose to [N][K] half) ----------------
__global__ void conv_weights(const float* __restrict__ wq, const float* __restrict__ wo)
{
    int i = blockIdx.x * 256 + threadIdx.x;           // 3*DD*DD
    {
        int n = i / DD, k2 = i % DD;
        h_wqkvT[i] = __float2half(wq[(long)k2 * (3 * DD) + n]);
    }
    if (i < DD * DD) {
        int n = i / DD, k2 = i % DD;
        h_woutT[i] = __float2half(wo[(long)k2 * DD + n]);
    }
}

// ---------------- landmarks (vectorized: 8 halves per thread) ------------------
__global__ void landmarks()
{
    long i = (long)blockIdx.x * 256 + threadIdx.x;    // BH*MM*8 granules
    int dg = i & 7; long r = i >> 3;
    int m = r % MM;  int bh = r / MM;
    long base = ((long)bh * NN + m * LLm) * DHD + dg * 8;
    float sq[8], sk[8];
#pragma unroll
    for (int e = 0; e < 8; e++) { sq[e] = 0.f; sk[e] = 0.f; }
#pragma unroll
    for (int u = 0; u < LLm; u++) {
        uint4 vq = *(const uint4*)(h_q + base + u * DHD);
        uint4 vk = *(const uint4*)(h_k + base + u * DHD);
        const uint32_t* q4 = &vq.x;
        const uint32_t* k4 = &vk.x;
#pragma unroll
        for (int p = 0; p < 4; p++) {
            float2 fq = __half22float2(*(const __half2*)&q4[p]);
            float2 fk = __half22float2(*(const __half2*)&k4[p]);
            sq[2 * p] += fq.x; sq[2 * p + 1] += fq.y;
            sk[2 * p] += fk.x; sk[2 * p + 1] += fk.y;
        }
    }
    uint4 oq, ok;
    uint32_t* oq4 = &oq.x; uint32_t* ok4 = &ok.x;
#pragma unroll
    for (int p = 0; p < 4; p++) {
        oq4[p] = h2pack(sq[2 * p] * (1.f / LLm), sq[2 * p + 1] * (1.f / LLm));
        ok4[p] = h2pack(sk[2 * p] * (1.f / LLm), sk[2 * p + 1] * (1.f / LLm));
    }
    long out = ((long)bh * MM + m) * DHD + dg * 8;
    *(uint4*)(h_ql + out) = oq;
    *(uint4*)(h_kl + out) = ok;
}

// ---------------- pinv init ----------------------------------------------------
__global__ void init_colmax() { g_colmax = 0.f; }

__global__ __launch_bounds__(256) void colmax_kernel()
{
    int bh = blockIdx.x, j = threadIdx.x;
    const __half* a = h_a2 + (long)bh * MM * MM;
    float s = 0.f;
    for (int i = 0; i < MM; i++) s += __half2float(a[i * MM + j]);
    __shared__ float red[32];
    float m = s;
    for (int o = 16; o > 0; o >>= 1) m = fmaxf(m, __shfl_xor_sync(~0u, m, o));
    if ((j & 31) == 0) red[j >> 5] = m;
    __syncthreads();
    if (j < 32) {
        float m2 = (j < 8) ? red[j] : -1e30f;
        for (int o = 4; o > 0; o >>= 1) m2 = fmaxf(m2, __shfl_xor_sync(~0u, m2, o));
        if (j == 0) atomicMax((int*)&g_colmax, __float_as_int(m2));
    }
}

__global__ void zinit()
{
    long i = (long)blockIdx.x * 256 + threadIdx.x;    // BH*MM*MM
    int col = i % MM; long r = i / MM;
    int row = r % MM; int bh = r / MM;
    float inv = 1.f / g_colmax;
    h_zT[i] = __float2half(__half2float(h_a2[i]) * inv);
    h_z [i] = __float2half(__half2float(h_a2[((long)bh * MM + col) * MM + row]) * inv);
}

// ---------------- fused reshape + depthwise conv (fp32 in, half att out) -------
__global__ void att_conv(const float* __restrict__ rw)
{
    long i = (long)blockIdx.x * 256 + threadIdx.x;
    int dq = i % 16; long r = i / 16;
    int h = r % HH;  long r2 = r / HH;
    int n = r2 % NN; int b = r2 / NN;
    long bhbase = (long)(b * HH + h) * NN;
    const float4* v4 = (const float4*)(g_vf + bhbase * DHD);
    float4 a = *(const float4*)(g_o + (bhbase + n) * DHD + dq * 4);
#pragma unroll
    for (int j = 0; j < KC; j++) {
        int tt = n + j - KC / 2;
        if (tt >= 0 && tt < NN) {
            float w = rw[h * KC + j];
            float4 vv = v4[(long)tt * 16 + dq];
            a.x += w * vv.x; a.y += w * vv.y; a.z += w * vv.z; a.w += w * vv.w;
        }
    }
    uint2 w2;
    w2.x = h2pack(a.x, a.y);
    w2.y = h2pack(a.z, a.w);
    *(uint2*)&h_att[((long)(b * NN + n)) * DD + h * DHD + dq * 4] = w2;
}

// ---------------- host orchestration -------------------------------------------
extern "C" void kernel_launch(void* const* d_in, const int* in_sizes, int n_in,
                              void* d_out, int out_size)
{
    const float* x      = (const float*)d_in[0];
    const float* norm_w = (const float*)d_in[1];
    const float* norm_b = (const float*)d_in[2];
    const float* w_qkv  = (const float*)d_in[3];
    const float* w_out  = (const float*)d_in[4];
    const float* b_out  = (const float*)d_in[5];
    const float* res_w  = (const float*)d_in[6];
    float* y = (float*)d_out;

    __half *p_xn, *p_wqkvT, *p_woutT, *p_q, *p_k, *p_v, *p_ql, *p_kl;
    __half *p_a1, *p_a2, *p_z, *p_zT, *p_z2, *p_z2T, *p_xz, *p_t1T, *p_t2T, *p_a3vT, *p_WT, *p_att;
    float *p_vf, *p_o;
    cudaGetSymbolAddress((void**)&p_xn,   h_xn);
    cudaGetSymbolAddress((void**)&p_wqkvT,h_wqkvT);
    cudaGetSymbolAddress((void**)&p_woutT,h_woutT);
    cudaGetSymbolAddress((void**)&p_q,    h_q);
    cudaGetSymbolAddress((void**)&p_k,    h_k);
    cudaGetSymbolAddress((void**)&p_v,    h_v);
    cudaGetSymbolAddress((void**)&p_ql,   h_ql);
    cudaGetSymbolAddress((void**)&p_kl,   h_kl);
    cudaGetSymbolAddress((void**)&p_a1,   h_a1);
    cudaGetSymbolAddress((void**)&p_a2,   h_a2);
    cudaGetSymbolAddress((void**)&p_z,    h_z);
    cudaGetSymbolAddress((void**)&p_zT,   h_zT);
    cudaGetSymbolAddress((void**)&p_z2,   h_z2);
    cudaGetSymbolAddress((void**)&p_z2T,  h_z2T);
    cudaGetSymbolAddress((void**)&p_xz,   h_xz);
    cudaGetSymbolAddress((void**)&p_t1T,  h_t1T);
    cudaGetSymbolAddress((void**)&p_t2T,  h_t2T);
    cudaGetSymbolAddress((void**)&p_a3vT, h_a3vT);
    cudaGetSymbolAddress((void**)&p_WT,   h_WT);
    cudaGetSymbolAddress((void**)&p_att,  h_att);
    cudaGetSymbolAddress((void**)&p_vf,   g_vf);
    cudaGetSymbolAddress((void**)&p_o,    g_o);

    const long MM2 = (long)MM * MM;
    void* nul = nullptr;

    // 1. LayerNorm -> h_xn; weight conversion
    ln_kernel<<<BB * NN, 256>>>(x, norm_w, norm_b);
    conv_weights<<<(3 * DD * DD) / 256, 256>>>(w_qkv, w_out);
    // 2. qkv = xn @ wqkvT^T with fused split
    gemm_h<128, 1><<<dim3((3 * DD) / 128, (BB * NN) / 128, 1), 256>>>(
        p_xn, p_wqkvT, p_q, p_k, p_v, p_vf,
        BB * NN, 3 * DD, DD, 0, 0, 0, 1.f, 0.f);
    // 3. landmarks
    landmarks<<<(BH * MM * 8) / 256, 256>>>();
    // 4. a2 = softmax(ql @ kl^T)
    sim_softmax_h<<<dim3(MM / 64, 1, BH), 256>>>(
        p_ql, p_kl, p_a2, (long)MM * DHD, (long)MM * DHD, MM2);
    // 5. pinv init
    init_colmax<<<1, 1>>>();
    colmax_kernel<<<BH, 256>>>();
    zinit<<<(int)((long)BH * MM * MM / 256), 256>>>();
    // 6. Newton-Schulz
    __half *zin = p_z, *zinT = p_zT, *zout = p_z2, *zoutT = p_z2T;
    for (int it = 0; it < NITER; it++) {
        gemm_h<64, 3><<<dim3(MM / 64, MM / 128, BH), 256>>>(
            p_a2, zinT, p_xz, nul, p_t1T, nul, MM, MM, MM, MM2, MM2, MM2, 1.f, 7.f);
        gemm_h<64, 3><<<dim3(MM / 64, MM / 128, BH), 256>>>(
            p_xz, p_t1T, nul, nul, p_t2T, nul, MM, MM, MM, MM2, MM2, MM2, 1.f, 15.f);
        gemm_h<64, 3><<<dim3(MM / 64, MM / 128, BH), 256>>>(
            p_xz, p_t2T, nul, nul, p_t1T, nul, MM, MM, MM, MM2, MM2, MM2, 1.f, 13.f);
        gemm_h<64, 3><<<dim3(MM / 64, MM / 128, BH), 256>>>(
            zin, p_t1T, zout, zoutT, nul, nul, MM, MM, MM, MM2, MM2, MM2, 0.25f, 0.f);
        __half* t;
        t = zin;  zin  = zout;  zout  = t;
        t = zinT; zinT = zoutT; zoutT = t;
    }
    // 7. a1 = softmax(q @ kl^T)
    sim_softmax_h<<<dim3(NN / 64, 1, BH), 256>>>(
        p_q, p_kl, p_a1, (long)NN * DHD, (long)MM * DHD, (long)NN * MM);
    // 8. a3vT = (softmax(ql @ k^T) @ v)^T  (flash)
    a3v_flash_h<<<dim3(MM / 32, 1, BH), 256>>>();
    // 9. WT = (z @ a3v)^T
    gemm_h<64, 3><<<dim3(1, MM / 128, BH), 256>>>(
        zin, p_a3vT, nul, p_WT, nul, nul, MM, DHD, MM,
        MM2, (long)DHD * MM, (long)DHD * MM, 1.f, 0.f);
    // 10. o = a1 @ W  (fp32 out)
    gemm_h<64, 0><<<dim3(1, NN / 128, BH), 256>>>(
        p_a1, p_WT, p_o, nul, nul, nul, NN, DHD, MM,
        (long)NN * MM, (long)DHD * MM, (long)NN * DHD, 1.f, 0.f);
    // 11. att = reshape(o) + conv(v)  (half out)
    att_conv<<<(BB * NN * HH * 16) / 256, 256>>>(res_w);
    // 12. y = att @ w_out + x + b_out
    gemm_h<128, 2><<<dim3(DD / 128, (BB * NN) / 128, 1), 256>>>(
        p_att, p_woutT, y, (void*)x, (void*)b_out, nul,
        BB * NN, DD, DD, 0, 0, 0, 1.f, 0.f);
}

// round 12
// speedup vs baseline: 5.0559x; 1.0314x over previous
#include <cuda_runtime.h>
#include <cuda_fp16.h>
#include <cstdint>

#define BB 4
#define NN 4096
#define DD 512
#define HH 8
#define DHD 64
#define MM 256
#define LLm 16
#define NITER 6
#define KC 33
#define BH (BB*HH)
#define SN2 128
#define NCH2 (NN/SN2)

// ---------------- scratch (half for MMA operands, fp32 where needed) -----------
__device__ __align__(16) __half h_xn   [BB*NN*DD];
__device__ __align__(16) __half h_wqkvT[3*DD*DD];     // [1536][512]
__device__ __align__(16) __half h_woutT[DD*DD];       // [512][512]
__device__ __align__(16) __half h_q  [BH*NN*DHD];
__device__ __align__(16) __half h_k  [BH*NN*DHD];
__device__ __align__(16) __half h_v  [BH*NN*DHD];
__device__ __align__(16) __half h_o  [BH*NN*DHD];
__device__ __align__(16) __half h_ql [BH*MM*DHD];
__device__ __align__(16) __half h_kl [BH*MM*DHD];
__device__ __align__(16) __half h_a1 [(long)BH*NN*MM];
__device__ __align__(16) __half h_a2 [BH*MM*MM];
__device__ __align__(16) __half h_z  [BH*MM*MM];
__device__ __align__(16) __half h_zT [BH*MM*MM];
__device__ __align__(16) __half h_z2 [BH*MM*MM];
__device__ __align__(16) __half h_z2T[BH*MM*MM];
__device__ __align__(16) __half h_xz [BH*MM*MM];
__device__ __align__(16) __half h_t1T[BH*MM*MM];
__device__ __align__(16) __half h_t2T[BH*MM*MM];
__device__ __align__(16) __half h_a3vT[BH*DHD*MM];    // [d][m]
__device__ __align__(16) __half h_WT [BH*DHD*MM];     // [d][m]
__device__ __align__(16) __half h_att[BB*NN*DD];
__device__ float g_colmax;

// ---------------- helpers ------------------------------------------------------
__device__ __forceinline__ uint32_t h2pack(float a, float b) {
    __half2 h = __floats2half2_rn(a, b);
    return *reinterpret_cast<uint32_t*>(&h);
}
__device__ __forceinline__ uint32_t prmtb(uint32_t a, uint32_t b, uint32_t sel) {
    uint32_t d;
    asm("prmt.b32 %0, %1, %2, %3;" : "=r"(d) : "r"(a), "r"(b), "r"(sel));
    return d;
}
__device__ __forceinline__ void mma_f16(float* c, const uint32_t* a, const uint32_t* b) {
    asm volatile(
        "mma.sync.aligned.m16n8k16.row.col.f32.f16.f16.f32 "
        "{%0,%1,%2,%3}, {%4,%5,%6,%7}, {%8,%9}, {%0,%1,%2,%3};"
        : "+f"(c[0]), "+f"(c[1]), "+f"(c[2]), "+f"(c[3])
        : "r"(a[0]), "r"(a[1]), "r"(a[2]), "r"(a[3]), "r"(b[0]), "r"(b[1]));
}
__device__ __forceinline__ void ldsm4(uint32_t* r, uint32_t saddr) {
    asm volatile("ldmatrix.sync.aligned.m8n8.x4.shared.b16 {%0,%1,%2,%3}, [%4];"
        : "=r"(r[0]), "=r"(r[1]), "=r"(r[2]), "=r"(r[3]) : "r"(saddr));
}
__device__ __forceinline__ void ldsm2(uint32_t* r, uint32_t saddr) {
    asm volatile("ldmatrix.sync.aligned.m8n8.x2.shared.b16 {%0,%1}, [%2];"
        : "=r"(r[0]), "=r"(r[1]) : "r"(saddr));
}
__device__ __forceinline__ void cpa16(uint32_t dst, const void* src) {
    asm volatile("cp.async.cg.shared.global [%0], [%1], 16;" :: "r"(dst), "l"(src));
}
#define CP_COMMIT() asm volatile("cp.async.commit_group;")

// =============================================================================
// gemm_h: C = alpha * A @ B^T, A [M][K] half, B [N][K] half (both k-contig).
// BM=128, BN template (64/128), BK=32. cp.async double-buffered, LDSM fragment
// loads, 2 blocks/SM. 8 warps 4m x 2n; warp tile 32 x (BN/2).
// MODE 0: p0 = float* C (normal, stride Nd), * alpha
// MODE 1: qkv split -> p0=h_q(x0.125) p1=h_k p2=h_v (half)
// MODE 2: p0=float* y = acc + x(p1) + bout(p2)
// MODE 3: p0=half* Cn(normal, alpha*acc), p1=half* CtRaw(transposed, alpha*acc),
//         p2=half* CtDiag(transposed, dg*I - acc).
// =============================================================================
template<int BN, int MODE>
__global__ __launch_bounds__(256, 2) void gemm_h(
    const __half* __restrict__ Ag, const __half* __restrict__ Bg,
    void* __restrict__ p0, void* __restrict__ p1, void* __restrict__ p2,
    int Md, int Nd, int Kd, long sA, long sB, long sC,
    float alpha, float dg)
{
    constexpr int NT = BN / 16;
    constexpr int WN = BN / 2;
    constexpr int NBJ = BN / 64;

    __shared__ uint32_t As[2][128 * 16];
    __shared__ uint32_t Bs[2][BN * 16];

    const __half* A = Ag + (long)blockIdx.z * sA;
    const __half* Bp = Bg + (long)blockIdx.z * sB;
    const int m0 = blockIdx.y * 128;
    const int n0 = blockIdx.x * BN;
    const int tid = threadIdx.x;
    const int wid = tid >> 5, lane = tid & 31;
    const int warpm = wid & 3, warpn = wid >> 2;
    const int lg = lane >> 2, lt = lane & 3;

    const uint32_t asmb = (uint32_t)__cvta_generic_to_shared(&As[0][0]);
    const uint32_t bsmb = (uint32_t)__cvta_generic_to_shared(&Bs[0][0]);

    const int t4  = lane >> 3;
    const int agh = t4 >> 1;
    int aoff[2], asw[2];
#pragma unroll
    for (int mt = 0; mt < 2; mt++) {
        int rr = warpm * 32 + mt * 16 + (t4 & 1) * 8 + (lane & 7);
        aoff[mt] = rr * 64;
        asw[mt]  = (rr >> 1) & 3;
    }
    const int btb = t4 & 1;
    int boff[NT], bsw[NT];
#pragma unroll
    for (int nt = 0; nt < NT; nt++) {
        int n = warpn * WN + nt * 8 + (lane & 7);
        boff[nt] = n * 64;
        bsw[nt]  = (n >> 1) & 3;
    }

    float acc[2][NT][4];
#pragma unroll
    for (int mt = 0; mt < 2; mt++)
#pragma unroll
        for (int nt = 0; nt < NT; nt++)
#pragma unroll
            for (int i = 0; i < 4; i++) acc[mt][nt][i] = 0.f;

    const int nk = Kd >> 5;

#define LOADT(kt, st) do {                                                      \
    const int k0_ = (kt) << 5;                                                  \
    _Pragma("unroll")                                                           \
    for (int j = 0; j < 2; j++) {                                               \
        int e = tid + j * 256;                                                  \
        int row = e >> 2, g = e & 3;                                            \
        uint32_t d = asmb + (uint32_t)(((st) * 2048 + row * 16 +                \
                     4 * (g ^ ((row >> 1) & 3))) << 2);                         \
        cpa16(d, A + (long)(m0 + row) * Kd + k0_ + 8 * g);                      \
    }                                                                           \
    _Pragma("unroll")                                                           \
    for (int j = 0; j < NBJ; j++) {                                             \
        int e = tid + j * 256;                                                  \
        int n = e >> 2, g = e & 3;                                              \
        uint32_t d = bsmb + (uint32_t)(((st) * (BN * 16) + n * 16 +             \
                     4 * (g ^ ((n >> 1) & 3))) << 2);                           \
        cpa16(d, Bp + (long)(n0 + n) * Kd + k0_ + 8 * g);                       \
    }                                                                           \
    CP_COMMIT();                                                                \
} while (0)

    LOADT(0, 0);

    for (int kt = 0; kt < nk; kt++) {
        const int st = kt & 1;
        if (kt + 1 < nk) {
            LOADT(kt + 1, st ^ 1);
            asm volatile("cp.async.wait_group 1;");
        } else {
            asm volatile("cp.async.wait_group 0;");
        }
        __syncthreads();

        const uint32_t a_base = asmb + (uint32_t)((st * 2048) << 2);
        const uint32_t b_base = bsmb + (uint32_t)((st * (BN * 16)) << 2);
#pragma unroll
        for (int s = 0; s < 2; s++) {
            uint32_t af[2][4], bf[NT][2];
#pragma unroll
            for (int mt = 0; mt < 2; mt++)
                ldsm4(af[mt], a_base + (uint32_t)((aoff[mt] +
                      ((((s << 1) | agh) ^ asw[mt]) << 4))));
#pragma unroll
            for (int nt = 0; nt < NT; nt++)
                ldsm2(bf[nt], b_base + (uint32_t)((boff[nt] +
                      ((((s << 1) | btb) ^ bsw[nt]) << 4))));
#pragma unroll
            for (int mt = 0; mt < 2; mt++)
#pragma unroll
                for (int nt = 0; nt < NT; nt++)
                    mma_f16(acc[mt][nt], af[mt], bf[nt]);
        }
        __syncthreads();
    }
#undef LOADT

    // ---- epilogues ----
    if (MODE == 0) {
        float* C = (float*)p0 + (long)blockIdx.z * sC;
#pragma unroll
        for (int mt = 0; mt < 2; mt++)
#pragma unroll
            for (int nt = 0; nt < NT; nt++) {
                int r = m0 + warpm * 32 + mt * 16 + lg;
                int c = n0 + warpn * WN + nt * 8 + 2 * lt;
                *(float2*)(C + (long)r * Nd + c) =
                    make_float2(acc[mt][nt][0] * alpha, acc[mt][nt][1] * alpha);
                *(float2*)(C + (long)(r + 8) * Nd + c) =
                    make_float2(acc[mt][nt][2] * alpha, acc[mt][nt][3] * alpha);
            }
    } else if (MODE == 1) {
        __half* qh = (__half*)p0; __half* kh = (__half*)p1; __half* vh = (__half*)p2;
#pragma unroll
        for (int mt = 0; mt < 2; mt++)
#pragma unroll
            for (int nt = 0; nt < NT; nt++) {
                int c = n0 + warpn * WN + nt * 8 + 2 * lt;
                int which = c >> 9, cc = c & 511;
                int h = cc >> 6, d = cc & 63;
                float sc = (which == 0) ? 0.125f : 1.f;
                __half* dsth = (which == 0) ? qh : (which == 1) ? kh : vh;
#pragma unroll
                for (int half_ = 0; half_ < 2; half_++) {
                    int m = m0 + warpm * 32 + mt * 16 + half_ * 8 + lg;
                    int b = m >> 12, n = m & 4095;
                    long dst = ((long)(b * HH + h) * NN + n) * DHD + d;
                    *(uint32_t*)(dsth + dst) = h2pack(acc[mt][nt][half_ * 2] * sc,
                                                      acc[mt][nt][half_ * 2 + 1] * sc);
                }
            }
    } else if (MODE == 2) {
        float* y = (float*)p0;
        const float* xp = (const float*)p1;
        const float* bp = (const float*)p2;
#pragma unroll
        for (int mt = 0; mt < 2; mt++)
#pragma unroll
            for (int nt = 0; nt < NT; nt++) {
                int r = m0 + warpm * 32 + mt * 16 + lg;
                int c = n0 + warpn * WN + nt * 8 + 2 * lt;
                float b0 = bp[c], b1 = bp[c + 1];
                float2 x0 = *(const float2*)(xp + (long)r * Nd + c);
                float2 x1 = *(const float2*)(xp + (long)(r + 8) * Nd + c);
                *(float2*)(y + (long)r * Nd + c) =
                    make_float2(acc[mt][nt][0] + x0.x + b0, acc[mt][nt][1] + x0.y + b1);
                *(float2*)(y + (long)(r + 8) * Nd + c) =
                    make_float2(acc[mt][nt][2] + x1.x + b0, acc[mt][nt][3] + x1.y + b1);
            }
    } else {
        __half* Cn = p0 ? (__half*)p0 + (long)blockIdx.z * sC : nullptr;
        __half* Ctr = p1 ? (__half*)p1 + (long)blockIdx.z * sC : nullptr;
        __half* Ctd = p2 ? (__half*)p2 + (long)blockIdx.z * sC : nullptr;
#pragma unroll
        for (int mt = 0; mt < 2; mt++)
#pragma unroll
            for (int nt = 0; nt < NT; nt++) {
                int r = m0 + warpm * 32 + mt * 16 + lg;
                int c = n0 + warpn * WN + nt * 8 + 2 * lt;
                float v00 = acc[mt][nt][0] * alpha;
                float v01 = acc[mt][nt][1] * alpha;
                float v10 = acc[mt][nt][2] * alpha;
                float v11 = acc[mt][nt][3] * alpha;
                if (Cn) {
                    *(uint32_t*)(Cn + (long)r * Nd + c)       = h2pack(v00, v01);
                    *(uint32_t*)(Cn + (long)(r + 8) * Nd + c) = h2pack(v10, v11);
                }
                if (Ctr) {
                    Ctr[(long)c * Md + r]           = __float2half(v00);
                    Ctr[(long)(c + 1) * Md + r]     = __float2half(v01);
                    Ctr[(long)c * Md + r + 8]       = __float2half(v10);
                    Ctr[(long)(c + 1) * Md + r + 8] = __float2half(v11);
                }
                if (Ctd) {
                    Ctd[(long)c * Md + r]           = __float2half(((r == c)         ? dg : 0.f) - v00);
                    Ctd[(long)(c + 1) * Md + r]     = __float2half(((r == c + 1)     ? dg : 0.f) - v01);
                    Ctd[(long)c * Md + r + 8]       = __float2half(((r + 8 == c)     ? dg : 0.f) - v10);
                    Ctd[(long)(c + 1) * Md + r + 8] = __float2half(((r + 8 == c + 1) ? dg : 0.f) - v11);
                }
            }
    }
}

// =============================================================================
// sim_softmax_h: Out(half) = softmax_row(A @ B^T), A [.][64] half, B [256][64].
// 64 rows/block; 8 warps 2m x 4n (warp 32x64). LDSM fragment loads.
// =============================================================================
__global__ __launch_bounds__(256, 2) void sim_softmax_h(
    const __half* __restrict__ Ag, const __half* __restrict__ Bg,
    __half* __restrict__ Og, long sA, long sB, long sO)
{
    __shared__ uint32_t As[64 * 16];
    __shared__ uint32_t Bs[256 * 16];
    __shared__ float redm[64 * 4];
    __shared__ float reds[64 * 4];

    const __half* A = Ag + (long)blockIdx.z * sA;
    const __half* B = Bg + (long)blockIdx.z * sB;
    __half*       O = Og + (long)blockIdx.z * sO;
    const int m0 = blockIdx.x * 64;
    const int tid = threadIdx.x;
    const int wid = tid >> 5, lane = tid & 31;
    const int warpm = wid & 1, warpn = wid >> 1;
    const int lg = lane >> 2, lt = lane & 3;

    const uint32_t asmb = (uint32_t)__cvta_generic_to_shared(&As[0]);
    const uint32_t bsmb = (uint32_t)__cvta_generic_to_shared(&Bs[0]);

    const int t4  = lane >> 3;
    const int agh = t4 >> 1;
    int aoff[2], asw[2];
#pragma unroll
    for (int mt = 0; mt < 2; mt++) {
        int rr = warpm * 32 + mt * 16 + (t4 & 1) * 8 + (lane & 7);
        aoff[mt] = rr * 64;
        asw[mt]  = (rr >> 1) & 3;
    }
    const int btb = t4 & 1;
    int boff[8], bsw[8];
#pragma unroll
    for (int nt = 0; nt < 8; nt++) {
        int n = warpn * 64 + nt * 8 + (lane & 7);
        boff[nt] = n * 64;
        bsw[nt]  = (n >> 1) & 3;
    }

    float acc[2][8][4];
#pragma unroll
    for (int mt = 0; mt < 2; mt++)
#pragma unroll
        for (int nt = 0; nt < 8; nt++)
#pragma unroll
            for (int i = 0; i < 4; i++) acc[mt][nt][i] = 0.f;

#pragma unroll
    for (int kt = 0; kt < 2; kt++) {
        const int k0 = kt * 32;
        {
            int row = tid >> 2, g = tid & 3;
            uint4 va = *(const uint4*)(A + (long)(m0 + row) * DHD + k0 + 8 * g);
            *(uint4*)&As[row * 16 + 4 * (g ^ ((row >> 1) & 3))] = va;
        }
#pragma unroll
        for (int j = 0; j < 4; j++) {
            int e = tid + j * 256;
            int n = e >> 2, g = e & 3;
            uint4 vb = *(const uint4*)(B + (long)n * DHD + k0 + 8 * g);
            *(uint4*)&Bs[n * 16 + 4 * (g ^ ((n >> 1) & 3))] = vb;
        }
        __syncthreads();

#pragma unroll
        for (int s = 0; s < 2; s++) {
            uint32_t af[2][4], bf[8][2];
#pragma unroll
            for (int mt = 0; mt < 2; mt++)
                ldsm4(af[mt], asmb + (uint32_t)(aoff[mt] +
                      ((((s << 1) | agh) ^ asw[mt]) << 4)));
#pragma unroll
            for (int nt = 0; nt < 8; nt++)
                ldsm2(bf[nt], bsmb + (uint32_t)(boff[nt] +
                      ((((s << 1) | btb) ^ bsw[nt]) << 4)));
#pragma unroll
            for (int mt = 0; mt < 2; mt++)
#pragma unroll
                for (int nt = 0; nt < 8; nt++)
                    mma_f16(acc[mt][nt], af[mt], bf[nt]);
        }
        __syncthreads();
    }

#pragma unroll
    for (int mt = 0; mt < 2; mt++)
#pragma unroll
        for (int half_ = 0; half_ < 2; half_++) {
            float mx = -1e30f;
#pragma unroll
            for (int nt = 0; nt < 8; nt++) {
                mx = fmaxf(mx, acc[mt][nt][half_ * 2]);
                mx = fmaxf(mx, acc[mt][nt][half_ * 2 + 1]);
            }
            mx = fmaxf(mx, __shfl_xor_sync(~0u, mx, 1));
            mx = fmaxf(mx, __shfl_xor_sync(~0u, mx, 2));
            int rloc = warpm * 32 + mt * 16 + half_ * 8 + lg;
            if (lt == 0) redm[rloc * 4 + warpn] = mx;
        }
    __syncthreads();
#pragma unroll
    for (int mt = 0; mt < 2; mt++)
#pragma unroll
        for (int half_ = 0; half_ < 2; half_++) {
            int rloc = warpm * 32 + mt * 16 + half_ * 8 + lg;
            float m4 = fmaxf(fmaxf(redm[rloc * 4 + 0], redm[rloc * 4 + 1]),
                             fmaxf(redm[rloc * 4 + 2], redm[rloc * 4 + 3]));
            float s = 0.f;
#pragma unroll
            for (int nt = 0; nt < 8; nt++) {
                float e0 = __expf(acc[mt][nt][half_ * 2]     - m4);
                float e1 = __expf(acc[mt][nt][half_ * 2 + 1] - m4);
                acc[mt][nt][half_ * 2]     = e0;
                acc[mt][nt][half_ * 2 + 1] = e1;
                s += e0 + e1;
            }
            s += __shfl_xor_sync(~0u, s, 1);
            s += __shfl_xor_sync(~0u, s, 2);
            if (lt == 0) reds[rloc * 4 + warpn] = s;
        }
    __syncthreads();
#pragma unroll
    for (int mt = 0; mt < 2; mt++)
#pragma unroll
        for (int half_ = 0; half_ < 2; half_++) {
            int rloc = warpm * 32 + mt * 16 + half_ * 8 + lg;
            float tot = reds[rloc * 4 + 0] + reds[rloc * 4 + 1]
                      + reds[rloc * 4 + 2] + reds[rloc * 4 + 3];
            float inv = 1.f / tot;
            int r = m0 + rloc;
#pragma unroll
            for (int nt = 0; nt < 8; nt++) {
                int c = warpn * 64 + nt * 8 + 2 * lt;
                *(uint32_t*)(O + (long)r * MM + c) =
                    h2pack(acc[mt][nt][half_ * 2] * inv, acc[mt][nt][half_ * 2 + 1] * inv);
            }
        }
}

// =============================================================================
// a3v_flash_h: a3vT = (softmax_row(ql @ k^T) @ v)^T, online softmax, half.
// 32 rows/block, chunk SN2=128 tokens (32 chunks). Output transposed [d][m].
// =============================================================================
__global__ __launch_bounds__(256, 2) void a3v_flash_h()
{
    __shared__ uint32_t Ks[128 * 32];  // K [tok][8 granules], swizzle g^(tok&7)
    __shared__ uint32_t Vs[64 * 64];   // V interleaved [kp_tok][d]
    __shared__ uint32_t Ps[32 * 64];   // P [m][kp], swizzle kp^((m&7)<<2)
    __shared__ float redm[32 * 4];
    __shared__ float reds[32 * 4];

    const int bh = blockIdx.z;
    const int m0 = blockIdx.x * 32;
    const __half* ql = h_ql + (long)bh * MM * DHD;
    const __half* kg = h_k  + (long)bh * NN * DHD;
    const __half* vg = h_v  + (long)bh * NN * DHD;

    const int tid = threadIdx.x;
    const int wid = tid >> 5, lane = tid & 31;
    const int warpm = wid & 1, warpn = wid >> 1;
    const int lg = lane >> 2, lt = lane & 3;

    uint32_t aq[4][4];
    {
        int mr = m0 + warpm * 16;
#pragma unroll
        for (int s = 0; s < 4; s++) {
            int d0 = s * 16 + 2 * lt;
            aq[s][0] = *(const uint32_t*)(ql + (long)(mr + lg) * DHD + d0);
            aq[s][1] = *(const uint32_t*)(ql + (long)(mr + 8 + lg) * DHD + d0);
            aq[s][2] = *(const uint32_t*)(ql + (long)(mr + lg) * DHD + d0 + 8);
            aq[s][3] = *(const uint32_t*)(ql + (long)(mr + 8 + lg) * DHD + d0 + 8);
        }
    }

    float oacc[2][4];
#pragma unroll
    for (int nt = 0; nt < 2; nt++)
#pragma unroll
        for (int i = 0; i < 4; i++) oacc[nt][i] = 0.f;
    float mprev[2] = {-1e30f, -1e30f};
    float lsum[2]  = {0.f, 0.f};

    // prefetch chunk 0: K = 128x64 half (4 uint4/thr), V same (4x uint2 pairs)
    uint4 kpre[4];
    uint2 vpa[4], vpb[4];
#pragma unroll
    for (int j = 0; j < 4; j++) {
        int e = tid + j * 256;
        { int tok = e >> 3, g = e & 7;
          kpre[j] = *(const uint4*)(kg + (long)tok * DHD + 8 * g); }
        { int kpt = e >> 4, d4 = (e & 15) << 2;
          vpa[j] = *(const uint2*)(vg + (long)(2 * kpt) * DHD + d4);
          vpb[j] = *(const uint2*)(vg + (long)(2 * kpt + 1) * DHD + d4); }
    }

    for (int ch = 0; ch < NCH2; ch++) {
        __syncthreads();
#pragma unroll
        for (int j = 0; j < 4; j++) {
            int e = tid + j * 256;
            { int tok = e >> 3, g = e & 7;
              *(uint4*)&Ks[tok * 32 + 4 * (g ^ (tok & 7))] = kpre[j]; }
            { int kpt = e >> 4, d4 = (e & 15) << 2;
              uint4 w;
              w.x = prmtb(vpa[j].x, vpb[j].x, 0x5410);
              w.y = prmtb(vpa[j].x, vpb[j].x, 0x7632);
              w.z = prmtb(vpa[j].y, vpb[j].y, 0x5410);
              w.w = prmtb(vpa[j].y, vpb[j].y, 0x7632);
              *(uint4*)&Vs[kpt * 64 + (d4 ^ ((kpt & 3) << 3))] = w; }
        }
        if (ch + 1 < NCH2) {
            const __half* kc = kg + (long)(ch + 1) * SN2 * DHD;
            const __half* vc = vg + (long)(ch + 1) * SN2 * DHD;
#pragma unroll
            for (int j = 0; j < 4; j++) {
                int e = tid + j * 256;
                { int tok = e >> 3, g = e & 7;
                  kpre[j] = *(const uint4*)(kc + (long)tok * DHD + 8 * g); }
                { int kpt = e >> 4, d4 = (e & 15) << 2;
                  vpa[j] = *(const uint2*)(vc + (long)(2 * kpt) * DHD + d4);
                  vpb[j] = *(const uint2*)(vc + (long)(2 * kpt + 1) * DHD + d4); }
            }
        }
        __syncthreads();

        // S = ql @ K^T : 16 rows x 32 tokens per warp (4 n-tiles), 4 k16 steps
        float sacc[4][4];
#pragma unroll
        for (int nt = 0; nt < 4; nt++)
#pragma unroll
            for (int i = 0; i < 4; i++) sacc[nt][i] = 0.f;
#pragma unroll
        for (int s = 0; s < 4; s++) {
            uint32_t bf[4][2];
#pragma unroll
            for (int nt = 0; nt < 4; nt++) {
                int c = warpn * 32 + nt * 8 + lg;
                bf[nt][0] = Ks[c * 32 + lt + 4 * ((2 * s) ^ (c & 7))];
                bf[nt][1] = Ks[c * 32 + lt + 4 * ((2 * s + 1) ^ (c & 7))];
            }
#pragma unroll
            for (int nt = 0; nt < 4; nt++)
                mma_f16(sacc[nt], aq[s], bf[nt]);
        }

#pragma unroll
        for (int half_ = 0; half_ < 2; half_++) {
            float mx = -1e30f;
#pragma unroll
            for (int nt = 0; nt < 4; nt++) {
                mx = fmaxf(mx, sacc[nt][half_ * 2]);
                mx = fmaxf(mx, sacc[nt][half_ * 2 + 1]);
            }
            mx = fmaxf(mx, __shfl_xor_sync(~0u, mx, 1));
            mx = fmaxf(mx, __shfl_xor_sync(~0u, mx, 2));
            if (lt == 0) redm[(warpm * 16 + half_ * 8 + lg) * 4 + warpn] = mx;
        }
        __syncthreads();

        float scale[2];
#pragma unroll
        for (int half_ = 0; half_ < 2; half_++) {
            int row = warpm * 16 + half_ * 8 + lg;
            float mch = fmaxf(fmaxf(redm[row * 4 + 0], redm[row * 4 + 1]),
                              fmaxf(redm[row * 4 + 2], redm[row * 4 + 3]));
            float mnew = fmaxf(mprev[half_], mch);
            scale[half_] = __expf(mprev[half_] - mnew);
            mprev[half_] = mnew;
            float s = 0.f;
#pragma unroll
            for (int nt = 0; nt < 4; nt++) {
                float e0 = __expf(sacc[nt][half_ * 2]     - mnew);
                float e1 = __expf(sacc[nt][half_ * 2 + 1] - mnew);
                sacc[nt][half_ * 2]     = e0;
                sacc[nt][half_ * 2 + 1] = e1;
                s += e0 + e1;
            }
            s += __shfl_xor_sync(~0u, s, 1);
            s += __shfl_xor_sync(~0u, s, 2);
            if (lt == 0) reds[row * 4 + warpn] = s;
#pragma unroll
            for (int nt = 0; nt < 4; nt++) {
                int kp = warpn * 16 + nt * 4 + lt;
                Ps[row * 64 + (kp ^ ((row & 7) << 2))] =
                    h2pack(sacc[nt][half_ * 2], sacc[nt][half_ * 2 + 1]);
            }
        }
        __syncthreads();

#pragma unroll
        for (int half_ = 0; half_ < 2; half_++) {
            int row = warpm * 16 + half_ * 8 + lg;
            lsum[half_] = lsum[half_] * scale[half_]
                        + reds[row * 4 + 0] + reds[row * 4 + 1]
                        + reds[row * 4 + 2] + reds[row * 4 + 3];
        }
#pragma unroll
        for (int nt = 0; nt < 2; nt++) {
            oacc[nt][0] *= scale[0]; oacc[nt][1] *= scale[0];
            oacc[nt][2] *= scale[1]; oacc[nt][3] *= scale[1];
        }

        // O += P @ V : 16 rows x 16 d per warp, 8 k16 steps over 128 tokens
#pragma unroll
        for (int s = 0; s < 8; s++) {
            const int kp0 = s * 8;
            int mr = warpm * 16 + lg;
            uint32_t af[4];
            af[0] = Ps[mr * 64 + ((kp0 + lt) ^ ((mr & 7) << 2))];
            af[1] = Ps[(mr + 8) * 64 + ((kp0 + lt) ^ (((mr + 8) & 7) << 2))];
            af[2] = Ps[mr * 64 + ((kp0 + lt + 4) ^ ((mr & 7) << 2))];
            af[3] = Ps[(mr + 8) * 64 + ((kp0 + lt + 4) ^ (((mr + 8) & 7) << 2))];
            uint32_t bf[2][2];
#pragma unroll
            for (int nt = 0; nt < 2; nt++) {
                int d = warpn * 16 + nt * 8 + lg;
                bf[nt][0] = Vs[(kp0 + lt) * 64 + (d ^ (lt << 3))];
                bf[nt][1] = Vs[(kp0 + lt + 4) * 64 + (d ^ (lt << 3))];
            }
#pragma unroll
            for (int nt = 0; nt < 2; nt++)
                mma_f16(oacc[nt], af, bf[nt]);
        }
    }

    __half* outb = h_a3vT + (long)bh * DHD * MM;
#pragma unroll
    for (int half_ = 0; half_ < 2; half_++) {
        float inv = 1.f / lsum[half_];
        int r = m0 + warpm * 16 + half_ * 8 + lg;
#pragma unroll
        for (int nt = 0; nt < 2; nt++) {
            int d = warpn * 16 + nt * 8 + 2 * lt;
            outb[(long)d * MM + r]       = __float2half(oacc[nt][half_ * 2] * inv);
            outb[(long)(d + 1) * MM + r] = __float2half(oacc[nt][half_ * 2 + 1] * inv);
        }
    }
}

// ---------------- LayerNorm (half out) -----------------------------------------
__global__ __launch_bounds__(256) void ln_kernel(
    const float* __restrict__ x, const float* __restrict__ w, const float* __restrict__ b)
{
    long row = blockIdx.x;
    const float* xr = x + row * DD;
    int t = threadIdx.x;
    float v0 = xr[t], v1 = xr[t + 256];
    __shared__ float red[32];

    float s = v0 + v1;
    for (int o = 16; o > 0; o >>= 1) s += __shfl_xor_sync(~0u, s, o);
    if ((t & 31) == 0) red[t >> 5] = s;
    __syncthreads();
    if (t < 32) {
        float ss = (t < 8) ? red[t] : 0.f;
        for (int o = 4; o > 0; o >>= 1) ss += __shfl_xor_sync(~0u, ss, o);
        if (t == 0) red[0] = ss;
    }
    __syncthreads();
    float mu = red[0] * (1.f / DD);
    __syncthreads();

    float d0 = v0 - mu, d1 = v1 - mu;
    float q = d0 * d0 + d1 * d1;
    for (int o = 16; o > 0; o >>= 1) q += __shfl_xor_sync(~0u, q, o);
    if ((t & 31) == 0) red[t >> 5] = q;
    __syncthreads();
    if (t < 32) {
        float ss = (t < 8) ? red[t] : 0.f;
        for (int o = 4; o > 0; o >>= 1) ss += __shfl_xor_sync(~0u, ss, o);
        if (t == 0) red[0] = ss;
    }
    __syncthreads();
    float inv = rsqrtf(red[0] * (1.f / DD) + 1e-5f);
    h_xn[row * DD + t]       = __float2half(d0 * inv * w[t]       + b[t]);
    h_xn[row * DD + t + 256] = __float2half(d1 * inv * w[t + 256] + b[t + 256]);
}

// ---------------- weight conversion (transpose to [N][K] half) ----------------
__global__ void conv_weights(const float* __restrict__ wq, const float* __restrict__ wo)
{
    int i = blockIdx.x * 256 + threadIdx.x;
    {
        int n = i / DD, k2 = i % DD;
        h_wqkvT[i] = __float2half(wq[(long)k2 * (3 * DD) + n]);
    }
    if (i < DD * DD) {
        int n = i / DD, k2 = i % DD;
        h_woutT[i] = __float2half(wo[(long)k2 * DD + n]);
    }
}

// ---------------- landmarks (vectorized) ---------------------------------------
__global__ void landmarks()
{
    long i = (long)blockIdx.x * 256 + threadIdx.x;    // BH*MM*8 granules
    int dg = i & 7; long r = i >> 3;
    int m = r % MM;  int bh = r / MM;
    long base = ((long)bh * NN + m * LLm) * DHD + dg * 8;
    float sq[8], sk[8];
#pragma unroll
    for (int e = 0; e < 8; e++) { sq[e] = 0.f; sk[e] = 0.f; }
#pragma unroll
    for (int u = 0; u < LLm; u++) {
        uint4 vq = *(const uint4*)(h_q + base + u * DHD);
        uint4 vk = *(const uint4*)(h_k + base + u * DHD);
        const uint32_t* q4 = &vq.x;
        const uint32_t* k4 = &vk.x;
#pragma unroll
        for (int p = 0; p < 4; p++) {
            float2 fq = __half22float2(*(const __half2*)&q4[p]);
            float2 fk = __half22float2(*(const __half2*)&k4[p]);
            sq[2 * p] += fq.x; sq[2 * p + 1] += fq.y;
            sk[2 * p] += fk.x; sk[2 * p + 1] += fk.y;
        }
    }
    uint4 oq, ok;
    uint32_t* oq4 = &oq.x; uint32_t* ok4 = &ok.x;
#pragma unroll
    for (int p = 0; p < 4; p++) {
        oq4[p] = h2pack(sq[2 * p] * (1.f / LLm), sq[2 * p + 1] * (1.f / LLm));
        ok4[p] = h2pack(sk[2 * p] * (1.f / LLm), sk[2 * p + 1] * (1.f / LLm));
    }
    long out = ((long)bh * MM + m) * DHD + dg * 8;
    *(uint4*)(h_ql + out) = oq;
    *(uint4*)(h_kl + out) = ok;
}

// ---------------- pinv init ----------------------------------------------------
__global__ void init_colmax() { g_colmax = 0.f; }

__global__ __launch_bounds__(256) void colmax_kernel()
{
    int bh = blockIdx.x, j = threadIdx.x;
    const __half* a = h_a2 + (long)bh * MM * MM;
    float s = 0.f;
    for (int i = 0; i < MM; i++) s += __half2float(a[i * MM + j]);
    __shared__ float red[32];
    float m = s;
    for (int o = 16; o > 0; o >>= 1) m = fmaxf(m, __shfl_xor_sync(~0u, m, o));
    if ((j & 31) == 0) red[j >> 5] = m;
    __syncthreads();
    if (j < 32) {
        float m2 = (j < 8) ? red[j] : -1e30f;
        for (int o = 4; o > 0; o >>= 1) m2 = fmaxf(m2, __shfl_xor_sync(~0u, m2, o));
        if (j == 0) atomicMax((int*)&g_colmax, __float_as_int(m2));
    }
}

__global__ void zinit()
{
    long i = (long)blockIdx.x * 256 + threadIdx.x;
    int col = i % MM; long r = i / MM;
    int row = r % MM; int bh = r / MM;
    float inv = 1.f / g_colmax;
    h_zT[i] = __float2half(__half2float(h_a2[i]) * inv);
    h_z [i] = __float2half(__half2float(h_a2[((long)bh * MM + col) * MM + row]) * inv);
}

// ---------------- fused reshape + depthwise conv (all half) --------------------
__global__ void att_conv(const float* __restrict__ rw)
{
    long i = (long)blockIdx.x * 256 + threadIdx.x;    // BH*NN*16 granules (4 halves)
    int dq = i % 16; long r = i / 16;
    int h = r % HH;  long r2 = r / HH;
    int n = r2 % NN; int b = r2 / NN;
    long bhbase = (long)(b * HH + h) * NN;
    const __half* vb = h_v + bhbase * DHD;
    uint2 ov = *(const uint2*)(h_o + (bhbase + n) * DHD + dq * 4);
    float2 o0 = __half22float2(*(const __half2*)&ov.x);
    float2 o1 = __half22float2(*(const __half2*)&ov.y);
    float a0 = o0.x, a1 = o0.y, a2 = o1.x, a3 = o1.y;
#pragma unroll
    for (int j = 0; j < KC; j++) {
        int tt = n + j - KC / 2;
        if (tt >= 0 && tt < NN) {
            float w = rw[h * KC + j];
            uint2 vv = *(const uint2*)(vb + (long)tt * DHD + dq * 4);
            float2 v0 = __half22float2(*(const __half2*)&vv.x);
            float2 v1 = __half22float2(*(const __half2*)&vv.y);
            a0 += w * v0.x; a1 += w * v0.y; a2 += w * v1.x; a3 += w * v1.y;
        }
    }
    uint2 w2;
    w2.x = h2pack(a0, a1);
    w2.y = h2pack(a2, a3);
    *(uint2*)&h_att[((long)(b * NN + n)) * DD + h * DHD + dq * 4] = w2;
}

// ---------------- host orchestration -------------------------------------------
extern "C" void kernel_launch(void* const* d_in, const int* in_sizes, int n_in,
                              void* d_out, int out_size)
{
    const float* x      = (const float*)d_in[0];
    const float* norm_w = (const float*)d_in[1];
    const float* norm_b = (const float*)d_in[2];
    const float* w_qkv  = (const float*)d_in[3];
    const float* w_out  = (const float*)d_in[4];
    const float* b_out  = (const float*)d_in[5];
    const float* res_w  = (const float*)d_in[6];
    float* y = (float*)d_out;

    __half *p_xn, *p_wqkvT, *p_woutT, *p_q, *p_k, *p_v, *p_o, *p_ql, *p_kl;
    __half *p_a1, *p_a2, *p_z, *p_zT, *p_z2, *p_z2T, *p_xz, *p_t1T, *p_t2T, *p_a3vT, *p_WT, *p_att;
    cudaGetSymbolAddress((void**)&p_xn,   h_xn);
    cudaGetSymbolAddress((void**)&p_wqkvT,h_wqkvT);
    cudaGetSymbolAddress((void**)&p_woutT,h_woutT);
    cudaGetSymbolAddress((void**)&p_q,    h_q);
    cudaGetSymbolAddress((void**)&p_k,    h_k);
    cudaGetSymbolAddress((void**)&p_v,    h_v);
    cudaGetSymbolAddress((void**)&p_o,    h_o);
    cudaGetSymbolAddress((void**)&p_ql,   h_ql);
    cudaGetSymbolAddress((void**)&p_kl,   h_kl);
    cudaGetSymbolAddress((void**)&p_a1,   h_a1);
    cudaGetSymbolAddress((void**)&p_a2,   h_a2);
    cudaGetSymbolAddress((void**)&p_z,    h_z);
    cudaGetSymbolAddress((void**)&p_zT,   h_zT);
    cudaGetSymbolAddress((void**)&p_z2,   h_z2);
    cudaGetSymbolAddress((void**)&p_z2T,  h_z2T);
    cudaGetSymbolAddress((void**)&p_xz,   h_xz);
    cudaGetSymbolAddress((void**)&p_t1T,  h_t1T);
    cudaGetSymbolAddress((void**)&p_t2T,  h_t2T);
    cudaGetSymbolAddress((void**)&p_a3vT, h_a3vT);
    cudaGetSymbolAddress((void**)&p_WT,   h_WT);
    cudaGetSymbolAddress((void**)&p_att,  h_att);

    const long MM2 = (long)MM * MM;
    void* nul = nullptr;

    // 1. LayerNorm -> h_xn; weight conversion
    ln_kernel<<<BB * NN, 256>>>(x, norm_w, norm_b);
    conv_weights<<<(3 * DD * DD) / 256, 256>>>(w_qkv, w_out);
    // 2. qkv = xn @ wqkvT^T with fused split
    gemm_h<128, 1><<<dim3((3 * DD) / 128, (BB * NN) / 128, 1), 256>>>(
        p_xn, p_wqkvT, p_q, p_k, p_v,
        BB * NN, 3 * DD, DD, 0, 0, 0, 1.f, 0.f);
    // 3. landmarks
    landmarks<<<(BH * MM * 8) / 256, 256>>>();
    // 4. a2 = softmax(ql @ kl^T)
    sim_softmax_h<<<dim3(MM / 64, 1, BH), 256>>>(
        p_ql, p_kl, p_a2, (long)MM * DHD, (long)MM * DHD, MM2);
    // 5. pinv init
    init_colmax<<<1, 1>>>();
    colmax_kernel<<<BH, 256>>>();
    zinit<<<(int)((long)BH * MM * MM / 256), 256>>>();
    // 6. Newton-Schulz
    __half *zin = p_z, *zinT = p_zT, *zout = p_z2, *zoutT = p_z2T;
    for (int it = 0; it < NITER; it++) {
        gemm_h<64, 3><<<dim3(MM / 64, MM / 128, BH), 256>>>(
            p_a2, zinT, p_xz, nul, p_t1T, MM, MM, MM, MM2, MM2, MM2, 1.f, 7.f);
        gemm_h<64, 3><<<dim3(MM / 64, MM / 128, BH), 256>>>(
            p_xz, p_t1T, nul, nul, p_t2T, MM, MM, MM, MM2, MM2, MM2, 1.f, 15.f);
        gemm_h<64, 3><<<dim3(MM / 64, MM / 128, BH), 256>>>(
            p_xz, p_t2T, nul, nul, p_t1T, MM, MM, MM, MM2, MM2, MM2, 1.f, 13.f);
        gemm_h<64, 3><<<dim3(MM / 64, MM / 128, BH), 256>>>(
            zin, p_t1T, zout, zoutT, nul, MM, MM, MM, MM2, MM2, MM2, 0.25f, 0.f);
        __half* t;
        t = zin;  zin  = zout;  zout  = t;
        t = zinT; zinT = zoutT; zoutT = t;
    }
    // 7. a1 = softmax(q @ kl^T)
    sim_softmax_h<<<dim3(NN / 64, 1, BH), 256>>>(
        p_q, p_kl, p_a1, (long)NN * DHD, (long)MM * DHD, (long)NN * MM);
    // 8. a3vT = (softmax(ql @ k^T) @ v)^T  (flash, SN2=128)
    a3v_flash_h<<<dim3(MM / 32, 1, BH), 256>>>();
    // 9. WT = (z @ a3v)^T
    gemm_h<64, 3><<<dim3(1, MM / 128, BH), 256>>>(
        zin, p_a3vT, nul, p_WT, nul, MM, DHD, MM,
        MM2, (long)DHD * MM, (long)DHD * MM, 1.f, 0.f);
    // 10. o = a1 @ W  (half out via MODE 3 Cn)
    gemm_h<64, 3><<<dim3(1, NN / 128, BH), 256>>>(
        p_a1, p_WT, p_o, nul, nul, NN, DHD, MM,
        (long)NN * MM, (long)DHD * MM, (long)NN * DHD, 1.f, 0.f);
    // 11. att = reshape(o) + conv(v)  (all half)
    att_conv<<<(BB * NN * HH * 16) / 256, 256>>>(res_w);
    // 12. y = att @ w_out + x + b_out
    gemm_h<128, 2><<<dim3(DD / 128, (BB * NN) / 128, 1), 256>>>(
        p_att, p_woutT, y, (void*)x, (void*)b_out,
        BB * NN, DD, DD, 0, 0, 0, 1.f, 0.f);
}

// round 13
// speedup vs baseline: 5.0906x; 1.0069x over previous
#include <cuda_runtime.h>
#include <cuda_fp16.h>
#include <cstdint>

#define BB 4
#define NN 4096
#define DD 512
#define HH 8
#define DHD 64
#define MM 256
#define LLm 16
#define NITER 6
#define KC 33
#define BH (BB*HH)
#define SN2 128
#define NCH2 (NN/SN2)

// ---------------- scratch -------------------------------------------------------
__device__ __align__(16) __half h_xn   [BB*NN*DD];
__device__ __align__(16) __half h_wqkvT[3*DD*DD];
__device__ __align__(16) __half h_woutT[DD*DD];
__device__ __align__(16) __half h_q  [BH*NN*DHD];
__device__ __align__(16) __half h_k  [BH*NN*DHD];
__device__ __align__(16) __half h_v  [BH*NN*DHD];
__device__ __align__(16) __half h_o  [BH*NN*DHD];
__device__ __align__(16) __half h_ql [BH*MM*DHD];
__device__ __align__(16) __half h_kl [BH*MM*DHD];
__device__ __align__(16) __half h_a2 [BH*MM*MM];
__device__ __align__(16) __half h_z  [BH*MM*MM];
__device__ __align__(16) __half h_zT [BH*MM*MM];
__device__ __align__(16) __half h_z2 [BH*MM*MM];
__device__ __align__(16) __half h_z2T[BH*MM*MM];
__device__ __align__(16) __half h_xz [BH*MM*MM];
__device__ __align__(16) __half h_t1T[BH*MM*MM];
__device__ __align__(16) __half h_t2T[BH*MM*MM];
__device__ __align__(16) __half h_a3vT[BH*DHD*MM];    // [d][m]
__device__ __align__(16) __half h_WT [BH*DHD*MM];     // [d][m]
__device__ __align__(16) __half h_att[BB*NN*DD];
__device__ float g_colmax;

// ---------------- helpers ------------------------------------------------------
__device__ __forceinline__ uint32_t h2pack(float a, float b) {
    __half2 h = __floats2half2_rn(a, b);
    return *reinterpret_cast<uint32_t*>(&h);
}
__device__ __forceinline__ uint32_t prmtb(uint32_t a, uint32_t b, uint32_t sel) {
    uint32_t d;
    asm("prmt.b32 %0, %1, %2, %3;" : "=r"(d) : "r"(a), "r"(b), "r"(sel));
    return d;
}
__device__ __forceinline__ void mma_f16(float* c, const uint32_t* a, const uint32_t* b) {
    asm volatile(
        "mma.sync.aligned.m16n8k16.row.col.f32.f16.f16.f32 "
        "{%0,%1,%2,%3}, {%4,%5,%6,%7}, {%8,%9}, {%0,%1,%2,%3};"
        : "+f"(c[0]), "+f"(c[1]), "+f"(c[2]), "+f"(c[3])
        : "r"(a[0]), "r"(a[1]), "r"(a[2]), "r"(a[3]), "r"(b[0]), "r"(b[1]));
}
__device__ __forceinline__ void ldsm4(uint32_t* r, uint32_t saddr) {
    asm volatile("ldmatrix.sync.aligned.m8n8.x4.shared.b16 {%0,%1,%2,%3}, [%4];"
        : "=r"(r[0]), "=r"(r[1]), "=r"(r[2]), "=r"(r[3]) : "r"(saddr));
}
__device__ __forceinline__ void ldsm2(uint32_t* r, uint32_t saddr) {
    asm volatile("ldmatrix.sync.aligned.m8n8.x2.shared.b16 {%0,%1}, [%2];"
        : "=r"(r[0]), "=r"(r[1]) : "r"(saddr));
}
__device__ __forceinline__ void cpa16(uint32_t dst, const void* src) {
    asm volatile("cp.async.cg.shared.global [%0], [%1], 16;" :: "r"(dst), "l"(src));
}
#define CP_COMMIT() asm volatile("cp.async.commit_group;")

// =============================================================================
// gemm_h: C = alpha * A @ B^T, A [M][K] half, B [N][K] half (both k-contig).
// BM=128, BN template, BK=32. cp.async + LDSM, 2 blocks/SM. 8 warps 4m x 2n.
// MODE 0: p0 = float* C ; MODE 1: qkv split ; MODE 2: y = acc + x + bout
// MODE 3: p0 Cn(half normal), p1 CtRaw(half transp), p2 CtDiag(half transp, dgI-acc)
// =============================================================================
template<int BN, int MODE>
__global__ __launch_bounds__(256, 2) void gemm_h(
    const __half* __restrict__ Ag, const __half* __restrict__ Bg,
    void* __restrict__ p0, void* __restrict__ p1, void* __restrict__ p2,
    int Md, int Nd, int Kd, long sA, long sB, long sC,
    float alpha, float dg)
{
    constexpr int NT = BN / 16;
    constexpr int WN = BN / 2;
    constexpr int NBJ = BN / 64;

    __shared__ uint32_t As[2][128 * 16];
    __shared__ uint32_t Bs[2][BN * 16];

    const __half* A = Ag + (long)blockIdx.z * sA;
    const __half* Bp = Bg + (long)blockIdx.z * sB;
    const int m0 = blockIdx.y * 128;
    const int n0 = blockIdx.x * BN;
    const int tid = threadIdx.x;
    const int wid = tid >> 5, lane = tid & 31;
    const int warpm = wid & 3, warpn = wid >> 2;
    const int lg = lane >> 2, lt = lane & 3;

    const uint32_t asmb = (uint32_t)__cvta_generic_to_shared(&As[0][0]);
    const uint32_t bsmb = (uint32_t)__cvta_generic_to_shared(&Bs[0][0]);

    const int t4  = lane >> 3;
    const int agh = t4 >> 1;
    int aoff[2], asw[2];
#pragma unroll
    for (int mt = 0; mt < 2; mt++) {
        int rr = warpm * 32 + mt * 16 + (t4 & 1) * 8 + (lane & 7);
        aoff[mt] = rr * 64;
        asw[mt]  = (rr >> 1) & 3;
    }
    const int btb = t4 & 1;
    int boff[NT], bsw[NT];
#pragma unroll
    for (int nt = 0; nt < NT; nt++) {
        int n = warpn * WN + nt * 8 + (lane & 7);
        boff[nt] = n * 64;
        bsw[nt]  = (n >> 1) & 3;
    }

    float acc[2][NT][4];
#pragma unroll
    for (int mt = 0; mt < 2; mt++)
#pragma unroll
        for (int nt = 0; nt < NT; nt++)
#pragma unroll
            for (int i = 0; i < 4; i++) acc[mt][nt][i] = 0.f;

    const int nk = Kd >> 5;

#define LOADT(kt, st) do {                                                      \
    const int k0_ = (kt) << 5;                                                  \
    _Pragma("unroll")                                                           \
    for (int j = 0; j < 2; j++) {                                               \
        int e = tid + j * 256;                                                  \
        int row = e >> 2, g = e & 3;                                            \
        uint32_t d = asmb + (uint32_t)(((st) * 2048 + row * 16 +                \
                     4 * (g ^ ((row >> 1) & 3))) << 2);                         \
        cpa16(d, A + (long)(m0 + row) * Kd + k0_ + 8 * g);                      \
    }                                                                           \
    _Pragma("unroll")                                                           \
    for (int j = 0; j < NBJ; j++) {                                             \
        int e = tid + j * 256;                                                  \
        int n = e >> 2, g = e & 3;                                              \
        uint32_t d = bsmb + (uint32_t)(((st) * (BN * 16) + n * 16 +             \
                     4 * (g ^ ((n >> 1) & 3))) << 2);                           \
        cpa16(d, Bp + (long)(n0 + n) * Kd + k0_ + 8 * g);                       \
    }                                                                           \
    CP_COMMIT();                                                                \
} while (0)

    LOADT(0, 0);

    for (int kt = 0; kt < nk; kt++) {
        const int st = kt & 1;
        if (kt + 1 < nk) {
            LOADT(kt + 1, st ^ 1);
            asm volatile("cp.async.wait_group 1;");
        } else {
            asm volatile("cp.async.wait_group 0;");
        }
        __syncthreads();

        const uint32_t a_base = asmb + (uint32_t)((st * 2048) << 2);
        const uint32_t b_base = bsmb + (uint32_t)((st * (BN * 16)) << 2);
#pragma unroll
        for (int s = 0; s < 2; s++) {
            uint32_t af[2][4], bf[NT][2];
#pragma unroll
            for (int mt = 0; mt < 2; mt++)
                ldsm4(af[mt], a_base + (uint32_t)((aoff[mt] +
                      ((((s << 1) | agh) ^ asw[mt]) << 4))));
#pragma unroll
            for (int nt = 0; nt < NT; nt++)
                ldsm2(bf[nt], b_base + (uint32_t)((boff[nt] +
                      ((((s << 1) | btb) ^ bsw[nt]) << 4))));
#pragma unroll
            for (int mt = 0; mt < 2; mt++)
#pragma unroll
                for (int nt = 0; nt < NT; nt++)
                    mma_f16(acc[mt][nt], af[mt], bf[nt]);
        }
        __syncthreads();
    }
#undef LOADT

    if (MODE == 0) {
        float* C = (float*)p0 + (long)blockIdx.z * sC;
#pragma unroll
        for (int mt = 0; mt < 2; mt++)
#pragma unroll
            for (int nt = 0; nt < NT; nt++) {
                int r = m0 + warpm * 32 + mt * 16 + lg;
                int c = n0 + warpn * WN + nt * 8 + 2 * lt;
                *(float2*)(C + (long)r * Nd + c) =
                    make_float2(acc[mt][nt][0] * alpha, acc[mt][nt][1] * alpha);
                *(float2*)(C + (long)(r + 8) * Nd + c) =
                    make_float2(acc[mt][nt][2] * alpha, acc[mt][nt][3] * alpha);
            }
    } else if (MODE == 1) {
        __half* qh = (__half*)p0; __half* kh = (__half*)p1; __half* vh = (__half*)p2;
#pragma unroll
        for (int mt = 0; mt < 2; mt++)
#pragma unroll
            for (int nt = 0; nt < NT; nt++) {
                int c = n0 + warpn * WN + nt * 8 + 2 * lt;
                int which = c >> 9, cc = c & 511;
                int h = cc >> 6, d = cc & 63;
                float sc = (which == 0) ? 0.125f : 1.f;
                __half* dsth = (which == 0) ? qh : (which == 1) ? kh : vh;
#pragma unroll
                for (int half_ = 0; half_ < 2; half_++) {
                    int m = m0 + warpm * 32 + mt * 16 + half_ * 8 + lg;
                    int b = m >> 12, n = m & 4095;
                    long dst = ((long)(b * HH + h) * NN + n) * DHD + d;
                    *(uint32_t*)(dsth + dst) = h2pack(acc[mt][nt][half_ * 2] * sc,
                                                      acc[mt][nt][half_ * 2 + 1] * sc);
                }
            }
    } else if (MODE == 2) {
        float* y = (float*)p0;
        const float* xp = (const float*)p1;
        const float* bp = (const float*)p2;
#pragma unroll
        for (int mt = 0; mt < 2; mt++)
#pragma unroll
            for (int nt = 0; nt < NT; nt++) {
                int r = m0 + warpm * 32 + mt * 16 + lg;
                int c = n0 + warpn * WN + nt * 8 + 2 * lt;
                float b0 = bp[c], b1 = bp[c + 1];
                float2 x0 = *(const float2*)(xp + (long)r * Nd + c);
                float2 x1 = *(const float2*)(xp + (long)(r + 8) * Nd + c);
                *(float2*)(y + (long)r * Nd + c) =
                    make_float2(acc[mt][nt][0] + x0.x + b0, acc[mt][nt][1] + x0.y + b1);
                *(float2*)(y + (long)(r + 8) * Nd + c) =
                    make_float2(acc[mt][nt][2] + x1.x + b0, acc[mt][nt][3] + x1.y + b1);
            }
    } else {
        __half* Cn = p0 ? (__half*)p0 + (long)blockIdx.z * sC : nullptr;
        __half* Ctr = p1 ? (__half*)p1 + (long)blockIdx.z * sC : nullptr;
        __half* Ctd = p2 ? (__half*)p2 + (long)blockIdx.z * sC : nullptr;
#pragma unroll
        for (int mt = 0; mt < 2; mt++)
#pragma unroll
            for (int nt = 0; nt < NT; nt++) {
                int r = m0 + warpm * 32 + mt * 16 + lg;
                int c = n0 + warpn * WN + nt * 8 + 2 * lt;
                float v00 = acc[mt][nt][0] * alpha;
                float v01 = acc[mt][nt][1] * alpha;
                float v10 = acc[mt][nt][2] * alpha;
                float v11 = acc[mt][nt][3] * alpha;
                if (Cn) {
                    *(uint32_t*)(Cn + (long)r * Nd + c)       = h2pack(v00, v01);
                    *(uint32_t*)(Cn + (long)(r + 8) * Nd + c) = h2pack(v10, v11);
                }
                if (Ctr) {
                    Ctr[(long)c * Md + r]           = __float2half(v00);
                    Ctr[(long)(c + 1) * Md + r]     = __float2half(v01);
                    Ctr[(long)c * Md + r + 8]       = __float2half(v10);
                    Ctr[(long)(c + 1) * Md + r + 8] = __float2half(v11);
                }
                if (Ctd) {
                    Ctd[(long)c * Md + r]           = __float2half(((r == c)         ? dg : 0.f) - v00);
                    Ctd[(long)(c + 1) * Md + r]     = __float2half(((r == c + 1)     ? dg : 0.f) - v01);
                    Ctd[(long)c * Md + r + 8]       = __float2half(((r + 8 == c)     ? dg : 0.f) - v10);
                    Ctd[(long)(c + 1) * Md + r + 8] = __float2half(((r + 8 == c + 1) ? dg : 0.f) - v11);
                }
            }
    }
}

// =============================================================================
// sim_softmax_h: Out(half) = softmax_row(A @ B^T)  (used for a2 only)
// =============================================================================
__global__ __launch_bounds__(256, 2) void sim_softmax_h(
    const __half* __restrict__ Ag, const __half* __restrict__ Bg,
    __half* __restrict__ Og, long sA, long sB, long sO)
{
    __shared__ uint32_t As[64 * 16];
    __shared__ uint32_t Bs[256 * 16];
    __shared__ float redm[64 * 4];
    __shared__ float reds[64 * 4];

    const __half* A = Ag + (long)blockIdx.z * sA;
    const __half* B = Bg + (long)blockIdx.z * sB;
    __half*       O = Og + (long)blockIdx.z * sO;
    const int m0 = blockIdx.x * 64;
    const int tid = threadIdx.x;
    const int wid = tid >> 5, lane = tid & 31;
    const int warpm = wid & 1, warpn = wid >> 1;
    const int lg = lane >> 2, lt = lane & 3;

    const uint32_t asmb = (uint32_t)__cvta_generic_to_shared(&As[0]);
    const uint32_t bsmb = (uint32_t)__cvta_generic_to_shared(&Bs[0]);

    const int t4  = lane >> 3;
    const int agh = t4 >> 1;
    int aoff[2], asw[2];
#pragma unroll
    for (int mt = 0; mt < 2; mt++) {
        int rr = warpm * 32 + mt * 16 + (t4 & 1) * 8 + (lane & 7);
        aoff[mt] = rr * 64;
        asw[mt]  = (rr >> 1) & 3;
    }
    const int btb = t4 & 1;
    int boff[8], bsw[8];
#pragma unroll
    for (int nt = 0; nt < 8; nt++) {
        int n = warpn * 64 + nt * 8 + (lane & 7);
        boff[nt] = n * 64;
        bsw[nt]  = (n >> 1) & 3;
    }

    float acc[2][8][4];
#pragma unroll
    for (int mt = 0; mt < 2; mt++)
#pragma unroll
        for (int nt = 0; nt < 8; nt++)
#pragma unroll
            for (int i = 0; i < 4; i++) acc[mt][nt][i] = 0.f;

#pragma unroll
    for (int kt = 0; kt < 2; kt++) {
        const int k0 = kt * 32;
        {
            int row = tid >> 2, g = tid & 3;
            uint4 va = *(const uint4*)(A + (long)(m0 + row) * DHD + k0 + 8 * g);
            *(uint4*)&As[row * 16 + 4 * (g ^ ((row >> 1) & 3))] = va;
        }
#pragma unroll
        for (int j = 0; j < 4; j++) {
            int e = tid + j * 256;
            int n = e >> 2, g = e & 3;
            uint4 vb = *(const uint4*)(B + (long)n * DHD + k0 + 8 * g);
            *(uint4*)&Bs[n * 16 + 4 * (g ^ ((n >> 1) & 3))] = vb;
        }
        __syncthreads();

#pragma unroll
        for (int s = 0; s < 2; s++) {
            uint32_t af[2][4], bf[8][2];
#pragma unroll
            for (int mt = 0; mt < 2; mt++)
                ldsm4(af[mt], asmb + (uint32_t)(aoff[mt] +
                      ((((s << 1) | agh) ^ asw[mt]) << 4)));
#pragma unroll
            for (int nt = 0; nt < 8; nt++)
                ldsm2(bf[nt], bsmb + (uint32_t)(boff[nt] +
                      ((((s << 1) | btb) ^ bsw[nt]) << 4)));
#pragma unroll
            for (int mt = 0; mt < 2; mt++)
#pragma unroll
                for (int nt = 0; nt < 8; nt++)
                    mma_f16(acc[mt][nt], af[mt], bf[nt]);
        }
        __syncthreads();
    }

#pragma unroll
    for (int mt = 0; mt < 2; mt++)
#pragma unroll
        for (int half_ = 0; half_ < 2; half_++) {
            float mx = -1e30f;
#pragma unroll
            for (int nt = 0; nt < 8; nt++) {
                mx = fmaxf(mx, acc[mt][nt][half_ * 2]);
                mx = fmaxf(mx, acc[mt][nt][half_ * 2 + 1]);
            }
            mx = fmaxf(mx, __shfl_xor_sync(~0u, mx, 1));
            mx = fmaxf(mx, __shfl_xor_sync(~0u, mx, 2));
            int rloc = warpm * 32 + mt * 16 + half_ * 8 + lg;
            if (lt == 0) redm[rloc * 4 + warpn] = mx;
        }
    __syncthreads();
#pragma unroll
    for (int mt = 0; mt < 2; mt++)
#pragma unroll
        for (int half_ = 0; half_ < 2; half_++) {
            int rloc = warpm * 32 + mt * 16 + half_ * 8 + lg;
            float m4 = fmaxf(fmaxf(redm[rloc * 4 + 0], redm[rloc * 4 + 1]),
                             fmaxf(redm[rloc * 4 + 2], redm[rloc * 4 + 3]));
            float s = 0.f;
#pragma unroll
            for (int nt = 0; nt < 8; nt++) {
                float e0 = __expf(acc[mt][nt][half_ * 2]     - m4);
                float e1 = __expf(acc[mt][nt][half_ * 2 + 1] - m4);
                acc[mt][nt][half_ * 2]     = e0;
                acc[mt][nt][half_ * 2 + 1] = e1;
                s += e0 + e1;
            }
            s += __shfl_xor_sync(~0u, s, 1);
            s += __shfl_xor_sync(~0u, s, 2);
            if (lt == 0) reds[rloc * 4 + warpn] = s;
        }
    __syncthreads();
#pragma unroll
    for (int mt = 0; mt < 2; mt++)
#pragma unroll
        for (int half_ = 0; half_ < 2; half_++) {
            int rloc = warpm * 32 + mt * 16 + half_ * 8 + lg;
            float tot = reds[rloc * 4 + 0] + reds[rloc * 4 + 1]
                      + reds[rloc * 4 + 2] + reds[rloc * 4 + 3];
            float inv = 1.f / tot;
            int r = m0 + rloc;
#pragma unroll
            for (int nt = 0; nt < 8; nt++) {
                int c = warpn * 64 + nt * 8 + 2 * lt;
                *(uint32_t*)(O + (long)r * MM + c) =
                    h2pack(acc[mt][nt][half_ * 2] * inv, acc[mt][nt][half_ * 2 + 1] * inv);
            }
        }
}

// =============================================================================
// sim_out_h: o = softmax_row(q @ kl^T) @ W, fully fused (a1 never materialized).
// 64 q-rows/block, grid (NN/64, 1, BH). Stage 1 = sim GEMM + softmax.
// Stage 2: P (half) -> smem [64][128kp], B-fragments streamed from h_WT (global,
// L2-hot). Output h_o [bh][n][d] half.
// =============================================================================
__global__ __launch_bounds__(256, 2) void sim_out_h()
{
    __shared__ uint32_t S[8192];       // 32KB: stage1 As=S[0..1023], Bs=S[1024..5119]; stage2 P
    __shared__ float redm[64 * 4];
    __shared__ float reds[64 * 4];

    const int bh = blockIdx.z;
    const __half* A = h_q  + (long)bh * NN * DHD;
    const __half* B = h_kl + (long)bh * MM * DHD;
    const __half* WTb = h_WT + (long)bh * DHD * MM;
    const int m0 = blockIdx.x * 64;
    const int tid = threadIdx.x;
    const int wid = tid >> 5, lane = tid & 31;
    const int warpm = wid & 1, warpn = wid >> 1;
    const int lg = lane >> 2, lt = lane & 3;

    uint32_t* As = S;
    uint32_t* Bs = S + 1024;
    const uint32_t asmb = (uint32_t)__cvta_generic_to_shared(As);
    const uint32_t bsmb = (uint32_t)__cvta_generic_to_shared(Bs);

    const int t4  = lane >> 3;
    const int agh = t4 >> 1;
    int aoff[2], asw[2];
#pragma unroll
    for (int mt = 0; mt < 2; mt++) {
        int rr = warpm * 32 + mt * 16 + (t4 & 1) * 8 + (lane & 7);
        aoff[mt] = rr * 64;
        asw[mt]  = (rr >> 1) & 3;
    }
    const int btb = t4 & 1;
    int boff[8], bsw[8];
#pragma unroll
    for (int nt = 0; nt < 8; nt++) {
        int n = warpn * 64 + nt * 8 + (lane & 7);
        boff[nt] = n * 64;
        bsw[nt]  = (n >> 1) & 3;
    }

    float acc[2][8][4];
#pragma unroll
    for (int mt = 0; mt < 2; mt++)
#pragma unroll
        for (int nt = 0; nt < 8; nt++)
#pragma unroll
            for (int i = 0; i < 4; i++) acc[mt][nt][i] = 0.f;

    // ---- stage 1: S = q @ kl^T ----
#pragma unroll
    for (int kt = 0; kt < 2; kt++) {
        const int k0 = kt * 32;
        {
            int row = tid >> 2, g = tid & 3;
            uint4 va = *(const uint4*)(A + (long)(m0 + row) * DHD + k0 + 8 * g);
            *(uint4*)&As[row * 16 + 4 * (g ^ ((row >> 1) & 3))] = va;
        }
#pragma unroll
        for (int j = 0; j < 4; j++) {
            int e = tid + j * 256;
            int n = e >> 2, g = e & 3;
            uint4 vb = *(const uint4*)(B + (long)n * DHD + k0 + 8 * g);
            *(uint4*)&Bs[n * 16 + 4 * (g ^ ((n >> 1) & 3))] = vb;
        }
        __syncthreads();

#pragma unroll
        for (int s = 0; s < 2; s++) {
            uint32_t af[2][4], bf[8][2];
#pragma unroll
            for (int mt = 0; mt < 2; mt++)
                ldsm4(af[mt], asmb + (uint32_t)(aoff[mt] +
                      ((((s << 1) | agh) ^ asw[mt]) << 4)));
#pragma unroll
            for (int nt = 0; nt < 8; nt++)
                ldsm2(bf[nt], bsmb + (uint32_t)(boff[nt] +
                      ((((s << 1) | btb) ^ bsw[nt]) << 4)));
#pragma unroll
            for (int mt = 0; mt < 2; mt++)
#pragma unroll
                for (int nt = 0; nt < 8; nt++)
                    mma_f16(acc[mt][nt], af[mt], bf[nt]);
        }
        __syncthreads();
    }

    // ---- softmax ----
#pragma unroll
    for (int mt = 0; mt < 2; mt++)
#pragma unroll
        for (int half_ = 0; half_ < 2; half_++) {
            float mx = -1e30f;
#pragma unroll
            for (int nt = 0; nt < 8; nt++) {
                mx = fmaxf(mx, acc[mt][nt][half_ * 2]);
                mx = fmaxf(mx, acc[mt][nt][half_ * 2 + 1]);
            }
            mx = fmaxf(mx, __shfl_xor_sync(~0u, mx, 1));
            mx = fmaxf(mx, __shfl_xor_sync(~0u, mx, 2));
            int rloc = warpm * 32 + mt * 16 + half_ * 8 + lg;
            if (lt == 0) redm[rloc * 4 + warpn] = mx;
        }
    __syncthreads();
#pragma unroll
    for (int mt = 0; mt < 2; mt++)
#pragma unroll
        for (int half_ = 0; half_ < 2; half_++) {
            int rloc = warpm * 32 + mt * 16 + half_ * 8 + lg;
            float m4 = fmaxf(fmaxf(redm[rloc * 4 + 0], redm[rloc * 4 + 1]),
                             fmaxf(redm[rloc * 4 + 2], redm[rloc * 4 + 3]));
            float s = 0.f;
#pragma unroll
            for (int nt = 0; nt < 8; nt++) {
                float e0 = __expf(acc[mt][nt][half_ * 2]     - m4);
                float e1 = __expf(acc[mt][nt][half_ * 2 + 1] - m4);
                acc[mt][nt][half_ * 2]     = e0;
                acc[mt][nt][half_ * 2 + 1] = e1;
                s += e0 + e1;
            }
            s += __shfl_xor_sync(~0u, s, 1);
            s += __shfl_xor_sync(~0u, s, 2);
            if (lt == 0) reds[rloc * 4 + warpn] = s;
        }
    __syncthreads();
    // normalize + write P into smem S: P[row][kp ^ ((row&7)<<2)], row*128 stride
#pragma unroll
    for (int mt = 0; mt < 2; mt++)
#pragma unroll
        for (int half_ = 0; half_ < 2; half_++) {
            int rloc = warpm * 32 + mt * 16 + half_ * 8 + lg;
            float tot = reds[rloc * 4 + 0] + reds[rloc * 4 + 1]
                      + reds[rloc * 4 + 2] + reds[rloc * 4 + 3];
            float inv = 1.f / tot;
#pragma unroll
            for (int nt = 0; nt < 8; nt++) {
                int kp = warpn * 32 + nt * 4 + lt;
                S[rloc * 128 + (kp ^ ((rloc & 7) << 2))] =
                    h2pack(acc[mt][nt][half_ * 2] * inv, acc[mt][nt][half_ * 2 + 1] * inv);
            }
        }
    __syncthreads();

    // ---- stage 2: O = P @ W (K = 256 -> 16 k16 steps), B from global h_WT ----
    float oacc[2][2][4];
#pragma unroll
    for (int mt = 0; mt < 2; mt++)
#pragma unroll
        for (int nt = 0; nt < 2; nt++)
#pragma unroll
            for (int i = 0; i < 4; i++) oacc[mt][nt][i] = 0.f;

#pragma unroll
    for (int s = 0; s < 16; s++) {
        const int kp0 = s * 8;
        uint32_t af[2][4], bf[2][2];
#pragma unroll
        for (int mt = 0; mt < 2; mt++) {
            int mr = warpm * 32 + mt * 16 + lg;
            af[mt][0] = S[mr * 128 + ((kp0 + lt) ^ ((mr & 7) << 2))];
            af[mt][1] = S[(mr + 8) * 128 + ((kp0 + lt) ^ (((mr + 8) & 7) << 2))];
            af[mt][2] = S[mr * 128 + ((kp0 + lt + 4) ^ ((mr & 7) << 2))];
            af[mt][3] = S[(mr + 8) * 128 + ((kp0 + lt + 4) ^ (((mr + 8) & 7) << 2))];
        }
#pragma unroll
        for (int nt = 0; nt < 2; nt++) {
            int d = warpn * 16 + nt * 8 + lg;
            bf[nt][0] = *(const uint32_t*)(WTb + (long)d * MM + s * 16 + 2 * lt);
            bf[nt][1] = *(const uint32_t*)(WTb + (long)d * MM + s * 16 + 8 + 2 * lt);
        }
#pragma unroll
        for (int mt = 0; mt < 2; mt++)
#pragma unroll
            for (int nt = 0; nt < 2; nt++)
                mma_f16(oacc[mt][nt], af[mt], bf[nt]);
    }

    __half* ob = h_o + (long)bh * NN * DHD;
#pragma unroll
    for (int mt = 0; mt < 2; mt++)
#pragma unroll
        for (int half_ = 0; half_ < 2; half_++) {
            int r = m0 + warpm * 32 + mt * 16 + half_ * 8 + lg;
#pragma unroll
            for (int nt = 0; nt < 2; nt++) {
                int d = warpn * 16 + nt * 8 + 2 * lt;
                *(uint32_t*)(ob + (long)r * DHD + d) =
                    h2pack(oacc[mt][nt][half_ * 2], oacc[mt][nt][half_ * 2 + 1]);
            }
        }
}

// =============================================================================
// a3v_flash_h: a3vT = (softmax_row(ql @ k^T) @ v)^T, SN2=128 chunks.
// =============================================================================
__global__ __launch_bounds__(256, 2) void a3v_flash_h()
{
    __shared__ uint32_t Ks[128 * 32];
    __shared__ uint32_t Vs[64 * 64];
    __shared__ uint32_t Ps[32 * 64];
    __shared__ float redm[32 * 4];
    __shared__ float reds[32 * 4];

    const int bh = blockIdx.z;
    const int m0 = blockIdx.x * 32;
    const __half* ql = h_ql + (long)bh * MM * DHD;
    const __half* kg = h_k  + (long)bh * NN * DHD;
    const __half* vg = h_v  + (long)bh * NN * DHD;

    const int tid = threadIdx.x;
    const int wid = tid >> 5, lane = tid & 31;
    const int warpm = wid & 1, warpn = wid >> 1;
    const int lg = lane >> 2, lt = lane & 3;

    uint32_t aq[4][4];
    {
        int mr = m0 + warpm * 16;
#pragma unroll
        for (int s = 0; s < 4; s++) {
            int d0 = s * 16 + 2 * lt;
            aq[s][0] = *(const uint32_t*)(ql + (long)(mr + lg) * DHD + d0);
            aq[s][1] = *(const uint32_t*)(ql + (long)(mr + 8 + lg) * DHD + d0);
            aq[s][2] = *(const uint32_t*)(ql + (long)(mr + lg) * DHD + d0 + 8);
            aq[s][3] = *(const uint32_t*)(ql + (long)(mr + 8 + lg) * DHD + d0 + 8);
        }
    }

    float oacc[2][4];
#pragma unroll
    for (int nt = 0; nt < 2; nt++)
#pragma unroll
        for (int i = 0; i < 4; i++) oacc[nt][i] = 0.f;
    float mprev[2] = {-1e30f, -1e30f};
    float lsum[2]  = {0.f, 0.f};

    uint4 kpre[4];
    uint2 vpa[4], vpb[4];
#pragma unroll
    for (int j = 0; j < 4; j++) {
        int e = tid + j * 256;
        { int tok = e >> 3, g = e & 7;
          kpre[j] = *(const uint4*)(kg + (long)tok * DHD + 8 * g); }
        { int kpt = e >> 4, d4 = (e & 15) << 2;
          vpa[j] = *(const uint2*)(vg + (long)(2 * kpt) * DHD + d4);
          vpb[j] = *(const uint2*)(vg + (long)(2 * kpt + 1) * DHD + d4); }
    }

    for (int ch = 0; ch < NCH2; ch++) {
        __syncthreads();
#pragma unroll
        for (int j = 0; j < 4; j++) {
            int e = tid + j * 256;
            { int tok = e >> 3, g = e & 7;
              *(uint4*)&Ks[tok * 32 + 4 * (g ^ (tok & 7))] = kpre[j]; }
            { int kpt = e >> 4, d4 = (e & 15) << 2;
              uint4 w;
              w.x = prmtb(vpa[j].x, vpb[j].x, 0x5410);
              w.y = prmtb(vpa[j].x, vpb[j].x, 0x7632);
              w.z = prmtb(vpa[j].y, vpb[j].y, 0x5410);
              w.w = prmtb(vpa[j].y, vpb[j].y, 0x7632);
              *(uint4*)&Vs[kpt * 64 + (d4 ^ ((kpt & 3) << 3))] = w; }
        }
        if (ch + 1 < NCH2) {
            const __half* kc = kg + (long)(ch + 1) * SN2 * DHD;
            const __half* vc = vg + (long)(ch + 1) * SN2 * DHD;
#pragma unroll
            for (int j = 0; j < 4; j++) {
                int e = tid + j * 256;
                { int tok = e >> 3, g = e & 7;
                  kpre[j] = *(const uint4*)(kc + (long)tok * DHD + 8 * g); }
                { int kpt = e >> 4, d4 = (e & 15) << 2;
                  vpa[j] = *(const uint2*)(vc + (long)(2 * kpt) * DHD + d4);
                  vpb[j] = *(const uint2*)(vc + (long)(2 * kpt + 1) * DHD + d4); }
            }
        }
        __syncthreads();

        float sacc[4][4];
#pragma unroll
        for (int nt = 0; nt < 4; nt++)
#pragma unroll
            for (int i = 0; i < 4; i++) sacc[nt][i] = 0.f;
#pragma unroll
        for (int s = 0; s < 4; s++) {
            uint32_t bf[4][2];
#pragma unroll
            for (int nt = 0; nt < 4; nt++) {
                int c = warpn * 32 + nt * 8 + lg;
                bf[nt][0] = Ks[c * 32 + lt + 4 * ((2 * s) ^ (c & 7))];
                bf[nt][1] = Ks[c * 32 + lt + 4 * ((2 * s + 1) ^ (c & 7))];
            }
#pragma unroll
            for (int nt = 0; nt < 4; nt++)
                mma_f16(sacc[nt], aq[s], bf[nt]);
        }

#pragma unroll
        for (int half_ = 0; half_ < 2; half_++) {
            float mx = -1e30f;
#pragma unroll
            for (int nt = 0; nt < 4; nt++) {
                mx = fmaxf(mx, sacc[nt][half_ * 2]);
                mx = fmaxf(mx, sacc[nt][half_ * 2 + 1]);
            }
            mx = fmaxf(mx, __shfl_xor_sync(~0u, mx, 1));
            mx = fmaxf(mx, __shfl_xor_sync(~0u, mx, 2));
            if (lt == 0) redm[(warpm * 16 + half_ * 8 + lg) * 4 + warpn] = mx;
        }
        __syncthreads();

        float scale[2];
#pragma unroll
        for (int half_ = 0; half_ < 2; half_++) {
            int row = warpm * 16 + half_ * 8 + lg;
            float mch = fmaxf(fmaxf(redm[row * 4 + 0], redm[row * 4 + 1]),
                              fmaxf(redm[row * 4 + 2], redm[row * 4 + 3]));
            float mnew = fmaxf(mprev[half_], mch);
            scale[half_] = __expf(mprev[half_] - mnew);
            mprev[half_] = mnew;
            float s = 0.f;
#pragma unroll
            for (int nt = 0; nt < 4; nt++) {
                float e0 = __expf(sacc[nt][half_ * 2]     - mnew);
                float e1 = __expf(sacc[nt][half_ * 2 + 1] - mnew);
                sacc[nt][half_ * 2]     = e0;
                sacc[nt][half_ * 2 + 1] = e1;
                s += e0 + e1;
            }
            s += __shfl_xor_sync(~0u, s, 1);
            s += __shfl_xor_sync(~0u, s, 2);
            if (lt == 0) reds[row * 4 + warpn] = s;
#pragma unroll
            for (int nt = 0; nt < 4; nt++) {
                int kp = warpn * 16 + nt * 4 + lt;
                Ps[row * 64 + (kp ^ ((row & 7) << 2))] =
                    h2pack(sacc[nt][half_ * 2], sacc[nt][half_ * 2 + 1]);
            }
        }
        __syncthreads();

#pragma unroll
        for (int half_ = 0; half_ < 2; half_++) {
            int row = warpm * 16 + half_ * 8 + lg;
            lsum[half_] = lsum[half_] * scale[half_]
                        + reds[row * 4 + 0] + reds[row * 4 + 1]
                        + reds[row * 4 + 2] + reds[row * 4 + 3];
        }
#pragma unroll
        for (int nt = 0; nt < 2; nt++) {
            oacc[nt][0] *= scale[0]; oacc[nt][1] *= scale[0];
            oacc[nt][2] *= scale[1]; oacc[nt][3] *= scale[1];
        }

#pragma unroll
        for (int s = 0; s < 8; s++) {
            const int kp0 = s * 8;
            int mr = warpm * 16 + lg;
            uint32_t af[4];
            af[0] = Ps[mr * 64 + ((kp0 + lt) ^ ((mr & 7) << 2))];
            af[1] = Ps[(mr + 8) * 64 + ((kp0 + lt) ^ (((mr + 8) & 7) << 2))];
            af[2] = Ps[mr * 64 + ((kp0 + lt + 4) ^ ((mr & 7) << 2))];
            af[3] = Ps[(mr + 8) * 64 + ((kp0 + lt + 4) ^ (((mr + 8) & 7) << 2))];
            uint32_t bf[2][2];
#pragma unroll
            for (int nt = 0; nt < 2; nt++) {
                int d = warpn * 16 + nt * 8 + lg;
                bf[nt][0] = Vs[(kp0 + lt) * 64 + (d ^ (lt << 3))];
                bf[nt][1] = Vs[(kp0 + lt + 4) * 64 + (d ^ (lt << 3))];
            }
#pragma unroll
            for (int nt = 0; nt < 2; nt++)
                mma_f16(oacc[nt], af, bf[nt]);
        }
    }

    __half* outb = h_a3vT + (long)bh * DHD * MM;
#pragma unroll
    for (int half_ = 0; half_ < 2; half_++) {
        float inv = 1.f / lsum[half_];
        int r = m0 + warpm * 16 + half_ * 8 + lg;
#pragma unroll
        for (int nt = 0; nt < 2; nt++) {
            int d = warpn * 16 + nt * 8 + 2 * lt;
            outb[(long)d * MM + r]       = __float2half(oacc[nt][half_ * 2] * inv);
            outb[(long)(d + 1) * MM + r] = __float2half(oacc[nt][half_ * 2 + 1] * inv);
        }
    }
}

// ---------------- LayerNorm (half out) -----------------------------------------
__global__ __launch_bounds__(256) void ln_kernel(
    const float* __restrict__ x, const float* __restrict__ w, const float* __restrict__ b)
{
    long row = blockIdx.x;
    const float* xr = x + row * DD;
    int t = threadIdx.x;
    float v0 = xr[t], v1 = xr[t + 256];
    __shared__ float red[32];

    float s = v0 + v1;
    for (int o = 16; o > 0; o >>= 1) s += __shfl_xor_sync(~0u, s, o);
    if ((t & 31) == 0) red[t >> 5] = s;
    __syncthreads();
    if (t < 32) {
        float ss = (t < 8) ? red[t] : 0.f;
        for (int o = 4; o > 0; o >>= 1) ss += __shfl_xor_sync(~0u, ss, o);
        if (t == 0) red[0] = ss;
    }
    __syncthreads();
    float mu = red[0] * (1.f / DD);
    __syncthreads();

    float d0 = v0 - mu, d1 = v1 - mu;
    float q = d0 * d0 + d1 * d1;
    for (int o = 16; o > 0; o >>= 1) q += __shfl_xor_sync(~0u, q, o);
    if ((t & 31) == 0) red[t >> 5] = q;
    __syncthreads();
    if (t < 32) {
        float ss = (t < 8) ? red[t] : 0.f;
        for (int o = 4; o > 0; o >>= 1) ss += __shfl_xor_sync(~0u, ss, o);
        if (t == 0) red[0] = ss;
    }
    __syncthreads();
    float inv = rsqrtf(red[0] * (1.f / DD) + 1e-5f);
    h_xn[row * DD + t]       = __float2half(d0 * inv * w[t]       + b[t]);
    h_xn[row * DD + t + 256] = __float2half(d1 * inv * w[t + 256] + b[t + 256]);
}

// ---------------- weight conversion --------------------------------------------
__global__ void conv_weights(const float* __restrict__ wq, const float* __restrict__ wo)
{
    int i = blockIdx.x * 256 + threadIdx.x;
    {
        int n = i / DD, k2 = i % DD;
        h_wqkvT[i] = __float2half(wq[(long)k2 * (3 * DD) + n]);
    }
    if (i < DD * DD) {
        int n = i / DD, k2 = i % DD;
        h_woutT[i] = __float2half(wo[(long)k2 * DD + n]);
    }
}

// ---------------- landmarks ----------------------------------------------------
__global__ void landmarks()
{
    long i = (long)blockIdx.x * 256 + threadIdx.x;
    int dg = i & 7; long r = i >> 3;
    int m = r % MM;  int bh = r / MM;
    long base = ((long)bh * NN + m * LLm) * DHD + dg * 8;
    float sq[8], sk[8];
#pragma unroll
    for (int e = 0; e < 8; e++) { sq[e] = 0.f; sk[e] = 0.f; }
#pragma unroll
    for (int u = 0; u < LLm; u++) {
        uint4 vq = *(const uint4*)(h_q + base + u * DHD);
        uint4 vk = *(const uint4*)(h_k + base + u * DHD);
        const uint32_t* q4 = &vq.x;
        const uint32_t* k4 = &vk.x;
#pragma unroll
        for (int p = 0; p < 4; p++) {
            float2 fq = __half22float2(*(const __half2*)&q4[p]);
            float2 fk = __half22float2(*(const __half2*)&k4[p]);
            sq[2 * p] += fq.x; sq[2 * p + 1] += fq.y;
            sk[2 * p] += fk.x; sk[2 * p + 1] += fk.y;
        }
    }
    uint4 oq, ok;
    uint32_t* oq4 = &oq.x; uint32_t* ok4 = &ok.x;
#pragma unroll
    for (int p = 0; p < 4; p++) {
        oq4[p] = h2pack(sq[2 * p] * (1.f / LLm), sq[2 * p + 1] * (1.f / LLm));
        ok4[p] = h2pack(sk[2 * p] * (1.f / LLm), sk[2 * p + 1] * (1.f / LLm));
    }
    long out = ((long)bh * MM + m) * DHD + dg * 8;
    *(uint4*)(h_ql + out) = oq;
    *(uint4*)(h_kl + out) = ok;
}

// ---------------- pinv init ----------------------------------------------------
__global__ void init_colmax() { g_colmax = 0.f; }

__global__ __launch_bounds__(256) void colmax_kernel()
{
    int bh = blockIdx.x, j = threadIdx.x;
    const __half* a = h_a2 + (long)bh * MM * MM;
    float s = 0.f;
    for (int i = 0; i < MM; i++) s += __half2float(a[i * MM + j]);
    __shared__ float red[32];
    float m = s;
    for (int o = 16; o > 0; o >>= 1) m = fmaxf(m, __shfl_xor_sync(~0u, m, o));
    if ((j & 31) == 0) red[j >> 5] = m;
    __syncthreads();
    if (j < 32) {
        float m2 = (j < 8) ? red[j] : -1e30f;
        for (int o = 4; o > 0; o >>= 1) m2 = fmaxf(m2, __shfl_xor_sync(~0u, m2, o));
        if (j == 0) atomicMax((int*)&g_colmax, __float_as_int(m2));
    }
}

__global__ void zinit()
{
    long i = (long)blockIdx.x * 256 + threadIdx.x;
    int col = i % MM; long r = i / MM;
    int row = r % MM; int bh = r / MM;
    float inv = 1.f / g_colmax;
    h_zT[i] = __float2half(__half2float(h_a2[i]) * inv);
    h_z [i] = __float2half(__half2float(h_a2[((long)bh * MM + col) * MM + row]) * inv);
}

// ---------------- fused reshape + depthwise conv (all half) --------------------
__global__ void att_conv(const float* __restrict__ rw)
{
    long i = (long)blockIdx.x * 256 + threadIdx.x;
    int dq = i % 16; long r = i / 16;
    int h = r % HH;  long r2 = r / HH;
    int n = r2 % NN; int b = r2 / NN;
    long bhbase = (long)(b * HH + h) * NN;
    const __half* vb = h_v + bhbase * DHD;
    uint2 ov = *(const uint2*)(h_o + (bhbase + n) * DHD + dq * 4);
    float2 o0 = __half22float2(*(const __half2*)&ov.x);
    float2 o1 = __half22float2(*(const __half2*)&ov.y);
    float a0 = o0.x, a1 = o0.y, a2 = o1.x, a3 = o1.y;
#pragma unroll
    for (int j = 0; j < KC; j++) {
        int tt = n + j - KC / 2;
        if (tt >= 0 && tt < NN) {
            float w = rw[h * KC + j];
            uint2 vv = *(const uint2*)(vb + (long)tt * DHD + dq * 4);
            float2 v0 = __half22float2(*(const __half2*)&vv.x);
            float2 v1 = __half22float2(*(const __half2*)&vv.y);
            a0 += w * v0.x; a1 += w * v0.y; a2 += w * v1.x; a3 += w * v1.y;
        }
    }
    uint2 w2;
    w2.x = h2pack(a0, a1);
    w2.y = h2pack(a2, a3);
    *(uint2*)&h_att[((long)(b * NN + n)) * DD + h * DHD + dq * 4] = w2;
}

// ---------------- host orchestration -------------------------------------------
extern "C" void kernel_launch(void* const* d_in, const int* in_sizes, int n_in,
                              void* d_out, int out_size)
{
    const float* x      = (const float*)d_in[0];
    const float* norm_w = (const float*)d_in[1];
    const float* norm_b = (const float*)d_in[2];
    const float* w_qkv  = (const float*)d_in[3];
    const float* w_out  = (const float*)d_in[4];
    const float* b_out  = (const float*)d_in[5];
    const float* res_w  = (const float*)d_in[6];
    float* y = (float*)d_out;

    __half *p_xn, *p_wqkvT, *p_woutT, *p_q, *p_k, *p_v, *p_ql, *p_kl;
    __half *p_a2, *p_z, *p_zT, *p_z2, *p_z2T, *p_xz, *p_t1T, *p_t2T, *p_a3vT, *p_WT, *p_att;
    cudaGetSymbolAddress((void**)&p_xn,   h_xn);
    cudaGetSymbolAddress((void**)&p_wqkvT,h_wqkvT);
    cudaGetSymbolAddress((void**)&p_woutT,h_woutT);
    cudaGetSymbolAddress((void**)&p_q,    h_q);
    cudaGetSymbolAddress((void**)&p_k,    h_k);
    cudaGetSymbolAddress((void**)&p_v,    h_v);
    cudaGetSymbolAddress((void**)&p_ql,   h_ql);
    cudaGetSymbolAddress((void**)&p_kl,   h_kl);
    cudaGetSymbolAddress((void**)&p_a2,   h_a2);
    cudaGetSymbolAddress((void**)&p_z,    h_z);
    cudaGetSymbolAddress((void**)&p_zT,   h_zT);
    cudaGetSymbolAddress((void**)&p_z2,   h_z2);
    cudaGetSymbolAddress((void**)&p_z2T,  h_z2T);
    cudaGetSymbolAddress((void**)&p_xz,   h_xz);
    cudaGetSymbolAddress((void**)&p_t1T,  h_t1T);
    cudaGetSymbolAddress((void**)&p_t2T,  h_t2T);
    cudaGetSymbolAddress((void**)&p_a3vT, h_a3vT);
    cudaGetSymbolAddress((void**)&p_WT,   h_WT);
    cudaGetSymbolAddress((void**)&p_att,  h_att);

    const long MM2 = (long)MM * MM;
    void* nul = nullptr;

    // 1. LayerNorm + weight conversion
    ln_kernel<<<BB * NN, 256>>>(x, norm_w, norm_b);
    conv_weights<<<(3 * DD * DD) / 256, 256>>>(w_qkv, w_out);
    // 2. qkv GEMM with fused split
    gemm_h<128, 1><<<dim3((3 * DD) / 128, (BB * NN) / 128, 1), 256>>>(
        p_xn, p_wqkvT, p_q, p_k, p_v,
        BB * NN, 3 * DD, DD, 0, 0, 0, 1.f, 0.f);
    // 3. landmarks
    landmarks<<<(BH * MM * 8) / 256, 256>>>();
    // 4. a2 = softmax(ql @ kl^T)
    sim_softmax_h<<<dim3(MM / 64, 1, BH), 256>>>(
        p_ql, p_kl, p_a2, (long)MM * DHD, (long)MM * DHD, MM2);
    // 5. pinv init
    init_colmax<<<1, 1>>>();
    colmax_kernel<<<BH, 256>>>();
    zinit<<<(int)((long)BH * MM * MM / 256), 256>>>();
    // 6. Newton-Schulz
    __half *zin = p_z, *zinT = p_zT, *zout = p_z2, *zoutT = p_z2T;
    for (int it = 0; it < NITER; it++) {
        gemm_h<64, 3><<<dim3(MM / 64, MM / 128, BH), 256>>>(
            p_a2, zinT, p_xz, nul, p_t1T, MM, MM, MM, MM2, MM2, MM2, 1.f, 7.f);
        gemm_h<64, 3><<<dim3(MM / 64, MM / 128, BH), 256>>>(
            p_xz, p_t1T, nul, nul, p_t2T, MM, MM, MM, MM2, MM2, MM2, 1.f, 15.f);
        gemm_h<64, 3><<<dim3(MM / 64, MM / 128, BH), 256>>>(
            p_xz, p_t2T, nul, nul, p_t1T, MM, MM, MM, MM2, MM2, MM2, 1.f, 13.f);
        gemm_h<64, 3><<<dim3(MM / 64, MM / 128, BH), 256>>>(
            zin, p_t1T, zout, zoutT, nul, MM, MM, MM, MM2, MM2, MM2, 0.25f, 0.f);
        __half* t;
        t = zin;  zin  = zout;  zout  = t;
        t = zinT; zinT = zoutT; zoutT = t;
    }
    // 7. a3vT = (softmax(ql @ k^T) @ v)^T  (flash)
    a3v_flash_h<<<dim3(MM / 32, 1, BH), 256>>>();
    // 8. WT = (z @ a3v)^T
    gemm_h<64, 3><<<dim3(1, MM / 128, BH), 256>>>(
        zin, p_a3vT, nul, p_WT, nul, MM, DHD, MM,
        MM2, (long)DHD * MM, (long)DHD * MM, 1.f, 0.f);
    // 9. o = softmax(q @ kl^T) @ W  (fully fused; a1 never stored)
    sim_out_h<<<dim3(NN / 64, 1, BH), 256>>>();
    // 10. att = reshape(o) + conv(v)
    att_conv<<<(BB * NN * HH * 16) / 256, 256>>>(res_w);
    // 11. y = att @ w_out + x + b_out
    gemm_h<128, 2><<<dim3(DD / 128, (BB * NN) / 128, 1), 256>>>(
        p_att, p_woutT, y, (void*)x, (void*)b_out,
        BB * NN, DD, DD, 0, 0, 0, 1.f, 0.f);
}